// round 8
// baseline (speedup 1.0000x reference)
#include <cuda_runtime.h>
#include <cuda_fp16.h>
#include <math.h>
#include <stdint.h>

#define BB 8
#define SS 1024
#define EE 1024
#define HH 16
#define DD 64
#define LL 2
#define MROWS (BB*SS)              // 8192
#define OUT_MAIN (BB*SS*EE)        // 8388608
#define OFF_PROBS OUT_MAIN
#define OFF_MODE  (OUT_MAIN + 8)
#define OFF_MEAN  (OUT_MAIN + 16)

// ---------------- scratch (device globals; no allocation allowed) ------------
__device__ float g_bufA[MROWS * EE];     // out-proj fp32
__device__ float g_bufB[MROWS * EE];     // ffn2 out fp32
__device__ float g_bufT[MROWS * EE];     // t (post layer)
__device__ float g_bufT1[MROWS * EE];    // t1 (post LN1)
__device__ float g_bufFast[MROWS * EE];  // fast path
__device__ float g_pooled[BB * EE];

// fp16 split buffers
#define NW_TOTAL 26214400
#define OW_IN   0
#define OW_OUT  6291456
#define OW_F1   8388608
#define OW_F2   16777216
#define OW_FAST 25165824
__device__ __half g_wb_hi[NW_TOTAL];
__device__ __half g_wb_lo[NW_TOTAL];
__device__ __half g_actA_hi[MROWS * 1024];   // narrow activations
__device__ __half g_actA_lo[MROWS * 1024];
__device__ __half g_actB_hi[MROWS * 4096];   // qkv (3072) / ffn hidden (4096)
__device__ __half g_actB_lo[MROWS * 4096];

__device__ __forceinline__ float gelu_exact(float v) {
    return 0.5f * v * (1.0f + erff(v * 0.7071067811865476f));
}
__device__ __forceinline__ uint32_t pack_f16(float a, float b) {
    __half2 t = __floats2half2_rn(a, b);
    return *(uint32_t*)&t;
}

// =================== portable tensor-core primitives (sm_80+ PTX) ============
__device__ __forceinline__ uint32_t smem_u32(const void* p) {
    uint32_t a;
    asm("{ .reg .u64 t; cvta.to.shared.u64 t, %1; cvt.u32.u64 %0, t; }" : "=r"(a) : "l"(p));
    return a;
}
__device__ __forceinline__ void ldm_x4(uint32_t& r0, uint32_t& r1, uint32_t& r2, uint32_t& r3,
                                       uint32_t addr) {
    asm volatile("ldmatrix.sync.aligned.m8n8.x4.shared.b16 {%0,%1,%2,%3}, [%4];"
                 : "=r"(r0), "=r"(r1), "=r"(r2), "=r"(r3) : "r"(addr));
}
__device__ __forceinline__ void ldm_x4_t(uint32_t& r0, uint32_t& r1, uint32_t& r2, uint32_t& r3,
                                         uint32_t addr) {
    asm volatile("ldmatrix.sync.aligned.m8n8.x4.trans.shared.b16 {%0,%1,%2,%3}, [%4];"
                 : "=r"(r0), "=r"(r1), "=r"(r2), "=r"(r3) : "r"(addr));
}
// fp16 inputs, fp32 accumulator
__device__ __forceinline__ void mma_f32(float* c, uint32_t a0, uint32_t a1, uint32_t a2,
                                        uint32_t a3, uint32_t b0, uint32_t b1) {
    asm volatile(
        "mma.sync.aligned.m16n8k16.row.col.f32.f16.f16.f32 "
        "{%0,%1,%2,%3}, {%4,%5,%6,%7}, {%8,%9}, {%0,%1,%2,%3};"
        : "+f"(c[0]), "+f"(c[1]), "+f"(c[2]), "+f"(c[3])
        : "r"(a0), "r"(a1), "r"(a2), "r"(a3), "r"(b0), "r"(b1));
}
// fp16 inputs, fp16 accumulator (for small correction terms)
__device__ __forceinline__ void mma_f16(uint32_t* c, uint32_t a0, uint32_t a1, uint32_t a2,
                                        uint32_t a3, uint32_t b0, uint32_t b1) {
    asm volatile(
        "mma.sync.aligned.m16n8k16.row.col.f16.f16.f16.f16 "
        "{%0,%1}, {%2,%3,%4,%5}, {%6,%7}, {%0,%1};"
        : "+r"(c[0]), "+r"(c[1])
        : "r"(a0), "r"(a1), "r"(a2), "r"(a3), "r"(b0), "r"(b1));
}
__device__ __forceinline__ void cp16(uint32_t saddr, const void* g) {
    asm volatile("cp.async.cg.shared.global [%0], [%1], 16;" :: "r"(saddr), "l"(g));
}
#define CP_COMMIT() asm volatile("cp.async.commit_group;" ::: "memory")
#define CP_WAIT(N)  asm volatile("cp.async.wait_group %0;" :: "n"(N) : "memory")

// =================== mma.sync GEMM: C[M,N] = A[M,K] @ B[N,K]^T ===============
// 128x128 block, 8 warps (2M x 4N), warp tile 64x32, K-chunk 32.
// Main term hi*hi in f32 acc; corrections hi*lo + lo*hi share one f16 acc.
// One __syncthreads per chunk. smem rows 80B: conflict-free ldmatrix.
#define TIL   10240
#define STAGE (4 * TIL)
#define SMT   (2 * STAGE)

__device__ __forceinline__ void copy_tile_async(uint32_t sdst, const __half* __restrict__ g,
                                                int row0, int K, int k0, int tid) {
    #pragma unroll
    for (int i = 0; i < 2; i++) {
        int idx = tid + i * 256;
        int r = idx >> 2, c4 = idx & 3;
        cp16(sdst + r * 80 + c4 * 16, g + (size_t)(row0 + r) * K + k0 + c4 * 8);
    }
}

template<int EPI>   // 0 fp32, 1 gelu fp32, 2 fp16 split, 3 gelu+split
__global__ __launch_bounds__(256, 2) void mma_gemm(
        const __half* __restrict__ Ahi, const __half* __restrict__ Alo,
        const __half* __restrict__ Bhi, const __half* __restrict__ Blo,
        float* __restrict__ C, __half* __restrict__ Chi,
        __half* __restrict__ Clo, int N, int K) {
    extern __shared__ __align__(128) char smem[];
    uint32_t sb = smem_u32(smem);
    int tid = threadIdx.x, lane = tid & 31, warp = tid >> 5;
    int wm = warp & 1, wn = warp >> 1;
    int rowB = blockIdx.y * 128, colB = blockIdx.x * 128;

    int aRow = wm * 64 + (lane & 15);
    int aK   = (lane >> 4) * 8;
    uint32_t aOff = (uint32_t)(aRow * 80 + aK * 2);
    int bRow = wn * 32 + ((lane >> 4) << 3) + (lane & 7);
    int bK   = ((lane >> 3) & 1) * 8;
    uint32_t bOff = (uint32_t)(bRow * 80 + bK * 2);

    float acc[4][4][4];
    uint32_t acc16[4][4][2];
    #pragma unroll
    for (int i = 0; i < 4; i++)
        #pragma unroll
        for (int j = 0; j < 4; j++) {
            acc[i][j][0] = acc[i][j][1] = acc[i][j][2] = acc[i][j][3] = 0.0f;
            acc16[i][j][0] = 0u; acc16[i][j][1] = 0u;
        }

    int nch = K >> 5;
    {
        copy_tile_async(sb + 0 * TIL, Ahi, rowB, K, 0, tid);
        copy_tile_async(sb + 1 * TIL, Alo, rowB, K, 0, tid);
        copy_tile_async(sb + 2 * TIL, Bhi, colB, K, 0, tid);
        copy_tile_async(sb + 3 * TIL, Blo, colB, K, 0, tid);
        CP_COMMIT();
    }

    for (int c = 0; c < nch; c++) {
        CP_WAIT(0);
        __syncthreads();   // cp(c) visible to all; all warps done reading stage (c+1)&1
        if (c + 1 < nch) {
            uint32_t sn = sb + ((c + 1) & 1) * STAGE;
            int k0 = (c + 1) * 32;
            copy_tile_async(sn + 0 * TIL, Ahi, rowB, K, k0, tid);
            copy_tile_async(sn + 1 * TIL, Alo, rowB, K, k0, tid);
            copy_tile_async(sn + 2 * TIL, Bhi, colB, K, k0, tid);
            copy_tile_async(sn + 3 * TIL, Blo, colB, K, k0, tid);
            CP_COMMIT();
        }

        uint32_t ss = sb + (c & 1) * STAGE;
        uint32_t sAh = ss + aOff, sAl = ss + TIL + aOff;
        uint32_t sBh = ss + 2 * TIL + bOff, sBl = ss + 3 * TIL + bOff;

        #pragma unroll
        for (int k16 = 0; k16 < 2; k16++) {
            uint32_t kb = k16 * 32;
            uint32_t bh[2][4], bl[2][4];
            #pragma unroll
            for (int nh = 0; nh < 2; nh++) {
                uint32_t off = (uint32_t)(nh * 16 * 80) + kb;
                ldm_x4(bh[nh][0], bh[nh][1], bh[nh][2], bh[nh][3], sBh + off);
                ldm_x4(bl[nh][0], bl[nh][1], bl[nh][2], bl[nh][3], sBl + off);
            }
            #pragma unroll
            for (int mt = 0; mt < 4; mt++) {
                uint32_t off = (uint32_t)(mt * 16 * 80) + kb;
                uint32_t ah0, ah1, ah2, ah3, al0, al1, al2, al3;
                ldm_x4(ah0, ah1, ah2, ah3, sAh + off);
                ldm_x4(al0, al1, al2, al3, sAl + off);
                #pragma unroll
                for (int nt = 0; nt < 4; nt++) {
                    int nh = nt >> 1, o = (nt & 1) * 2;
                    mma_f32(acc[mt][nt], ah0, ah1, ah2, ah3, bh[nh][o], bh[nh][o + 1]);
                    mma_f16(acc16[mt][nt], ah0, ah1, ah2, ah3, bl[nh][o], bl[nh][o + 1]);
                    mma_f16(acc16[mt][nt], al0, al1, al2, al3, bh[nh][o], bh[nh][o + 1]);
                }
            }
        }
    }

    int r = lane >> 2, c2 = (lane & 3) * 2;
    int row0 = rowB + wm * 64, col0 = colB + wn * 32;
    #pragma unroll
    for (int mt = 0; mt < 4; mt++)
        #pragma unroll
        for (int nt = 0; nt < 4; nt++) {
            float2 q0 = __half22float2(*(__half2*)&acc16[mt][nt][0]);
            float2 q1 = __half22float2(*(__half2*)&acc16[mt][nt][1]);
            float v0 = acc[mt][nt][0] + q0.x, v1 = acc[mt][nt][1] + q0.y;
            float v2 = acc[mt][nt][2] + q1.x, v3 = acc[mt][nt][3] + q1.y;
            if (EPI == 1 || EPI == 3) {
                v0 = gelu_exact(v0); v1 = gelu_exact(v1);
                v2 = gelu_exact(v2); v3 = gelu_exact(v3);
            }
            int row = row0 + mt * 16 + r, col = col0 + nt * 8 + c2;
            if (EPI <= 1) {
                float2 p0 = {v0, v1}, p1 = {v2, v3};
                *(float2*)(C + (size_t)row * N + col) = p0;
                *(float2*)(C + (size_t)(row + 8) * N + col) = p1;
            } else {
                __half h0 = __float2half_rn(v0), h1 = __float2half_rn(v1);
                __half h2 = __float2half_rn(v2), h3 = __float2half_rn(v3);
                uint32_t hp0 = (uint32_t)__half_as_ushort(h0) |
                               ((uint32_t)__half_as_ushort(h1) << 16);
                uint32_t hp1 = (uint32_t)__half_as_ushort(h2) |
                               ((uint32_t)__half_as_ushort(h3) << 16);
                *(uint32_t*)(Chi + (size_t)row * N + col) = hp0;
                *(uint32_t*)(Chi + (size_t)(row + 8) * N + col) = hp1;
                *(uint32_t*)(Clo + (size_t)row * N + col) =
                    pack_f16(v0 - __half2float(h0), v1 - __half2float(h1));
                *(uint32_t*)(Clo + (size_t)(row + 8) * N + col) =
                    pack_f16(v2 - __half2float(h2), v3 - __half2float(h3));
            }
        }
}

// =================== tensor-core flash attention (fp16 split) ================
#define ATT_SQH 0
#define ATT_SQL 18432
#define ATT_SKH 36864
#define ATT_SKL 46080
#define ATT_SVH 55296
#define ATT_SVL 64512
#define ATT_SMEM 73728
#define QSTR 3072

__global__ __launch_bounds__(256) void attn_mma(
        const __half* __restrict__ qh, const __half* __restrict__ ql,
        __half* __restrict__ oh, __half* __restrict__ ol) {
    extern __shared__ __align__(128) char smem[];
    uint32_t sb = smem_u32(smem);
    int tid = threadIdx.x, lane = tid & 31, warp = tid >> 5;
    int qt = blockIdx.x, h = blockIdx.y, b = blockIdx.z;
    int rb = b * SS;

    #pragma unroll
    for (int i = 0; i < 4; i++) {
        int idx = tid + i * 256;
        int r = idx >> 3, c8 = idx & 7;
        size_t srow = (size_t)(rb + qt * 128 + r) * QSTR + h * 64 + c8 * 8;
        *(uint4*)(smem + ATT_SQH + r * 144 + c8 * 16) = *(const uint4*)(qh + srow);
        *(uint4*)(smem + ATT_SQL + r * 144 + c8 * 16) = *(const uint4*)(ql + srow);
    }

    float m0 = -1e30f, m1 = -1e30f, l0 = 0.0f, l1 = 0.0f;
    float accO[8][4];
    #pragma unroll
    for (int i = 0; i < 8; i++)
        #pragma unroll
        for (int j = 0; j < 4; j++) accO[i][j] = 0.0f;

    uint32_t aAddr = sb + ATT_SQH + (uint32_t)((warp * 16 + (lane & 15)) * 144 + (lane >> 4) * 16);
    uint32_t bOff  = (uint32_t)(((lane & 7) + ((lane >> 4) << 3)) * 144 + ((lane >> 3) & 1) * 16);
    uint32_t vOff  = (uint32_t)(((lane & 7) + ((lane >> 3) & 1) * 8) * 144 + ((lane >> 4) & 1) * 16);

    __syncthreads();

    for (int kv0 = 0; kv0 < SS; kv0 += 64) {
        #pragma unroll
        for (int i = 0; i < 2; i++) {
            int idx = tid + i * 256;
            int r = idx >> 3, c8 = idx & 7;
            size_t srow = (size_t)(rb + kv0 + r) * QSTR + h * 64 + c8 * 8;
            *(uint4*)(smem + ATT_SKH + r * 144 + c8 * 16) = *(const uint4*)(qh + srow + 1024);
            *(uint4*)(smem + ATT_SKL + r * 144 + c8 * 16) = *(const uint4*)(ql + srow + 1024);
            *(uint4*)(smem + ATT_SVH + r * 144 + c8 * 16) = *(const uint4*)(qh + srow + 2048);
            *(uint4*)(smem + ATT_SVL + r * 144 + c8 * 16) = *(const uint4*)(ql + srow + 2048);
        }
        __syncthreads();

        float s[8][4];
        #pragma unroll
        for (int i = 0; i < 8; i++)
            #pragma unroll
            for (int j = 0; j < 4; j++) s[i][j] = 0.0f;

        #pragma unroll
        for (int kc = 0; kc < 4; kc++) {
            uint32_t ah0, ah1, ah2, ah3, al0, al1, al2, al3;
            ldm_x4(ah0, ah1, ah2, ah3, aAddr + kc * 32);
            ldm_x4(al0, al1, al2, al3, aAddr + (ATT_SQL - ATT_SQH) + kc * 32);
            #pragma unroll
            for (int nh = 0; nh < 4; nh++) {
                uint32_t ba = sb + ATT_SKH + (uint32_t)(nh * 16 * 144) + bOff + kc * 32;
                uint32_t bh_[4], bl_[4];
                ldm_x4(bh_[0], bh_[1], bh_[2], bh_[3], ba);
                ldm_x4(bl_[0], bl_[1], bl_[2], bl_[3], ba + (ATT_SKL - ATT_SKH));
                #pragma unroll
                for (int o = 0; o < 2; o++) {
                    int nt = nh * 2 + o;
                    mma_f32(s[nt], ah0, ah1, ah2, ah3, bh_[o * 2], bh_[o * 2 + 1]);
                    mma_f32(s[nt], ah0, ah1, ah2, ah3, bl_[o * 2], bl_[o * 2 + 1]);
                    mma_f32(s[nt], al0, al1, al2, al3, bh_[o * 2], bh_[o * 2 + 1]);
                }
            }
        }

        float mx0 = -1e30f, mx1 = -1e30f;
        #pragma unroll
        for (int nt = 0; nt < 8; nt++) {
            s[nt][0] *= 0.125f; s[nt][1] *= 0.125f; s[nt][2] *= 0.125f; s[nt][3] *= 0.125f;
            mx0 = fmaxf(mx0, fmaxf(s[nt][0], s[nt][1]));
            mx1 = fmaxf(mx1, fmaxf(s[nt][2], s[nt][3]));
        }
        mx0 = fmaxf(mx0, __shfl_xor_sync(0xffffffffu, mx0, 1));
        mx0 = fmaxf(mx0, __shfl_xor_sync(0xffffffffu, mx0, 2));
        mx1 = fmaxf(mx1, __shfl_xor_sync(0xffffffffu, mx1, 1));
        mx1 = fmaxf(mx1, __shfl_xor_sync(0xffffffffu, mx1, 2));
        float mn0 = fmaxf(m0, mx0), mn1 = fmaxf(m1, mx1);
        float alpha0 = __expf(m0 - mn0), alpha1 = __expf(m1 - mn1);
        m0 = mn0; m1 = mn1;
        float sum0 = 0.0f, sum1 = 0.0f;
        #pragma unroll
        for (int nt = 0; nt < 8; nt++) {
            s[nt][0] = __expf(s[nt][0] - m0);
            s[nt][1] = __expf(s[nt][1] - m0);
            s[nt][2] = __expf(s[nt][2] - m1);
            s[nt][3] = __expf(s[nt][3] - m1);
            sum0 += s[nt][0] + s[nt][1];
            sum1 += s[nt][2] + s[nt][3];
        }
        sum0 += __shfl_xor_sync(0xffffffffu, sum0, 1);
        sum0 += __shfl_xor_sync(0xffffffffu, sum0, 2);
        sum1 += __shfl_xor_sync(0xffffffffu, sum1, 1);
        sum1 += __shfl_xor_sync(0xffffffffu, sum1, 2);
        l0 = l0 * alpha0 + sum0;
        l1 = l1 * alpha1 + sum1;
        #pragma unroll
        for (int dt = 0; dt < 8; dt++) {
            accO[dt][0] *= alpha0; accO[dt][1] *= alpha0;
            accO[dt][2] *= alpha1; accO[dt][3] *= alpha1;
        }

        #pragma unroll
        for (int kc2 = 0; kc2 < 4; kc2++) {
            int n0 = kc2 * 2, n1 = kc2 * 2 + 1;
            __half h00 = __float2half_rn(s[n0][0]), h01 = __float2half_rn(s[n0][1]);
            __half h02 = __float2half_rn(s[n0][2]), h03 = __float2half_rn(s[n0][3]);
            __half h10 = __float2half_rn(s[n1][0]), h11 = __float2half_rn(s[n1][1]);
            __half h12 = __float2half_rn(s[n1][2]), h13 = __float2half_rn(s[n1][3]);
            uint32_t ph0 = (uint32_t)__half_as_ushort(h00) | ((uint32_t)__half_as_ushort(h01) << 16);
            uint32_t ph1 = (uint32_t)__half_as_ushort(h02) | ((uint32_t)__half_as_ushort(h03) << 16);
            uint32_t ph2 = (uint32_t)__half_as_ushort(h10) | ((uint32_t)__half_as_ushort(h11) << 16);
            uint32_t ph3 = (uint32_t)__half_as_ushort(h12) | ((uint32_t)__half_as_ushort(h13) << 16);
            uint32_t pl0 = pack_f16(s[n0][0] - __half2float(h00), s[n0][1] - __half2float(h01));
            uint32_t pl1 = pack_f16(s[n0][2] - __half2float(h02), s[n0][3] - __half2float(h03));
            uint32_t pl2 = pack_f16(s[n1][0] - __half2float(h10), s[n1][1] - __half2float(h11));
            uint32_t pl3 = pack_f16(s[n1][2] - __half2float(h12), s[n1][3] - __half2float(h13));
            #pragma unroll
            for (int nd = 0; nd < 4; nd++) {
                uint32_t va = sb + ATT_SVH + (uint32_t)(kc2 * 16 * 144) + vOff + nd * 32;
                uint32_t vh_[4], vl_[4];
                ldm_x4_t(vh_[0], vh_[1], vh_[2], vh_[3], va);
                ldm_x4_t(vl_[0], vl_[1], vl_[2], vl_[3], va + (ATT_SVL - ATT_SVH));
                #pragma unroll
                for (int o = 0; o < 2; o++) {
                    int dt = nd * 2 + o;
                    mma_f32(accO[dt], ph0, ph1, ph2, ph3, vh_[o * 2], vh_[o * 2 + 1]);
                    mma_f32(accO[dt], ph0, ph1, ph2, ph3, vl_[o * 2], vl_[o * 2 + 1]);
                    mma_f32(accO[dt], pl0, pl1, pl2, pl3, vh_[o * 2], vh_[o * 2 + 1]);
                }
            }
        }
        __syncthreads();
    }

    float inv0 = 1.0f / l0, inv1 = 1.0f / l1;
    int g = lane >> 2, c2 = (lane & 3) * 2;
    int row = rb + qt * 128 + warp * 16 + g;
    int colb = h * 64 + c2;
    #pragma unroll
    for (int dt = 0; dt < 8; dt++) {
        float v0 = accO[dt][0] * inv0, v1 = accO[dt][1] * inv0;
        float v2 = accO[dt][2] * inv1, v3 = accO[dt][3] * inv1;
        __half h0 = __float2half_rn(v0), h1 = __float2half_rn(v1);
        __half h2 = __float2half_rn(v2), h3 = __float2half_rn(v3);
        uint32_t hp0 = (uint32_t)__half_as_ushort(h0) | ((uint32_t)__half_as_ushort(h1) << 16);
        uint32_t hp1 = (uint32_t)__half_as_ushort(h2) | ((uint32_t)__half_as_ushort(h3) << 16);
        int col = colb + dt * 8;
        *(uint32_t*)(oh + (size_t)row * EE + col) = hp0;
        *(uint32_t*)(oh + (size_t)(row + 8) * EE + col) = hp1;
        *(uint32_t*)(ol + (size_t)row * EE + col) =
            pack_f16(v0 - __half2float(h0), v1 - __half2float(h1));
        *(uint32_t*)(ol + (size_t)(row + 8) * EE + col) =
            pack_f16(v2 - __half2float(h2), v3 - __half2float(h3));
    }
}

// ---------------- fp32 -> fp16 hi/lo split -----------------------------------
__global__ __launch_bounds__(256) void split_kernel(const float* __restrict__ in,
                                                    __half* __restrict__ hi,
                                                    __half* __restrict__ lo,
                                                    int n4) {
    int i = blockIdx.x * 256 + threadIdx.x;
    if (i >= n4) return;
    float4 v = ((const float4*)in)[i];
    float x[4] = {v.x, v.y, v.z, v.w};
    uint32_t hw[4], lw[4];
    #pragma unroll
    for (int k = 0; k < 4; k++) {
        __half h = __float2half_rn(x[k]);
        float rr = x[k] - __half2float(h);
        __half l = __float2half_rn(rr);
        hw[k] = (uint32_t)__half_as_ushort(h);
        lw[k] = (uint32_t)__half_as_ushort(l);
    }
    uint2 ho, loo;
    ho.x  = hw[0] | (hw[1] << 16);  ho.y  = hw[2] | (hw[3] << 16);
    loo.x = lw[0] | (lw[1] << 16);  loo.y = lw[2] | (lw[3] << 16);
    ((uint2*)hi)[i] = ho;
    ((uint2*)lo)[i] = loo;
}

// ---------------- y = LN(a + b) * g + beta (+ fp16 split) --------------------
__global__ __launch_bounds__(256) void add_ln_split_kernel(const float* __restrict__ a,
                                                           const float* __restrict__ bsrc,
                                                           const float* __restrict__ g,
                                                           const float* __restrict__ beta,
                                                           float* __restrict__ y,
                                                           __half* __restrict__ yh,
                                                           __half* __restrict__ yl) {
    int row = blockIdx.x;
    int tid = threadIdx.x;
    const float* ar = a + (size_t)row * EE;
    const float* br = bsrc + (size_t)row * EE;
    float v[4];
    float s = 0.0f, s2 = 0.0f;
    #pragma unroll
    for (int k = 0; k < 4; k++) {
        float t = ar[tid + 256 * k] + br[tid + 256 * k];
        v[k] = t; s += t; s2 += t * t;
    }
    __shared__ float red[18];
    #pragma unroll
    for (int off = 16; off; off >>= 1) {
        s  += __shfl_xor_sync(0xffffffffu, s,  off);
        s2 += __shfl_xor_sync(0xffffffffu, s2, off);
    }
    int wid = tid >> 5, lid = tid & 31;
    if (lid == 0) { red[wid] = s; red[wid + 8] = s2; }
    __syncthreads();
    if (tid < 32) {
        float a1 = (tid < 8) ? red[tid] : 0.0f;
        float a2 = (tid < 8) ? red[tid + 8] : 0.0f;
        #pragma unroll
        for (int off = 4; off; off >>= 1) {
            a1 += __shfl_xor_sync(0xffffffffu, a1, off);
            a2 += __shfl_xor_sync(0xffffffffu, a2, off);
        }
        if (tid == 0) { red[16] = a1; red[17] = a2; }
    }
    __syncthreads();
    float mu = red[16] * (1.0f / EE);
    float var = red[17] * (1.0f / EE) - mu * mu;
    float rs = rsqrtf(var + 1e-5f);
    float* yr = y + (size_t)row * EE;
    __half* yhr = yh + (size_t)row * EE;
    __half* ylr = yl + (size_t)row * EE;
    #pragma unroll
    for (int k = 0; k < 4; k++) {
        int c = tid + 256 * k;
        float val = (v[k] - mu) * rs * g[c] + beta[c];
        yr[c] = val;
        __half h = __float2half_rn(val);
        yhr[c] = h;
        ylr[c] = __float2half_rn(val - __half2float(h));
    }
}

// ---------------- mean-pool over S -------------------------------------------
__global__ __launch_bounds__(256) void pool_kernel(const float* __restrict__ x,
                                                   float* __restrict__ pooled) {
    int idx = blockIdx.x * 256 + threadIdx.x;
    int b = idx >> 10, e = idx & 1023;
    const float* p = x + (size_t)b * SS * EE + e;
    float s = 0.0f;
    for (int sI = 0; sI < SS; sI++) s += p[(size_t)sI * EE];
    pooled[idx] = s * (1.0f / SS);
}

// ---------------- complexity estimator ---------------------------------------
__global__ __launch_bounds__(256) void ce_kernel(const float* __restrict__ pooled,
                                                 const float* __restrict__ w1,
                                                 const float* __restrict__ b1,
                                                 const float* __restrict__ w2,
                                                 const float* __restrict__ b2,
                                                 float* __restrict__ out) {
    int b = blockIdx.x, j = threadIdx.x;
    const float* p = pooled + b * EE;
    const float* w = w1 + (size_t)j * EE;
    float s = b1[j];
    for (int k = 0; k < EE; k++) s = fmaf(p[k], w[k], s);
    float h = fmaxf(s, 0.0f);
    __shared__ float red[256];
    red[j] = h * w2[j];
    __syncthreads();
    for (int off = 128; off; off >>= 1) {
        if (j < off) red[j] += red[j + off];
        __syncthreads();
    }
    if (j == 0) {
        float logit = red[0] + b2[0];
        float prob = 1.0f / (1.0f + expf(-logit));
        out[OFF_PROBS + b] = prob;
        out[OFF_MODE + b] = (prob > 0.5f) ? 1.0f : 0.0f;
    }
}

// ---------------- select + mean(mode) ----------------------------------------
__global__ __launch_bounds__(256) void finalize_kernel(const float* __restrict__ t,
                                                       const float* __restrict__ f,
                                                       float* __restrict__ out) {
    size_t i = (size_t)blockIdx.x * 256 + threadIdx.x;
    int b = (int)((i * 4) >> 20);
    float m = out[OFF_MODE + b];
    float4 r = (m > 0.5f) ? ((const float4*)t)[i] : ((const float4*)f)[i];
    ((float4*)out)[i] = r;
    if (i == 0) {
        float sAcc = 0.0f;
        for (int k = 0; k < 8; k++) sAcc += out[OFF_MODE + k];
        out[OFF_MEAN] = sAcc * 0.125f;
    }
}

// -----------------------------------------------------------------------------
extern "C" void kernel_launch(void* const* d_in, const int* in_sizes, int n_in,
                              void* d_out, int out_size) {
    const float* x      = (const float*)d_in[0];
    const float* w_in   = (const float*)d_in[1];
    const float* w_out  = (const float*)d_in[2];
    const float* ffn_w1 = (const float*)d_in[3];
    const float* ffn_w2 = (const float*)d_in[4];
    const float* ln1_g  = (const float*)d_in[5];
    const float* ln1_b  = (const float*)d_in[6];
    const float* ln2_g  = (const float*)d_in[7];
    const float* ln2_b  = (const float*)d_in[8];
    const float* ce_w1  = (const float*)d_in[9];
    const float* ce_b1  = (const float*)d_in[10];
    const float* ce_w2  = (const float*)d_in[11];
    const float* ce_b2  = (const float*)d_in[12];
    const float* fast_w = (const float*)d_in[13];
    float* out = (float*)d_out;

    float *bufA, *bufB, *bufT, *bufT1, *bufFast, *pooled;
    __half *wbh, *wbl, *ah, *al, *bh, *bl;
    cudaGetSymbolAddress((void**)&bufA, g_bufA);
    cudaGetSymbolAddress((void**)&bufB, g_bufB);
    cudaGetSymbolAddress((void**)&bufT, g_bufT);
    cudaGetSymbolAddress((void**)&bufT1, g_bufT1);
    cudaGetSymbolAddress((void**)&bufFast, g_bufFast);
    cudaGetSymbolAddress((void**)&pooled, g_pooled);
    cudaGetSymbolAddress((void**)&wbh, g_wb_hi);
    cudaGetSymbolAddress((void**)&wbl, g_wb_lo);
    cudaGetSymbolAddress((void**)&ah, g_actA_hi);
    cudaGetSymbolAddress((void**)&al, g_actA_lo);
    cudaGetSymbolAddress((void**)&bh, g_actB_hi);
    cudaGetSymbolAddress((void**)&bl, g_actB_lo);

    cudaFuncSetAttribute(mma_gemm<0>, cudaFuncAttributeMaxDynamicSharedMemorySize, SMT);
    cudaFuncSetAttribute(mma_gemm<1>, cudaFuncAttributeMaxDynamicSharedMemorySize, SMT);
    cudaFuncSetAttribute(mma_gemm<2>, cudaFuncAttributeMaxDynamicSharedMemorySize, SMT);
    cudaFuncSetAttribute(mma_gemm<3>, cudaFuncAttributeMaxDynamicSharedMemorySize, SMT);
    cudaFuncSetAttribute(attn_mma, cudaFuncAttributeMaxDynamicSharedMemorySize, ATT_SMEM);

    // weight splits
    split_kernel<<<(2*3*EE*EE/4)/256, 256>>>(w_in,   wbh + OW_IN,   wbl + OW_IN,   2*3*EE*EE/4);
    split_kernel<<<(2*EE*EE/4)/256,   256>>>(w_out,  wbh + OW_OUT,  wbl + OW_OUT,  2*EE*EE/4);
    split_kernel<<<(2*4*EE*EE/4)/256, 256>>>(ffn_w1, wbh + OW_F1,   wbl + OW_F1,   2*4*EE*EE/4);
    split_kernel<<<(2*4*EE*EE/4)/256, 256>>>(ffn_w2, wbh + OW_F2,   wbl + OW_F2,   2*4*EE*EE/4);
    split_kernel<<<(EE*EE/4)/256,     256>>>(fast_w, wbh + OW_FAST, wbl + OW_FAST, EE*EE/4);

    // complexity estimator
    pool_kernel<<<(BB * EE) / 256, 256>>>(x, pooled);
    ce_kernel<<<BB, 256>>>(pooled, ce_w1, ce_b1, ce_w2, ce_b2, out);

    // split x -> A (serves fast path + layer-0 qkv)
    split_kernel<<<(MROWS*EE/4)/256, 256>>>(x, ah, al, MROWS*EE/4);

    // fast path: gelu(x @ fast_w^T) -> fp32
    mma_gemm<1><<<dim3(EE/128, MROWS/128), 256, SMT>>>(
        ah, al, wbh + OW_FAST, wbl + OW_FAST, bufFast, nullptr, nullptr, EE, EE);

    // thinking path
    const float* tin = x;
    for (int l = 0; l < LL; l++) {
        mma_gemm<2><<<dim3(3*EE/128, MROWS/128), 256, SMT>>>(
            ah, al, wbh + OW_IN + (size_t)l*3*EE*EE, wbl + OW_IN + (size_t)l*3*EE*EE,
            nullptr, bh, bl, 3*EE, EE);
        attn_mma<<<dim3(SS/128, HH, BB), 256, ATT_SMEM>>>(bh, bl, ah, al);
        mma_gemm<0><<<dim3(EE/128, MROWS/128), 256, SMT>>>(
            ah, al, wbh + OW_OUT + (size_t)l*EE*EE, wbl + OW_OUT + (size_t)l*EE*EE,
            bufA, nullptr, nullptr, EE, EE);
        add_ln_split_kernel<<<MROWS, 256>>>(tin, bufA, ln1_g + l*EE, ln1_b + l*EE,
                                            bufT1, ah, al);
        mma_gemm<3><<<dim3(4*EE/128, MROWS/128), 256, SMT>>>(
            ah, al, wbh + OW_F1 + (size_t)l*4*EE*EE, wbl + OW_F1 + (size_t)l*4*EE*EE,
            nullptr, bh, bl, 4*EE, EE);
        mma_gemm<0><<<dim3(EE/128, MROWS/128), 256, SMT>>>(
            bh, bl, wbh + OW_F2 + (size_t)l*4*EE*EE, wbl + OW_F2 + (size_t)l*4*EE*EE,
            bufB, nullptr, nullptr, EE, 4*EE);
        add_ln_split_kernel<<<MROWS, 256>>>(bufT1, bufB, ln2_g + l*EE, ln2_b + l*EE,
                                            bufT, ah, al);
        tin = bufT;
    }

    finalize_kernel<<<(MROWS * EE / 4) / 256, 256>>>(bufT, bufFast, out);
}

// round 10
// speedup vs baseline: 1.1054x; 1.1054x over previous
#include <cuda_runtime.h>
#include <cuda_fp16.h>
#include <math.h>
#include <stdint.h>

#define BB 8
#define SS 1024
#define EE 1024
#define HH 16
#define DD 64
#define LL 2
#define MROWS (BB*SS)              // 8192
#define OUT_MAIN (BB*SS*EE)        // 8388608
#define OFF_PROBS OUT_MAIN
#define OFF_MODE  (OUT_MAIN + 8)
#define OFF_MEAN  (OUT_MAIN + 16)

// ---------------- scratch (device globals; no allocation allowed) ------------
__device__ float g_bufA[MROWS * EE];     // out-proj fp32
__device__ float g_bufB[MROWS * EE];     // ffn2 out fp32
__device__ float g_bufT[MROWS * EE];     // t (post layer)
__device__ float g_bufT1[MROWS * EE];    // t1 (post LN1)
__device__ float g_bufFast[MROWS * EE];  // fast path
__device__ float g_pooled[BB * EE];

// fp16 split buffers
#define NW_TOTAL 26214400
#define OW_IN   0
#define OW_OUT  6291456
#define OW_F1   8388608
#define OW_F2   16777216
#define OW_FAST 25165824
__device__ __half g_wb_hi[NW_TOTAL];
__device__ __half g_wb_lo[NW_TOTAL];
__device__ __half g_actA_hi[MROWS * 1024];   // narrow activations
__device__ __half g_actA_lo[MROWS * 1024];
__device__ __half g_actB_hi[MROWS * 4096];   // qkv (3072) / ffn hidden (4096)
__device__ __half g_actB_lo[MROWS * 4096];

__device__ __forceinline__ float gelu_exact(float v) {
    return 0.5f * v * (1.0f + erff(v * 0.7071067811865476f));
}
__device__ __forceinline__ uint32_t pack_f16(float a, float b) {
    __half2 t = __floats2half2_rn(a, b);
    return *(uint32_t*)&t;
}

// =================== portable tensor-core primitives (sm_80+ PTX) ============
__device__ __forceinline__ uint32_t smem_u32(const void* p) {
    uint32_t a;
    asm("{ .reg .u64 t; cvta.to.shared.u64 t, %1; cvt.u32.u64 %0, t; }" : "=r"(a) : "l"(p));
    return a;
}
__device__ __forceinline__ void ldm_x4(uint32_t& r0, uint32_t& r1, uint32_t& r2, uint32_t& r3,
                                       uint32_t addr) {
    asm volatile("ldmatrix.sync.aligned.m8n8.x4.shared.b16 {%0,%1,%2,%3}, [%4];"
                 : "=r"(r0), "=r"(r1), "=r"(r2), "=r"(r3) : "r"(addr));
}
__device__ __forceinline__ void ldm_x4_t(uint32_t& r0, uint32_t& r1, uint32_t& r2, uint32_t& r3,
                                         uint32_t addr) {
    asm volatile("ldmatrix.sync.aligned.m8n8.x4.trans.shared.b16 {%0,%1,%2,%3}, [%4];"
                 : "=r"(r0), "=r"(r1), "=r"(r2), "=r"(r3) : "r"(addr));
}
__device__ __forceinline__ void mma_f32(float* c, uint32_t a0, uint32_t a1, uint32_t a2,
                                        uint32_t a3, uint32_t b0, uint32_t b1) {
    asm volatile(
        "mma.sync.aligned.m16n8k16.row.col.f32.f16.f16.f32 "
        "{%0,%1,%2,%3}, {%4,%5,%6,%7}, {%8,%9}, {%0,%1,%2,%3};"
        : "+f"(c[0]), "+f"(c[1]), "+f"(c[2]), "+f"(c[3])
        : "r"(a0), "r"(a1), "r"(a2), "r"(a3), "r"(b0), "r"(b1));
}
__device__ __forceinline__ void cp16(uint32_t saddr, const void* g) {
    asm volatile("cp.async.cg.shared.global [%0], [%1], 16;" :: "r"(saddr), "l"(g));
}
#define CP_COMMIT() asm volatile("cp.async.commit_group;" ::: "memory")
#define CP_WAIT(N)  asm volatile("cp.async.wait_group %0;" :: "n"(N) : "memory")

// =================== mma.sync GEMM: C[M,N] = A[M,K] @ B[N,K]^T ===============
// 128x128 block, 8 warps (2M x 4N), warp tile 64x32, K-chunk 32.
// 3 mma_f32 per fragment (hh + hl + lh). Single barrier per chunk.
// EPI: 0 fp32, 1 gelu fp32, 2 fp16 split, 3 gelu+split,
//      4 fused qkv+fast (cols<3072: split->Chi/Clo stride 3072;
//                        cols>=3072: gelu fp32 -> CF stride 1024, B from BhiF/BloF)
#define TIL   10240
#define STAGE (4 * TIL)
#define SMT   (2 * STAGE)

__device__ __forceinline__ void copy_tile_async(uint32_t sdst, const __half* __restrict__ g,
                                                int row0, int K, int k0, int tid) {
    #pragma unroll
    for (int i = 0; i < 2; i++) {
        int idx = tid + i * 256;
        int r = idx >> 2, c4 = idx & 3;
        cp16(sdst + r * 80 + c4 * 16, g + (size_t)(row0 + r) * K + k0 + c4 * 8);
    }
}

template<int EPI>
__global__ __launch_bounds__(256, 2) void mma_gemm(
        const __half* __restrict__ Ahi, const __half* __restrict__ Alo,
        const __half* __restrict__ Bhi, const __half* __restrict__ Blo,
        const __half* __restrict__ BhiF, const __half* __restrict__ BloF,
        float* __restrict__ C, __half* __restrict__ Chi,
        __half* __restrict__ Clo, float* __restrict__ CF, int N, int K) {
    extern __shared__ __align__(128) char smem[];
    uint32_t sb = smem_u32(smem);
    int tid = threadIdx.x, lane = tid & 31, warp = tid >> 5;
    int wm = warp & 1, wn = warp >> 1;
    int rowB = blockIdx.y * 128, colB = blockIdx.x * 128;

    const __half* BhU = Bhi;
    const __half* BlU = Blo;
    int bcol = colB;
    bool isFast = false;
    if (EPI == 4 && colB >= 3 * EE) {
        BhU = BhiF; BlU = BloF; bcol = colB - 3 * EE; isFast = true;
    }

    int aRow = wm * 64 + (lane & 15);
    int aK   = (lane >> 4) * 8;
    uint32_t aOff = (uint32_t)(aRow * 80 + aK * 2);
    int bRow = wn * 32 + ((lane >> 4) << 3) + (lane & 7);
    int bK   = ((lane >> 3) & 1) * 8;
    uint32_t bOff = (uint32_t)(bRow * 80 + bK * 2);

    float acc[4][4][4];
    #pragma unroll
    for (int i = 0; i < 4; i++)
        #pragma unroll
        for (int j = 0; j < 4; j++)
            #pragma unroll
            for (int k = 0; k < 4; k++) acc[i][j][k] = 0.0f;

    int nch = K >> 5;
    {
        copy_tile_async(sb + 0 * TIL, Ahi, rowB, K, 0, tid);
        copy_tile_async(sb + 1 * TIL, Alo, rowB, K, 0, tid);
        copy_tile_async(sb + 2 * TIL, BhU, bcol, K, 0, tid);
        copy_tile_async(sb + 3 * TIL, BlU, bcol, K, 0, tid);
        CP_COMMIT();
    }

    for (int c = 0; c < nch; c++) {
        CP_WAIT(0);
        __syncthreads();   // cp(c) visible; all warps done reading stage (c+1)&1
        if (c + 1 < nch) {
            uint32_t sn = sb + ((c + 1) & 1) * STAGE;
            int k0 = (c + 1) * 32;
            copy_tile_async(sn + 0 * TIL, Ahi, rowB, K, k0, tid);
            copy_tile_async(sn + 1 * TIL, Alo, rowB, K, k0, tid);
            copy_tile_async(sn + 2 * TIL, BhU, bcol, K, k0, tid);
            copy_tile_async(sn + 3 * TIL, BlU, bcol, K, k0, tid);
            CP_COMMIT();
        }

        uint32_t ss = sb + (c & 1) * STAGE;
        uint32_t sAh = ss + aOff, sAl = ss + TIL + aOff;
        uint32_t sBh = ss + 2 * TIL + bOff, sBl = ss + 3 * TIL + bOff;

        #pragma unroll
        for (int k16 = 0; k16 < 2; k16++) {
            uint32_t kb = k16 * 32;
            uint32_t bh[2][4], bl[2][4];
            #pragma unroll
            for (int nh = 0; nh < 2; nh++) {
                uint32_t off = (uint32_t)(nh * 16 * 80) + kb;
                ldm_x4(bh[nh][0], bh[nh][1], bh[nh][2], bh[nh][3], sBh + off);
                ldm_x4(bl[nh][0], bl[nh][1], bl[nh][2], bl[nh][3], sBl + off);
            }
            #pragma unroll
            for (int mt = 0; mt < 4; mt++) {
                uint32_t off = (uint32_t)(mt * 16 * 80) + kb;
                uint32_t ah0, ah1, ah2, ah3, al0, al1, al2, al3;
                ldm_x4(ah0, ah1, ah2, ah3, sAh + off);
                ldm_x4(al0, al1, al2, al3, sAl + off);
                #pragma unroll
                for (int nt = 0; nt < 4; nt++) {
                    int nh = nt >> 1, o = (nt & 1) * 2;
                    mma_f32(acc[mt][nt], ah0, ah1, ah2, ah3, bh[nh][o], bh[nh][o + 1]);
                    mma_f32(acc[mt][nt], ah0, ah1, ah2, ah3, bl[nh][o], bl[nh][o + 1]);
                    mma_f32(acc[mt][nt], al0, al1, al2, al3, bh[nh][o], bh[nh][o + 1]);
                }
            }
        }
    }

    int r = lane >> 2, c2 = (lane & 3) * 2;
    int row0 = rowB + wm * 64;
    #pragma unroll
    for (int mt = 0; mt < 4; mt++)
        #pragma unroll
        for (int nt = 0; nt < 4; nt++) {
            float v0 = acc[mt][nt][0], v1 = acc[mt][nt][1];
            float v2 = acc[mt][nt][2], v3 = acc[mt][nt][3];
            int row = row0 + mt * 16 + r;
            int colLoc = wn * 32 + nt * 8 + c2;    // 0..127 within tile
            if (EPI == 4) {
                if (isFast) {
                    v0 = gelu_exact(v0); v1 = gelu_exact(v1);
                    v2 = gelu_exact(v2); v3 = gelu_exact(v3);
                    int col = bcol + colLoc;
                    float2 p0 = {v0, v1}, p1 = {v2, v3};
                    *(float2*)(CF + (size_t)row * EE + col) = p0;
                    *(float2*)(CF + (size_t)(row + 8) * EE + col) = p1;
                } else {
                    int col = colB + colLoc;
                    __half h0 = __float2half_rn(v0), h1 = __float2half_rn(v1);
                    __half h2 = __float2half_rn(v2), h3 = __float2half_rn(v3);
                    uint32_t hp0 = (uint32_t)__half_as_ushort(h0) |
                                   ((uint32_t)__half_as_ushort(h1) << 16);
                    uint32_t hp1 = (uint32_t)__half_as_ushort(h2) |
                                   ((uint32_t)__half_as_ushort(h3) << 16);
                    *(uint32_t*)(Chi + (size_t)row * (3 * EE) + col) = hp0;
                    *(uint32_t*)(Chi + (size_t)(row + 8) * (3 * EE) + col) = hp1;
                    *(uint32_t*)(Clo + (size_t)row * (3 * EE) + col) =
                        pack_f16(v0 - __half2float(h0), v1 - __half2float(h1));
                    *(uint32_t*)(Clo + (size_t)(row + 8) * (3 * EE) + col) =
                        pack_f16(v2 - __half2float(h2), v3 - __half2float(h3));
                }
            } else {
                if (EPI == 1 || EPI == 3) {
                    v0 = gelu_exact(v0); v1 = gelu_exact(v1);
                    v2 = gelu_exact(v2); v3 = gelu_exact(v3);
                }
                int col = colB + colLoc;
                if (EPI <= 1) {
                    float2 p0 = {v0, v1}, p1 = {v2, v3};
                    *(float2*)(C + (size_t)row * N + col) = p0;
                    *(float2*)(C + (size_t)(row + 8) * N + col) = p1;
                } else {
                    __half h0 = __float2half_rn(v0), h1 = __float2half_rn(v1);
                    __half h2 = __float2half_rn(v2), h3 = __float2half_rn(v3);
                    uint32_t hp0 = (uint32_t)__half_as_ushort(h0) |
                                   ((uint32_t)__half_as_ushort(h1) << 16);
                    uint32_t hp1 = (uint32_t)__half_as_ushort(h2) |
                                   ((uint32_t)__half_as_ushort(h3) << 16);
                    *(uint32_t*)(Chi + (size_t)row * N + col) = hp0;
                    *(uint32_t*)(Chi + (size_t)(row + 8) * N + col) = hp1;
                    *(uint32_t*)(Clo + (size_t)row * N + col) =
                        pack_f16(v0 - __half2float(h0), v1 - __half2float(h1));
                    *(uint32_t*)(Clo + (size_t)(row + 8) * N + col) =
                        pack_f16(v2 - __half2float(h2), v3 - __half2float(h3));
                }
            }
        }
}

// =================== tensor-core flash attention (fp16 split) ================
#define ATT_SQH 0
#define ATT_SQL 18432
#define ATT_SKH 36864
#define ATT_SKL 46080
#define ATT_SVH 55296
#define ATT_SVL 64512
#define ATT_SMEM 73728
#define QSTR 3072

__global__ __launch_bounds__(256) void attn_mma(
        const __half* __restrict__ qh, const __half* __restrict__ ql,
        __half* __restrict__ oh, __half* __restrict__ ol) {
    extern __shared__ __align__(128) char smem[];
    uint32_t sb = smem_u32(smem);
    int tid = threadIdx.x, lane = tid & 31, warp = tid >> 5;
    int qt = blockIdx.x, h = blockIdx.y, b = blockIdx.z;
    int rb = b * SS;

    #pragma unroll
    for (int i = 0; i < 4; i++) {
        int idx = tid + i * 256;
        int r = idx >> 3, c8 = idx & 7;
        size_t srow = (size_t)(rb + qt * 128 + r) * QSTR + h * 64 + c8 * 8;
        *(uint4*)(smem + ATT_SQH + r * 144 + c8 * 16) = *(const uint4*)(qh + srow);
        *(uint4*)(smem + ATT_SQL + r * 144 + c8 * 16) = *(const uint4*)(ql + srow);
    }

    float m0 = -1e30f, m1 = -1e30f, l0 = 0.0f, l1 = 0.0f;
    float accO[8][4];
    #pragma unroll
    for (int i = 0; i < 8; i++)
        #pragma unroll
        for (int j = 0; j < 4; j++) accO[i][j] = 0.0f;

    uint32_t aAddr = sb + ATT_SQH + (uint32_t)((warp * 16 + (lane & 15)) * 144 + (lane >> 4) * 16);
    uint32_t bOff  = (uint32_t)(((lane & 7) + ((lane >> 4) << 3)) * 144 + ((lane >> 3) & 1) * 16);
    uint32_t vOff  = (uint32_t)(((lane & 7) + ((lane >> 3) & 1) * 8) * 144 + ((lane >> 4) & 1) * 16);

    __syncthreads();

    for (int kv0 = 0; kv0 < SS; kv0 += 64) {
        #pragma unroll
        for (int i = 0; i < 2; i++) {
            int idx = tid + i * 256;
            int r = idx >> 3, c8 = idx & 7;
            size_t srow = (size_t)(rb + kv0 + r) * QSTR + h * 64 + c8 * 8;
            *(uint4*)(smem + ATT_SKH + r * 144 + c8 * 16) = *(const uint4*)(qh + srow + 1024);
            *(uint4*)(smem + ATT_SKL + r * 144 + c8 * 16) = *(const uint4*)(ql + srow + 1024);
            *(uint4*)(smem + ATT_SVH + r * 144 + c8 * 16) = *(const uint4*)(qh + srow + 2048);
            *(uint4*)(smem + ATT_SVL + r * 144 + c8 * 16) = *(const uint4*)(ql + srow + 2048);
        }
        __syncthreads();

        float s[8][4];
        #pragma unroll
        for (int i = 0; i < 8; i++)
            #pragma unroll
            for (int j = 0; j < 4; j++) s[i][j] = 0.0f;

        #pragma unroll
        for (int kc = 0; kc < 4; kc++) {
            uint32_t ah0, ah1, ah2, ah3, al0, al1, al2, al3;
            ldm_x4(ah0, ah1, ah2, ah3, aAddr + kc * 32);
            ldm_x4(al0, al1, al2, al3, aAddr + (ATT_SQL - ATT_SQH) + kc * 32);
            #pragma unroll
            for (int nh = 0; nh < 4; nh++) {
                uint32_t ba = sb + ATT_SKH + (uint32_t)(nh * 16 * 144) + bOff + kc * 32;
                uint32_t bh_[4], bl_[4];
                ldm_x4(bh_[0], bh_[1], bh_[2], bh_[3], ba);
                ldm_x4(bl_[0], bl_[1], bl_[2], bl_[3], ba + (ATT_SKL - ATT_SKH));
                #pragma unroll
                for (int o = 0; o < 2; o++) {
                    int nt = nh * 2 + o;
                    mma_f32(s[nt], ah0, ah1, ah2, ah3, bh_[o * 2], bh_[o * 2 + 1]);
                    mma_f32(s[nt], ah0, ah1, ah2, ah3, bl_[o * 2], bl_[o * 2 + 1]);
                    mma_f32(s[nt], al0, al1, al2, al3, bh_[o * 2], bh_[o * 2 + 1]);
                }
            }
        }

        float mx0 = -1e30f, mx1 = -1e30f;
        #pragma unroll
        for (int nt = 0; nt < 8; nt++) {
            s[nt][0] *= 0.125f; s[nt][1] *= 0.125f; s[nt][2] *= 0.125f; s[nt][3] *= 0.125f;
            mx0 = fmaxf(mx0, fmaxf(s[nt][0], s[nt][1]));
            mx1 = fmaxf(mx1, fmaxf(s[nt][2], s[nt][3]));
        }
        mx0 = fmaxf(mx0, __shfl_xor_sync(0xffffffffu, mx0, 1));
        mx0 = fmaxf(mx0, __shfl_xor_sync(0xffffffffu, mx0, 2));
        mx1 = fmaxf(mx1, __shfl_xor_sync(0xffffffffu, mx1, 1));
        mx1 = fmaxf(mx1, __shfl_xor_sync(0xffffffffu, mx1, 2));
        float mn0 = fmaxf(m0, mx0), mn1 = fmaxf(m1, mx1);
        float alpha0 = __expf(m0 - mn0), alpha1 = __expf(m1 - mn1);
        m0 = mn0; m1 = mn1;
        float sum0 = 0.0f, sum1 = 0.0f;
        #pragma unroll
        for (int nt = 0; nt < 8; nt++) {
            s[nt][0] = __expf(s[nt][0] - m0);
            s[nt][1] = __expf(s[nt][1] - m0);
            s[nt][2] = __expf(s[nt][2] - m1);
            s[nt][3] = __expf(s[nt][3] - m1);
            sum0 += s[nt][0] + s[nt][1];
            sum1 += s[nt][2] + s[nt][3];
        }
        sum0 += __shfl_xor_sync(0xffffffffu, sum0, 1);
        sum0 += __shfl_xor_sync(0xffffffffu, sum0, 2);
        sum1 += __shfl_xor_sync(0xffffffffu, sum1, 1);
        sum1 += __shfl_xor_sync(0xffffffffu, sum1, 2);
        l0 = l0 * alpha0 + sum0;
        l1 = l1 * alpha1 + sum1;
        #pragma unroll
        for (int dt = 0; dt < 8; dt++) {
            accO[dt][0] *= alpha0; accO[dt][1] *= alpha0;
            accO[dt][2] *= alpha1; accO[dt][3] *= alpha1;
        }

        #pragma unroll
        for (int kc2 = 0; kc2 < 4; kc2++) {
            int n0 = kc2 * 2, n1 = kc2 * 2 + 1;
            __half h00 = __float2half_rn(s[n0][0]), h01 = __float2half_rn(s[n0][1]);
            __half h02 = __float2half_rn(s[n0][2]), h03 = __float2half_rn(s[n0][3]);
            __half h10 = __float2half_rn(s[n1][0]), h11 = __float2half_rn(s[n1][1]);
            __half h12 = __float2half_rn(s[n1][2]), h13 = __float2half_rn(s[n1][3]);
            uint32_t ph0 = (uint32_t)__half_as_ushort(h00) | ((uint32_t)__half_as_ushort(h01) << 16);
            uint32_t ph1 = (uint32_t)__half_as_ushort(h02) | ((uint32_t)__half_as_ushort(h03) << 16);
            uint32_t ph2 = (uint32_t)__half_as_ushort(h10) | ((uint32_t)__half_as_ushort(h11) << 16);
            uint32_t ph3 = (uint32_t)__half_as_ushort(h12) | ((uint32_t)__half_as_ushort(h13) << 16);
            uint32_t pl0 = pack_f16(s[n0][0] - __half2float(h00), s[n0][1] - __half2float(h01));
            uint32_t pl1 = pack_f16(s[n0][2] - __half2float(h02), s[n0][3] - __half2float(h03));
            uint32_t pl2 = pack_f16(s[n1][0] - __half2float(h10), s[n1][1] - __half2float(h11));
            uint32_t pl3 = pack_f16(s[n1][2] - __half2float(h12), s[n1][3] - __half2float(h13));
            #pragma unroll
            for (int nd = 0; nd < 4; nd++) {
                uint32_t va = sb + ATT_SVH + (uint32_t)(kc2 * 16 * 144) + vOff + nd * 32;
                uint32_t vh_[4], vl_[4];
                ldm_x4_t(vh_[0], vh_[1], vh_[2], vh_[3], va);
                ldm_x4_t(vl_[0], vl_[1], vl_[2], vl_[3], va + (ATT_SVL - ATT_SVH));
                #pragma unroll
                for (int o = 0; o < 2; o++) {
                    int dt = nd * 2 + o;
                    mma_f32(accO[dt], ph0, ph1, ph2, ph3, vh_[o * 2], vh_[o * 2 + 1]);
                    mma_f32(accO[dt], ph0, ph1, ph2, ph3, vl_[o * 2], vl_[o * 2 + 1]);
                    mma_f32(accO[dt], pl0, pl1, pl2, pl3, vh_[o * 2], vh_[o * 2 + 1]);
                }
            }
        }
        __syncthreads();
    }

    float inv0 = 1.0f / l0, inv1 = 1.0f / l1;
    int g = lane >> 2, c2 = (lane & 3) * 2;
    int row = rb + qt * 128 + warp * 16 + g;
    int colb = h * 64 + c2;
    #pragma unroll
    for (int dt = 0; dt < 8; dt++) {
        float v0 = accO[dt][0] * inv0, v1 = accO[dt][1] * inv0;
        float v2 = accO[dt][2] * inv1, v3 = accO[dt][3] * inv1;
        __half h0 = __float2half_rn(v0), h1 = __float2half_rn(v1);
        __half h2 = __float2half_rn(v2), h3 = __float2half_rn(v3);
        uint32_t hp0 = (uint32_t)__half_as_ushort(h0) | ((uint32_t)__half_as_ushort(h1) << 16);
        uint32_t hp1 = (uint32_t)__half_as_ushort(h2) | ((uint32_t)__half_as_ushort(h3) << 16);
        int col = colb + dt * 8;
        *(uint32_t*)(oh + (size_t)row * EE + col) = hp0;
        *(uint32_t*)(oh + (size_t)(row + 8) * EE + col) = hp1;
        *(uint32_t*)(ol + (size_t)row * EE + col) =
            pack_f16(v0 - __half2float(h0), v1 - __half2float(h1));
        *(uint32_t*)(ol + (size_t)(row + 8) * EE + col) =
            pack_f16(v2 - __half2float(h2), v3 - __half2float(h3));
    }
}

// ---------------- fp32 -> fp16 hi/lo split -----------------------------------
__global__ __launch_bounds__(256) void split_kernel(const float* __restrict__ in,
                                                    __half* __restrict__ hi,
                                                    __half* __restrict__ lo,
                                                    int n4) {
    int i = blockIdx.x * 256 + threadIdx.x;
    if (i >= n4) return;
    float4 v = ((const float4*)in)[i];
    float x[4] = {v.x, v.y, v.z, v.w};
    uint32_t hw[4], lw[4];
    #pragma unroll
    for (int k = 0; k < 4; k++) {
        __half h = __float2half_rn(x[k]);
        float rr = x[k] - __half2float(h);
        __half l = __float2half_rn(rr);
        hw[k] = (uint32_t)__half_as_ushort(h);
        lw[k] = (uint32_t)__half_as_ushort(l);
    }
    uint2 ho, loo;
    ho.x  = hw[0] | (hw[1] << 16);  ho.y  = hw[2] | (hw[3] << 16);
    loo.x = lw[0] | (lw[1] << 16);  loo.y = lw[2] | (lw[3] << 16);
    ((uint2*)hi)[i] = ho;
    ((uint2*)lo)[i] = loo;
}

// ---------------- y = LN(a + b) * g + beta (+ fp16 split) --------------------
__global__ __launch_bounds__(256) void add_ln_split_kernel(const float* __restrict__ a,
                                                           const float* __restrict__ bsrc,
                                                           const float* __restrict__ g,
                                                           const float* __restrict__ beta,
                                                           float* __restrict__ y,
                                                           __half* __restrict__ yh,
                                                           __half* __restrict__ yl) {
    int row = blockIdx.x;
    int tid = threadIdx.x;
    const float* ar = a + (size_t)row * EE;
    const float* br = bsrc + (size_t)row * EE;
    float v[4];
    float s = 0.0f, s2 = 0.0f;
    #pragma unroll
    for (int k = 0; k < 4; k++) {
        float t = ar[tid + 256 * k] + br[tid + 256 * k];
        v[k] = t; s += t; s2 += t * t;
    }
    __shared__ float red[18];
    #pragma unroll
    for (int off = 16; off; off >>= 1) {
        s  += __shfl_xor_sync(0xffffffffu, s,  off);
        s2 += __shfl_xor_sync(0xffffffffu, s2, off);
    }
    int wid = tid >> 5, lid = tid & 31;
    if (lid == 0) { red[wid] = s; red[wid + 8] = s2; }
    __syncthreads();
    if (tid < 32) {
        float a1 = (tid < 8) ? red[tid] : 0.0f;
        float a2 = (tid < 8) ? red[tid + 8] : 0.0f;
        #pragma unroll
        for (int off = 4; off; off >>= 1) {
            a1 += __shfl_xor_sync(0xffffffffu, a1, off);
            a2 += __shfl_xor_sync(0xffffffffu, a2, off);
        }
        if (tid == 0) { red[16] = a1; red[17] = a2; }
    }
    __syncthreads();
    float mu = red[16] * (1.0f / EE);
    float var = red[17] * (1.0f / EE) - mu * mu;
    float rs = rsqrtf(var + 1e-5f);
    float* yr = y + (size_t)row * EE;
    __half* yhr = yh + (size_t)row * EE;
    __half* ylr = yl + (size_t)row * EE;
    #pragma unroll
    for (int k = 0; k < 4; k++) {
        int c = tid + 256 * k;
        float val = (v[k] - mu) * rs * g[c] + beta[c];
        yr[c] = val;
        __half h = __float2half_rn(val);
        yhr[c] = h;
        ylr[c] = __float2half_rn(val - __half2float(h));
    }
}

// ---------------- mean-pool over S -------------------------------------------
__global__ __launch_bounds__(256) void pool_kernel(const float* __restrict__ x,
                                                   float* __restrict__ pooled) {
    int idx = blockIdx.x * 256 + threadIdx.x;
    int b = idx >> 10, e = idx & 1023;
    const float* p = x + (size_t)b * SS * EE + e;
    float s = 0.0f;
    for (int sI = 0; sI < SS; sI++) s += p[(size_t)sI * EE];
    pooled[idx] = s * (1.0f / SS);
}

// ---------------- complexity estimator ---------------------------------------
__global__ __launch_bounds__(256) void ce_kernel(const float* __restrict__ pooled,
                                                 const float* __restrict__ w1,
                                                 const float* __restrict__ b1,
                                                 const float* __restrict__ w2,
                                                 const float* __restrict__ b2,
                                                 float* __restrict__ out) {
    int b = blockIdx.x, j = threadIdx.x;
    const float* p = pooled + b * EE;
    const float* w = w1 + (size_t)j * EE;
    float s = b1[j];
    for (int k = 0; k < EE; k++) s = fmaf(p[k], w[k], s);
    float h = fmaxf(s, 0.0f);
    __shared__ float red[256];
    red[j] = h * w2[j];
    __syncthreads();
    for (int off = 128; off; off >>= 1) {
        if (j < off) red[j] += red[j + off];
        __syncthreads();
    }
    if (j == 0) {
        float logit = red[0] + b2[0];
        float prob = 1.0f / (1.0f + expf(-logit));
        out[OFF_PROBS + b] = prob;
        out[OFF_MODE + b] = (prob > 0.5f) ? 1.0f : 0.0f;
    }
}

// ---------------- select + mean(mode) ----------------------------------------
__global__ __launch_bounds__(256) void finalize_kernel(const float* __restrict__ t,
                                                       const float* __restrict__ f,
                                                       float* __restrict__ out) {
    size_t i = (size_t)blockIdx.x * 256 + threadIdx.x;
    int b = (int)((i * 4) >> 20);
    float m = out[OFF_MODE + b];
    float4 r = (m > 0.5f) ? ((const float4*)t)[i] : ((const float4*)f)[i];
    ((float4*)out)[i] = r;
    if (i == 0) {
        float sAcc = 0.0f;
        for (int k = 0; k < 8; k++) sAcc += out[OFF_MODE + k];
        out[OFF_MEAN] = sAcc * 0.125f;
    }
}

// -----------------------------------------------------------------------------
extern "C" void kernel_launch(void* const* d_in, const int* in_sizes, int n_in,
                              void* d_out, int out_size) {
    const float* x      = (const float*)d_in[0];
    const float* w_in   = (const float*)d_in[1];
    const float* w_out  = (const float*)d_in[2];
    const float* ffn_w1 = (const float*)d_in[3];
    const float* ffn_w2 = (const float*)d_in[4];
    const float* ln1_g  = (const float*)d_in[5];
    const float* ln1_b  = (const float*)d_in[6];
    const float* ln2_g  = (const float*)d_in[7];
    const float* ln2_b  = (const float*)d_in[8];
    const float* ce_w1  = (const float*)d_in[9];
    const float* ce_b1  = (const float*)d_in[10];
    const float* ce_w2  = (const float*)d_in[11];
    const float* ce_b2  = (const float*)d_in[12];
    const float* fast_w = (const float*)d_in[13];
    float* out = (float*)d_out;

    float *bufA, *bufB, *bufT, *bufT1, *bufFast, *pooled;
    __half *wbh, *wbl, *ah, *al, *bh, *bl;
    cudaGetSymbolAddress((void**)&bufA, g_bufA);
    cudaGetSymbolAddress((void**)&bufB, g_bufB);
    cudaGetSymbolAddress((void**)&bufT, g_bufT);
    cudaGetSymbolAddress((void**)&bufT1, g_bufT1);
    cudaGetSymbolAddress((void**)&bufFast, g_bufFast);
    cudaGetSymbolAddress((void**)&pooled, g_pooled);
    cudaGetSymbolAddress((void**)&wbh, g_wb_hi);
    cudaGetSymbolAddress((void**)&wbl, g_wb_lo);
    cudaGetSymbolAddress((void**)&ah, g_actA_hi);
    cudaGetSymbolAddress((void**)&al, g_actA_lo);
    cudaGetSymbolAddress((void**)&bh, g_actB_hi);
    cudaGetSymbolAddress((void**)&bl, g_actB_lo);

    cudaFuncSetAttribute(mma_gemm<0>, cudaFuncAttributeMaxDynamicSharedMemorySize, SMT);
    cudaFuncSetAttribute(mma_gemm<2>, cudaFuncAttributeMaxDynamicSharedMemorySize, SMT);
    cudaFuncSetAttribute(mma_gemm<3>, cudaFuncAttributeMaxDynamicSharedMemorySize, SMT);
    cudaFuncSetAttribute(mma_gemm<4>, cudaFuncAttributeMaxDynamicSharedMemorySize, SMT);
    cudaFuncSetAttribute(attn_mma, cudaFuncAttributeMaxDynamicSharedMemorySize, ATT_SMEM);

    // weight splits
    split_kernel<<<(2*3*EE*EE/4)/256, 256>>>(w_in,   wbh + OW_IN,   wbl + OW_IN,   2*3*EE*EE/4);
    split_kernel<<<(2*EE*EE/4)/256,   256>>>(w_out,  wbh + OW_OUT,  wbl + OW_OUT,  2*EE*EE/4);
    split_kernel<<<(2*4*EE*EE/4)/256, 256>>>(ffn_w1, wbh + OW_F1,   wbl + OW_F1,   2*4*EE*EE/4);
    split_kernel<<<(2*4*EE*EE/4)/256, 256>>>(ffn_w2, wbh + OW_F2,   wbl + OW_F2,   2*4*EE*EE/4);
    split_kernel<<<(EE*EE/4)/256,     256>>>(fast_w, wbh + OW_FAST, wbl + OW_FAST, EE*EE/4);

    // complexity estimator
    pool_kernel<<<(BB * EE) / 256, 256>>>(x, pooled);
    ce_kernel<<<BB, 256>>>(pooled, ce_w1, ce_b1, ce_w2, ce_b2, out);

    // split x -> A (serves fused fast+qkv layer 0)
    split_kernel<<<(MROWS*EE/4)/256, 256>>>(x, ah, al, MROWS*EE/4);

    // thinking path
    const float* tin = x;
    for (int l = 0; l < LL; l++) {
        if (l == 0) {
            // fused: qkv (cols 0..3071 -> bh/bl split) + fast path (cols 3072..4095 -> gelu fp32)
            mma_gemm<4><<<dim3(4*EE/128, MROWS/128), 256, SMT>>>(
                ah, al, wbh + OW_IN, wbl + OW_IN, wbh + OW_FAST, wbl + OW_FAST,
                nullptr, bh, bl, bufFast, 4*EE, EE);
        } else {
            mma_gemm<2><<<dim3(3*EE/128, MROWS/128), 256, SMT>>>(
                ah, al, wbh + OW_IN + (size_t)l*3*EE*EE, wbl + OW_IN + (size_t)l*3*EE*EE,
                nullptr, nullptr, nullptr, bh, bl, nullptr, 3*EE, EE);
        }
        attn_mma<<<dim3(SS/128, HH, BB), 256, ATT_SMEM>>>(bh, bl, ah, al);
        mma_gemm<0><<<dim3(EE/128, MROWS/128), 256, SMT>>>(
            ah, al, wbh + OW_OUT + (size_t)l*EE*EE, wbl + OW_OUT + (size_t)l*EE*EE,
            nullptr, nullptr, bufA, nullptr, nullptr, nullptr, EE, EE);
        add_ln_split_kernel<<<MROWS, 256>>>(tin, bufA, ln1_g + l*EE, ln1_b + l*EE,
                                            bufT1, ah, al);
        mma_gemm<3><<<dim3(4*EE/128, MROWS/128), 256, SMT>>>(
            ah, al, wbh + OW_F1 + (size_t)l*4*EE*EE, wbl + OW_F1 + (size_t)l*4*EE*EE,
            nullptr, nullptr, nullptr, bh, bl, nullptr, 4*EE, EE);
        mma_gemm<0><<<dim3(EE/128, MROWS/128), 256, SMT>>>(
            bh, bl, wbh + OW_F2 + (size_t)l*4*EE*EE, wbl + OW_F2 + (size_t)l*4*EE*EE,
            nullptr, nullptr, bufB, nullptr, nullptr, nullptr, EE, 4*EE);
        add_ln_split_kernel<<<MROWS, 256>>>(bufT1, bufB, ln2_g + l*EE, ln2_b + l*EE,
                                            bufT, ah, al);
        tin = bufT;
    }

    finalize_kernel<<<(MROWS * EE / 4) / 256, 256>>>(bufT, bufFast, out);
}

// round 11
// speedup vs baseline: 1.1066x; 1.0011x over previous
#include <cuda_runtime.h>
#include <cuda_fp16.h>
#include <math.h>
#include <stdint.h>

#define BB 8
#define SS 1024
#define EE 1024
#define HH 16
#define DD 64
#define LL 2
#define MROWS (BB*SS)              // 8192
#define OUT_MAIN (BB*SS*EE)        // 8388608
#define OFF_PROBS OUT_MAIN
#define OFF_MODE  (OUT_MAIN + 8)
#define OFF_MEAN  (OUT_MAIN + 16)

// ---------------- scratch (device globals; no allocation allowed) ------------
__device__ float g_bufA[MROWS * EE];     // out-proj fp32
__device__ float g_bufB[MROWS * EE];     // ffn2 out fp32
__device__ float g_bufT[MROWS * EE];     // t (post layer)
__device__ float g_bufT1[MROWS * EE];    // t1 (post LN1)
__device__ float g_bufFast[MROWS * EE];  // fast path
__device__ float g_pooled[BB * EE];

// fp16 split buffers
#define NW_TOTAL 26214400
#define OW_IN   0
#define OW_OUT  6291456
#define OW_F1   8388608
#define OW_F2   16777216
#define OW_FAST 25165824
__device__ __half g_wb_hi[NW_TOTAL];
__device__ __half g_wb_lo[NW_TOTAL];
__device__ __half g_actA_hi[MROWS * 1024];   // narrow activations
__device__ __half g_actA_lo[MROWS * 1024];
__device__ __half g_actB_hi[MROWS * 4096];   // qkv (3072) / ffn hidden (4096)
__device__ __half g_actB_lo[MROWS * 4096];

__device__ __forceinline__ float gelu_exact(float v) {
    return 0.5f * v * (1.0f + erff(v * 0.7071067811865476f));
}
__device__ __forceinline__ uint32_t pack_f16(float a, float b) {
    __half2 t = __floats2half2_rn(a, b);
    return *(uint32_t*)&t;
}

// =================== portable tensor-core primitives (sm_80+ PTX) ============
__device__ __forceinline__ uint32_t smem_u32(const void* p) {
    uint32_t a;
    asm("{ .reg .u64 t; cvta.to.shared.u64 t, %1; cvt.u32.u64 %0, t; }" : "=r"(a) : "l"(p));
    return a;
}
__device__ __forceinline__ void ldm_x4(uint32_t& r0, uint32_t& r1, uint32_t& r2, uint32_t& r3,
                                       uint32_t addr) {
    asm volatile("ldmatrix.sync.aligned.m8n8.x4.shared.b16 {%0,%1,%2,%3}, [%4];"
                 : "=r"(r0), "=r"(r1), "=r"(r2), "=r"(r3) : "r"(addr));
}
__device__ __forceinline__ void ldm_x4_t(uint32_t& r0, uint32_t& r1, uint32_t& r2, uint32_t& r3,
                                         uint32_t addr) {
    asm volatile("ldmatrix.sync.aligned.m8n8.x4.trans.shared.b16 {%0,%1,%2,%3}, [%4];"
                 : "=r"(r0), "=r"(r1), "=r"(r2), "=r"(r3) : "r"(addr));
}
__device__ __forceinline__ void mma_f32(float* c, uint32_t a0, uint32_t a1, uint32_t a2,
                                        uint32_t a3, uint32_t b0, uint32_t b1) {
    asm volatile(
        "mma.sync.aligned.m16n8k16.row.col.f32.f16.f16.f32 "
        "{%0,%1,%2,%3}, {%4,%5,%6,%7}, {%8,%9}, {%0,%1,%2,%3};"
        : "+f"(c[0]), "+f"(c[1]), "+f"(c[2]), "+f"(c[3])
        : "r"(a0), "r"(a1), "r"(a2), "r"(a3), "r"(b0), "r"(b1));
}
__device__ __forceinline__ void cp16(uint32_t saddr, const void* g) {
    asm volatile("cp.async.cg.shared.global [%0], [%1], 16;" :: "r"(saddr), "l"(g));
}
#define CP_COMMIT() asm volatile("cp.async.commit_group;" ::: "memory")
#define CP_WAIT(N)  asm volatile("cp.async.wait_group %0;" :: "n"(N) : "memory")

// =================== mma.sync GEMM: C[M,N] = A[M,K] @ B[N,K]^T ===============
// 128x128 block, 8 warps (2M x 4N), warp tile 64x32, K-chunk 32.
// 3 mma_f32 per fragment (hh + hl + lh). Single barrier per chunk.
// EPI: 0 fp32, 1 gelu fp32, 2 fp16 split, 3 gelu+split,
//      4 fused qkv+fast (cols<3072: split->Chi/Clo stride 3072;
//                        cols>=3072: gelu fp32 -> CF stride 1024, B from BhiF/BloF)
#define TIL   10240
#define STAGE (4 * TIL)
#define SMT   (2 * STAGE)

__device__ __forceinline__ void copy_tile_async(uint32_t sdst, const __half* __restrict__ g,
                                                int row0, int K, int k0, int tid) {
    #pragma unroll
    for (int i = 0; i < 2; i++) {
        int idx = tid + i * 256;
        int r = idx >> 2, c4 = idx & 3;
        cp16(sdst + r * 80 + c4 * 16, g + (size_t)(row0 + r) * K + k0 + c4 * 8);
    }
}

template<int EPI>
__global__ __launch_bounds__(256, 2) void mma_gemm(
        const __half* __restrict__ Ahi, const __half* __restrict__ Alo,
        const __half* __restrict__ Bhi, const __half* __restrict__ Blo,
        const __half* __restrict__ BhiF, const __half* __restrict__ BloF,
        float* __restrict__ C, __half* __restrict__ Chi,
        __half* __restrict__ Clo, float* __restrict__ CF, int N, int K) {
    extern __shared__ __align__(128) char smem[];
    uint32_t sb = smem_u32(smem);
    int tid = threadIdx.x, lane = tid & 31, warp = tid >> 5;
    int wm = warp & 1, wn = warp >> 1;
    int rowB = blockIdx.y * 128, colB = blockIdx.x * 128;

    const __half* BhU = Bhi;
    const __half* BlU = Blo;
    int bcol = colB;
    bool isFast = false;
    if (EPI == 4 && colB >= 3 * EE) {
        BhU = BhiF; BlU = BloF; bcol = colB - 3 * EE; isFast = true;
    }

    int aRow = wm * 64 + (lane & 15);
    int aK   = (lane >> 4) * 8;
    uint32_t aOff = (uint32_t)(aRow * 80 + aK * 2);
    int bRow = wn * 32 + ((lane >> 4) << 3) + (lane & 7);
    int bK   = ((lane >> 3) & 1) * 8;
    uint32_t bOff = (uint32_t)(bRow * 80 + bK * 2);

    float acc[4][4][4];
    #pragma unroll
    for (int i = 0; i < 4; i++)
        #pragma unroll
        for (int j = 0; j < 4; j++)
            #pragma unroll
            for (int k = 0; k < 4; k++) acc[i][j][k] = 0.0f;

    int nch = K >> 5;
    {
        copy_tile_async(sb + 0 * TIL, Ahi, rowB, K, 0, tid);
        copy_tile_async(sb + 1 * TIL, Alo, rowB, K, 0, tid);
        copy_tile_async(sb + 2 * TIL, BhU, bcol, K, 0, tid);
        copy_tile_async(sb + 3 * TIL, BlU, bcol, K, 0, tid);
        CP_COMMIT();
    }

    for (int c = 0; c < nch; c++) {
        CP_WAIT(0);
        __syncthreads();   // cp(c) visible; all warps done reading stage (c+1)&1
        if (c + 1 < nch) {
            uint32_t sn = sb + ((c + 1) & 1) * STAGE;
            int k0 = (c + 1) * 32;
            copy_tile_async(sn + 0 * TIL, Ahi, rowB, K, k0, tid);
            copy_tile_async(sn + 1 * TIL, Alo, rowB, K, k0, tid);
            copy_tile_async(sn + 2 * TIL, BhU, bcol, K, k0, tid);
            copy_tile_async(sn + 3 * TIL, BlU, bcol, K, k0, tid);
            CP_COMMIT();
        }

        uint32_t ss = sb + (c & 1) * STAGE;
        uint32_t sAh = ss + aOff, sAl = ss + TIL + aOff;
        uint32_t sBh = ss + 2 * TIL + bOff, sBl = ss + 3 * TIL + bOff;

        #pragma unroll
        for (int k16 = 0; k16 < 2; k16++) {
            uint32_t kb = k16 * 32;
            uint32_t bh[2][4], bl[2][4];
            #pragma unroll
            for (int nh = 0; nh < 2; nh++) {
                uint32_t off = (uint32_t)(nh * 16 * 80) + kb;
                ldm_x4(bh[nh][0], bh[nh][1], bh[nh][2], bh[nh][3], sBh + off);
                ldm_x4(bl[nh][0], bl[nh][1], bl[nh][2], bl[nh][3], sBl + off);
            }
            #pragma unroll
            for (int mt = 0; mt < 4; mt++) {
                uint32_t off = (uint32_t)(mt * 16 * 80) + kb;
                uint32_t ah0, ah1, ah2, ah3, al0, al1, al2, al3;
                ldm_x4(ah0, ah1, ah2, ah3, sAh + off);
                ldm_x4(al0, al1, al2, al3, sAl + off);
                #pragma unroll
                for (int nt = 0; nt < 4; nt++) {
                    int nh = nt >> 1, o = (nt & 1) * 2;
                    mma_f32(acc[mt][nt], ah0, ah1, ah2, ah3, bh[nh][o], bh[nh][o + 1]);
                    mma_f32(acc[mt][nt], ah0, ah1, ah2, ah3, bl[nh][o], bl[nh][o + 1]);
                    mma_f32(acc[mt][nt], al0, al1, al2, al3, bh[nh][o], bh[nh][o + 1]);
                }
            }
        }
    }

    int r = lane >> 2, c2 = (lane & 3) * 2;
    int row0 = rowB + wm * 64;
    #pragma unroll
    for (int mt = 0; mt < 4; mt++)
        #pragma unroll
        for (int nt = 0; nt < 4; nt++) {
            float v0 = acc[mt][nt][0], v1 = acc[mt][nt][1];
            float v2 = acc[mt][nt][2], v3 = acc[mt][nt][3];
            int row = row0 + mt * 16 + r;
            int colLoc = wn * 32 + nt * 8 + c2;    // 0..127 within tile
            if (EPI == 4) {
                if (isFast) {
                    v0 = gelu_exact(v0); v1 = gelu_exact(v1);
                    v2 = gelu_exact(v2); v3 = gelu_exact(v3);
                    int col = bcol + colLoc;
                    float2 p0 = {v0, v1}, p1 = {v2, v3};
                    *(float2*)(CF + (size_t)row * EE + col) = p0;
                    *(float2*)(CF + (size_t)(row + 8) * EE + col) = p1;
                } else {
                    int col = colB + colLoc;
                    __half h0 = __float2half_rn(v0), h1 = __float2half_rn(v1);
                    __half h2 = __float2half_rn(v2), h3 = __float2half_rn(v3);
                    uint32_t hp0 = (uint32_t)__half_as_ushort(h0) |
                                   ((uint32_t)__half_as_ushort(h1) << 16);
                    uint32_t hp1 = (uint32_t)__half_as_ushort(h2) |
                                   ((uint32_t)__half_as_ushort(h3) << 16);
                    *(uint32_t*)(Chi + (size_t)row * (3 * EE) + col) = hp0;
                    *(uint32_t*)(Chi + (size_t)(row + 8) * (3 * EE) + col) = hp1;
                    *(uint32_t*)(Clo + (size_t)row * (3 * EE) + col) =
                        pack_f16(v0 - __half2float(h0), v1 - __half2float(h1));
                    *(uint32_t*)(Clo + (size_t)(row + 8) * (3 * EE) + col) =
                        pack_f16(v2 - __half2float(h2), v3 - __half2float(h3));
                }
            } else {
                if (EPI == 1 || EPI == 3) {
                    v0 = gelu_exact(v0); v1 = gelu_exact(v1);
                    v2 = gelu_exact(v2); v3 = gelu_exact(v3);
                }
                int col = colB + colLoc;
                if (EPI <= 1) {
                    float2 p0 = {v0, v1}, p1 = {v2, v3};
                    *(float2*)(C + (size_t)row * N + col) = p0;
                    *(float2*)(C + (size_t)(row + 8) * N + col) = p1;
                } else {
                    __half h0 = __float2half_rn(v0), h1 = __float2half_rn(v1);
                    __half h2 = __float2half_rn(v2), h3 = __float2half_rn(v3);
                    uint32_t hp0 = (uint32_t)__half_as_ushort(h0) |
                                   ((uint32_t)__half_as_ushort(h1) << 16);
                    uint32_t hp1 = (uint32_t)__half_as_ushort(h2) |
                                   ((uint32_t)__half_as_ushort(h3) << 16);
                    *(uint32_t*)(Chi + (size_t)row * N + col) = hp0;
                    *(uint32_t*)(Chi + (size_t)(row + 8) * N + col) = hp1;
                    *(uint32_t*)(Clo + (size_t)row * N + col) =
                        pack_f16(v0 - __half2float(h0), v1 - __half2float(h1));
                    *(uint32_t*)(Clo + (size_t)(row + 8) * N + col) =
                        pack_f16(v2 - __half2float(h2), v3 - __half2float(h3));
                }
            }
        }
}

// =================== tensor-core flash attention (fp16 split) ================
// cp.async double-buffered KV pipeline: Q hi/lo resident, 2 KV stages.
#define ATT_SQH 0
#define ATT_SQL 18432
#define ATT_KV  36864          // stage base; stage stride 36864
#define ATT_KSTR 36864
#define KOF_KH 0
#define KOF_KL 9216
#define KOF_VH 18432
#define KOF_VL 27648
#define ATT_SMEM 110592
#define QSTR 3072

__device__ __forceinline__ void attn_prefetch_kv(char* smem, uint32_t stageOff,
        const __half* __restrict__ qh, const __half* __restrict__ ql,
        size_t rowbase, int h, int tid, uint32_t sb) {
    #pragma unroll
    for (int i = 0; i < 2; i++) {
        int idx = tid + i * 256;
        int r = idx >> 3, c8 = idx & 7;
        size_t srow = (rowbase + r) * QSTR + h * 64 + c8 * 8;
        uint32_t d = sb + stageOff + (uint32_t)(r * 144 + c8 * 16);
        cp16(d + KOF_KH, qh + srow + 1024);
        cp16(d + KOF_KL, ql + srow + 1024);
        cp16(d + KOF_VH, qh + srow + 2048);
        cp16(d + KOF_VL, ql + srow + 2048);
    }
}

__global__ __launch_bounds__(256) void attn_mma(
        const __half* __restrict__ qh, const __half* __restrict__ ql,
        __half* __restrict__ oh, __half* __restrict__ ol) {
    extern __shared__ __align__(128) char smem[];
    uint32_t sb = smem_u32(smem);
    int tid = threadIdx.x, lane = tid & 31, warp = tid >> 5;
    int qt = blockIdx.x, h = blockIdx.y, b = blockIdx.z;
    int rb = b * SS;

    // load Q tile (hi + lo) synchronously (once)
    #pragma unroll
    for (int i = 0; i < 4; i++) {
        int idx = tid + i * 256;
        int r = idx >> 3, c8 = idx & 7;
        size_t srow = (size_t)(rb + qt * 128 + r) * QSTR + h * 64 + c8 * 8;
        *(uint4*)(smem + ATT_SQH + r * 144 + c8 * 16) = *(const uint4*)(qh + srow);
        *(uint4*)(smem + ATT_SQL + r * 144 + c8 * 16) = *(const uint4*)(ql + srow);
    }
    // prefetch KV chunk 0 into stage 0
    attn_prefetch_kv(smem, ATT_KV, qh, ql, (size_t)rb, h, tid, sb);
    CP_COMMIT();

    float m0 = -1e30f, m1 = -1e30f, l0 = 0.0f, l1 = 0.0f;
    float accO[8][4];
    #pragma unroll
    for (int i = 0; i < 8; i++)
        #pragma unroll
        for (int j = 0; j < 4; j++) accO[i][j] = 0.0f;

    uint32_t aAddr = sb + ATT_SQH + (uint32_t)((warp * 16 + (lane & 15)) * 144 + (lane >> 4) * 16);
    uint32_t bOff  = (uint32_t)(((lane & 7) + ((lane >> 4) << 3)) * 144 + ((lane >> 3) & 1) * 16);
    uint32_t vOff  = (uint32_t)(((lane & 7) + ((lane >> 3) & 1) * 8) * 144 + ((lane >> 4) & 1) * 16);

    for (int c = 0; c < SS / 64; c++) {
        CP_WAIT(0);
        __syncthreads();   // stage c data visible; all warps done with stage (c+1)&1
        if (c + 1 < SS / 64) {
            attn_prefetch_kv(smem, ATT_KV + ((c + 1) & 1) * ATT_KSTR,
                             qh, ql, (size_t)(rb + (c + 1) * 64), h, tid, sb);
            CP_COMMIT();
        }
        uint32_t kvB = ATT_KV + (uint32_t)((c & 1) * ATT_KSTR);

        float s[8][4];
        #pragma unroll
        for (int i = 0; i < 8; i++)
            #pragma unroll
            for (int j = 0; j < 4; j++) s[i][j] = 0.0f;

        #pragma unroll
        for (int kc = 0; kc < 4; kc++) {
            uint32_t ah0, ah1, ah2, ah3, al0, al1, al2, al3;
            ldm_x4(ah0, ah1, ah2, ah3, aAddr + kc * 32);
            ldm_x4(al0, al1, al2, al3, aAddr + (ATT_SQL - ATT_SQH) + kc * 32);
            #pragma unroll
            for (int nh = 0; nh < 4; nh++) {
                uint32_t ba = sb + kvB + KOF_KH + (uint32_t)(nh * 16 * 144) + bOff + kc * 32;
                uint32_t bh_[4], bl_[4];
                ldm_x4(bh_[0], bh_[1], bh_[2], bh_[3], ba);
                ldm_x4(bl_[0], bl_[1], bl_[2], bl_[3], ba + (KOF_KL - KOF_KH));
                #pragma unroll
                for (int o = 0; o < 2; o++) {
                    int nt = nh * 2 + o;
                    mma_f32(s[nt], ah0, ah1, ah2, ah3, bh_[o * 2], bh_[o * 2 + 1]);
                    mma_f32(s[nt], ah0, ah1, ah2, ah3, bl_[o * 2], bl_[o * 2 + 1]);
                    mma_f32(s[nt], al0, al1, al2, al3, bh_[o * 2], bh_[o * 2 + 1]);
                }
            }
        }

        float mx0 = -1e30f, mx1 = -1e30f;
        #pragma unroll
        for (int nt = 0; nt < 8; nt++) {
            s[nt][0] *= 0.125f; s[nt][1] *= 0.125f; s[nt][2] *= 0.125f; s[nt][3] *= 0.125f;
            mx0 = fmaxf(mx0, fmaxf(s[nt][0], s[nt][1]));
            mx1 = fmaxf(mx1, fmaxf(s[nt][2], s[nt][3]));
        }
        mx0 = fmaxf(mx0, __shfl_xor_sync(0xffffffffu, mx0, 1));
        mx0 = fmaxf(mx0, __shfl_xor_sync(0xffffffffu, mx0, 2));
        mx1 = fmaxf(mx1, __shfl_xor_sync(0xffffffffu, mx1, 1));
        mx1 = fmaxf(mx1, __shfl_xor_sync(0xffffffffu, mx1, 2));
        float mn0 = fmaxf(m0, mx0), mn1 = fmaxf(m1, mx1);
        float alpha0 = __expf(m0 - mn0), alpha1 = __expf(m1 - mn1);
        m0 = mn0; m1 = mn1;
        float sum0 = 0.0f, sum1 = 0.0f;
        #pragma unroll
        for (int nt = 0; nt < 8; nt++) {
            s[nt][0] = __expf(s[nt][0] - m0);
            s[nt][1] = __expf(s[nt][1] - m0);
            s[nt][2] = __expf(s[nt][2] - m1);
            s[nt][3] = __expf(s[nt][3] - m1);
            sum0 += s[nt][0] + s[nt][1];
            sum1 += s[nt][2] + s[nt][3];
        }
        sum0 += __shfl_xor_sync(0xffffffffu, sum0, 1);
        sum0 += __shfl_xor_sync(0xffffffffu, sum0, 2);
        sum1 += __shfl_xor_sync(0xffffffffu, sum1, 1);
        sum1 += __shfl_xor_sync(0xffffffffu, sum1, 2);
        l0 = l0 * alpha0 + sum0;
        l1 = l1 * alpha1 + sum1;
        #pragma unroll
        for (int dt = 0; dt < 8; dt++) {
            accO[dt][0] *= alpha0; accO[dt][1] *= alpha0;
            accO[dt][2] *= alpha1; accO[dt][3] *= alpha1;
        }

        #pragma unroll
        for (int kc2 = 0; kc2 < 4; kc2++) {
            int n0 = kc2 * 2, n1 = kc2 * 2 + 1;
            __half h00 = __float2half_rn(s[n0][0]), h01 = __float2half_rn(s[n0][1]);
            __half h02 = __float2half_rn(s[n0][2]), h03 = __float2half_rn(s[n0][3]);
            __half h10 = __float2half_rn(s[n1][0]), h11 = __float2half_rn(s[n1][1]);
            __half h12 = __float2half_rn(s[n1][2]), h13 = __float2half_rn(s[n1][3]);
            uint32_t ph0 = (uint32_t)__half_as_ushort(h00) | ((uint32_t)__half_as_ushort(h01) << 16);
            uint32_t ph1 = (uint32_t)__half_as_ushort(h02) | ((uint32_t)__half_as_ushort(h03) << 16);
            uint32_t ph2 = (uint32_t)__half_as_ushort(h10) | ((uint32_t)__half_as_ushort(h11) << 16);
            uint32_t ph3 = (uint32_t)__half_as_ushort(h12) | ((uint32_t)__half_as_ushort(h13) << 16);
            uint32_t pl0 = pack_f16(s[n0][0] - __half2float(h00), s[n0][1] - __half2float(h01));
            uint32_t pl1 = pack_f16(s[n0][2] - __half2float(h02), s[n0][3] - __half2float(h03));
            uint32_t pl2 = pack_f16(s[n1][0] - __half2float(h10), s[n1][1] - __half2float(h11));
            uint32_t pl3 = pack_f16(s[n1][2] - __half2float(h12), s[n1][3] - __half2float(h13));
            #pragma unroll
            for (int nd = 0; nd < 4; nd++) {
                uint32_t va = sb + kvB + KOF_VH + (uint32_t)(kc2 * 16 * 144) + vOff + nd * 32;
                uint32_t vh_[4], vl_[4];
                ldm_x4_t(vh_[0], vh_[1], vh_[2], vh_[3], va);
                ldm_x4_t(vl_[0], vl_[1], vl_[2], vl_[3], va + (KOF_VL - KOF_VH));
                #pragma unroll
                for (int o = 0; o < 2; o++) {
                    int dt = nd * 2 + o;
                    mma_f32(accO[dt], ph0, ph1, ph2, ph3, vh_[o * 2], vh_[o * 2 + 1]);
                    mma_f32(accO[dt], ph0, ph1, ph2, ph3, vl_[o * 2], vl_[o * 2 + 1]);
                    mma_f32(accO[dt], pl0, pl1, pl2, pl3, vh_[o * 2], vh_[o * 2 + 1]);
                }
            }
        }
    }

    float inv0 = 1.0f / l0, inv1 = 1.0f / l1;
    int g = lane >> 2, c2 = (lane & 3) * 2;
    int row = rb + qt * 128 + warp * 16 + g;
    int colb = h * 64 + c2;
    #pragma unroll
    for (int dt = 0; dt < 8; dt++) {
        float v0 = accO[dt][0] * inv0, v1 = accO[dt][1] * inv0;
        float v2 = accO[dt][2] * inv1, v3 = accO[dt][3] * inv1;
        __half h0 = __float2half_rn(v0), h1 = __float2half_rn(v1);
        __half h2 = __float2half_rn(v2), h3 = __float2half_rn(v3);
        uint32_t hp0 = (uint32_t)__half_as_ushort(h0) | ((uint32_t)__half_as_ushort(h1) << 16);
        uint32_t hp1 = (uint32_t)__half_as_ushort(h2) | ((uint32_t)__half_as_ushort(h3) << 16);
        int col = colb + dt * 8;
        *(uint32_t*)(oh + (size_t)row * EE + col) = hp0;
        *(uint32_t*)(oh + (size_t)(row + 8) * EE + col) = hp1;
        *(uint32_t*)(ol + (size_t)row * EE + col) =
            pack_f16(v0 - __half2float(h0), v1 - __half2float(h1));
        *(uint32_t*)(ol + (size_t)(row + 8) * EE + col) =
            pack_f16(v2 - __half2float(h2), v3 - __half2float(h3));
    }
}

// ---------------- fp32 -> fp16 hi/lo split -----------------------------------
__global__ __launch_bounds__(256) void split_kernel(const float* __restrict__ in,
                                                    __half* __restrict__ hi,
                                                    __half* __restrict__ lo,
                                                    int n4) {
    int i = blockIdx.x * 256 + threadIdx.x;
    if (i >= n4) return;
    float4 v = ((const float4*)in)[i];
    float x[4] = {v.x, v.y, v.z, v.w};
    uint32_t hw[4], lw[4];
    #pragma unroll
    for (int k = 0; k < 4; k++) {
        __half h = __float2half_rn(x[k]);
        float rr = x[k] - __half2float(h);
        __half l = __float2half_rn(rr);
        hw[k] = (uint32_t)__half_as_ushort(h);
        lw[k] = (uint32_t)__half_as_ushort(l);
    }
    uint2 ho, loo;
    ho.x  = hw[0] | (hw[1] << 16);  ho.y  = hw[2] | (hw[3] << 16);
    loo.x = lw[0] | (lw[1] << 16);  loo.y = lw[2] | (lw[3] << 16);
    ((uint2*)hi)[i] = ho;
    ((uint2*)lo)[i] = loo;
}

// ---------------- y = LN(a + b) * g + beta (+ fp16 split) --------------------
__global__ __launch_bounds__(256) void add_ln_split_kernel(const float* __restrict__ a,
                                                           const float* __restrict__ bsrc,
                                                           const float* __restrict__ g,
                                                           const float* __restrict__ beta,
                                                           float* __restrict__ y,
                                                           __half* __restrict__ yh,
                                                           __half* __restrict__ yl) {
    int row = blockIdx.x;
    int tid = threadIdx.x;
    const float* ar = a + (size_t)row * EE;
    const float* br = bsrc + (size_t)row * EE;
    float v[4];
    float s = 0.0f, s2 = 0.0f;
    #pragma unroll
    for (int k = 0; k < 4; k++) {
        float t = ar[tid + 256 * k] + br[tid + 256 * k];
        v[k] = t; s += t; s2 += t * t;
    }
    __shared__ float red[18];
    #pragma unroll
    for (int off = 16; off; off >>= 1) {
        s  += __shfl_xor_sync(0xffffffffu, s,  off);
        s2 += __shfl_xor_sync(0xffffffffu, s2, off);
    }
    int wid = tid >> 5, lid = tid & 31;
    if (lid == 0) { red[wid] = s; red[wid + 8] = s2; }
    __syncthreads();
    if (tid < 32) {
        float a1 = (tid < 8) ? red[tid] : 0.0f;
        float a2 = (tid < 8) ? red[tid + 8] : 0.0f;
        #pragma unroll
        for (int off = 4; off; off >>= 1) {
            a1 += __shfl_xor_sync(0xffffffffu, a1, off);
            a2 += __shfl_xor_sync(0xffffffffu, a2, off);
        }
        if (tid == 0) { red[16] = a1; red[17] = a2; }
    }
    __syncthreads();
    float mu = red[16] * (1.0f / EE);
    float var = red[17] * (1.0f / EE) - mu * mu;
    float rs = rsqrtf(var + 1e-5f);
    float* yr = y + (size_t)row * EE;
    __half* yhr = yh + (size_t)row * EE;
    __half* ylr = yl + (size_t)row * EE;
    #pragma unroll
    for (int k = 0; k < 4; k++) {
        int c = tid + 256 * k;
        float val = (v[k] - mu) * rs * g[c] + beta[c];
        yr[c] = val;
        __half h = __float2half_rn(val);
        yhr[c] = h;
        ylr[c] = __float2half_rn(val - __half2float(h));
    }
}

// ---------------- mean-pool over S -------------------------------------------
__global__ __launch_bounds__(256) void pool_kernel(const float* __restrict__ x,
                                                   float* __restrict__ pooled) {
    int idx = blockIdx.x * 256 + threadIdx.x;
    int b = idx >> 10, e = idx & 1023;
    const float* p = x + (size_t)b * SS * EE + e;
    float s = 0.0f;
    for (int sI = 0; sI < SS; sI++) s += p[(size_t)sI * EE];
    pooled[idx] = s * (1.0f / SS);
}

// ---------------- complexity estimator ---------------------------------------
__global__ __launch_bounds__(256) void ce_kernel(const float* __restrict__ pooled,
                                                 const float* __restrict__ w1,
                                                 const float* __restrict__ b1,
                                                 const float* __restrict__ w2,
                                                 const float* __restrict__ b2,
                                                 float* __restrict__ out) {
    int b = blockIdx.x, j = threadIdx.x;
    const float* p = pooled + b * EE;
    const float* w = w1 + (size_t)j * EE;
    float s = b1[j];
    for (int k = 0; k < EE; k++) s = fmaf(p[k], w[k], s);
    float h = fmaxf(s, 0.0f);
    __shared__ float red[256];
    red[j] = h * w2[j];
    __syncthreads();
    for (int off = 128; off; off >>= 1) {
        if (j < off) red[j] += red[j + off];
        __syncthreads();
    }
    if (j == 0) {
        float logit = red[0] + b2[0];
        float prob = 1.0f / (1.0f + expf(-logit));
        out[OFF_PROBS + b] = prob;
        out[OFF_MODE + b] = (prob > 0.5f) ? 1.0f : 0.0f;
    }
}

// ---------------- select + mean(mode) ----------------------------------------
__global__ __launch_bounds__(256) void finalize_kernel(const float* __restrict__ t,
                                                       const float* __restrict__ f,
                                                       float* __restrict__ out) {
    size_t i = (size_t)blockIdx.x * 256 + threadIdx.x;
    int b = (int)((i * 4) >> 20);
    float m = out[OFF_MODE + b];
    float4 r = (m > 0.5f) ? ((const float4*)t)[i] : ((const float4*)f)[i];
    ((float4*)out)[i] = r;
    if (i == 0) {
        float sAcc = 0.0f;
        for (int k = 0; k < 8; k++) sAcc += out[OFF_MODE + k];
        out[OFF_MEAN] = sAcc * 0.125f;
    }
}

// -----------------------------------------------------------------------------
extern "C" void kernel_launch(void* const* d_in, const int* in_sizes, int n_in,
                              void* d_out, int out_size) {
    const float* x      = (const float*)d_in[0];
    const float* w_in   = (const float*)d_in[1];
    const float* w_out  = (const float*)d_in[2];
    const float* ffn_w1 = (const float*)d_in[3];
    const float* ffn_w2 = (const float*)d_in[4];
    const float* ln1_g  = (const float*)d_in[5];
    const float* ln1_b  = (const float*)d_in[6];
    const float* ln2_g  = (const float*)d_in[7];
    const float* ln2_b  = (const float*)d_in[8];
    const float* ce_w1  = (const float*)d_in[9];
    const float* ce_b1  = (const float*)d_in[10];
    const float* ce_w2  = (const float*)d_in[11];
    const float* ce_b2  = (const float*)d_in[12];
    const float* fast_w = (const float*)d_in[13];
    float* out = (float*)d_out;

    float *bufA, *bufB, *bufT, *bufT1, *bufFast, *pooled;
    __half *wbh, *wbl, *ah, *al, *bh, *bl;
    cudaGetSymbolAddress((void**)&bufA, g_bufA);
    cudaGetSymbolAddress((void**)&bufB, g_bufB);
    cudaGetSymbolAddress((void**)&bufT, g_bufT);
    cudaGetSymbolAddress((void**)&bufT1, g_bufT1);
    cudaGetSymbolAddress((void**)&bufFast, g_bufFast);
    cudaGetSymbolAddress((void**)&pooled, g_pooled);
    cudaGetSymbolAddress((void**)&wbh, g_wb_hi);
    cudaGetSymbolAddress((void**)&wbl, g_wb_lo);
    cudaGetSymbolAddress((void**)&ah, g_actA_hi);
    cudaGetSymbolAddress((void**)&al, g_actA_lo);
    cudaGetSymbolAddress((void**)&bh, g_actB_hi);
    cudaGetSymbolAddress((void**)&bl, g_actB_lo);

    cudaFuncSetAttribute(mma_gemm<0>, cudaFuncAttributeMaxDynamicSharedMemorySize, SMT);
    cudaFuncSetAttribute(mma_gemm<2>, cudaFuncAttributeMaxDynamicSharedMemorySize, SMT);
    cudaFuncSetAttribute(mma_gemm<3>, cudaFuncAttributeMaxDynamicSharedMemorySize, SMT);
    cudaFuncSetAttribute(mma_gemm<4>, cudaFuncAttributeMaxDynamicSharedMemorySize, SMT);
    cudaFuncSetAttribute(attn_mma, cudaFuncAttributeMaxDynamicSharedMemorySize, ATT_SMEM);

    // Launch order arranged so ncu (-s 5 -c 1) captures mma_gemm<4> / attn_mma.
    // 0: split x -> A (serves fused fast+qkv layer 0)
    split_kernel<<<(MROWS*EE/4)/256, 256>>>(x, ah, al, MROWS*EE/4);
    // 1-2: complexity estimator
    pool_kernel<<<(BB * EE) / 256, 256>>>(x, pooled);
    ce_kernel<<<BB, 256>>>(pooled, ce_w1, ce_b1, ce_w2, ce_b2, out);
    // 3-4: weights needed by the first GEMM
    split_kernel<<<(2*3*EE*EE/4)/256, 256>>>(w_in,   wbh + OW_IN,   wbl + OW_IN,   2*3*EE*EE/4);
    split_kernel<<<(EE*EE/4)/256,     256>>>(fast_w, wbh + OW_FAST, wbl + OW_FAST, EE*EE/4);

    const float* tin = x;
    for (int l = 0; l < LL; l++) {
        if (l == 0) {
            // 5: fused qkv+fast
            mma_gemm<4><<<dim3(4*EE/128, MROWS/128), 256, SMT>>>(
                ah, al, wbh + OW_IN, wbl + OW_IN, wbh + OW_FAST, wbl + OW_FAST,
                nullptr, bh, bl, bufFast, 4*EE, EE);
        } else {
            mma_gemm<2><<<dim3(3*EE/128, MROWS/128), 256, SMT>>>(
                ah, al, wbh + OW_IN + (size_t)l*3*EE*EE, wbl + OW_IN + (size_t)l*3*EE*EE,
                nullptr, nullptr, nullptr, bh, bl, nullptr, 3*EE, EE);
        }
        // 6: attention
        attn_mma<<<dim3(SS/128, HH, BB), 256, ATT_SMEM>>>(bh, bl, ah, al);
        if (l == 0) {
            // remaining weight splits (overlap-friendly placement; needed below)
            split_kernel<<<(2*EE*EE/4)/256,   256>>>(w_out,  wbh + OW_OUT, wbl + OW_OUT, 2*EE*EE/4);
            split_kernel<<<(2*4*EE*EE/4)/256, 256>>>(ffn_w1, wbh + OW_F1,  wbl + OW_F1,  2*4*EE*EE/4);
            split_kernel<<<(2*4*EE*EE/4)/256, 256>>>(ffn_w2, wbh + OW_F2,  wbl + OW_F2,  2*4*EE*EE/4);
        }
        mma_gemm<0><<<dim3(EE/128, MROWS/128), 256, SMT>>>(
            ah, al, wbh + OW_OUT + (size_t)l*EE*EE, wbl + OW_OUT + (size_t)l*EE*EE,
            nullptr, nullptr, bufA, nullptr, nullptr, nullptr, EE, EE);
        add_ln_split_kernel<<<MROWS, 256>>>(tin, bufA, ln1_g + l*EE, ln1_b + l*EE,
                                            bufT1, ah, al);
        mma_gemm<3><<<dim3(4*EE/128, MROWS/128), 256, SMT>>>(
            ah, al, wbh + OW_F1 + (size_t)l*4*EE*EE, wbl + OW_F1 + (size_t)l*4*EE*EE,
            nullptr, nullptr, nullptr, bh, bl, nullptr, 4*EE, EE);
        mma_gemm<0><<<dim3(EE/128, MROWS/128), 256, SMT>>>(
            bh, bl, wbh + OW_F2 + (size_t)l*4*EE*EE, wbl + OW_F2 + (size_t)l*4*EE*EE,
            nullptr, nullptr, bufB, nullptr, nullptr, nullptr, EE, 4*EE);
        add_ln_split_kernel<<<MROWS, 256>>>(bufT1, bufB, ln2_g + l*EE, ln2_b + l*EE,
                                            bufT, ah, al);
        tin = bufT;
    }

    finalize_kernel<<<(MROWS * EE / 4) / 256, 256>>>(bufT, bufFast, out);
}

// round 13
// speedup vs baseline: 1.4388x; 1.3002x over previous
#include <cuda_runtime.h>
#include <cuda_fp16.h>
#include <math.h>
#include <stdint.h>

#define BB 8
#define SS 1024
#define EE 1024
#define HH 16
#define DD 64
#define LL 2
#define MROWS (BB*SS)              // 8192
#define OUT_MAIN (BB*SS*EE)        // 8388608
#define OFF_PROBS OUT_MAIN
#define OFF_MODE  (OUT_MAIN + 8)
#define OFF_MEAN  (OUT_MAIN + 16)

// ---------------- scratch (device globals; no allocation allowed) ------------
__device__ float g_bufA[MROWS * EE];     // out-proj fp32
__device__ float g_bufB[MROWS * EE];     // ffn2 out fp32
__device__ float g_bufT[MROWS * EE];     // t (post layer)
__device__ float g_bufT1[MROWS * EE];    // t1 (post LN1)
__device__ float g_bufFast[MROWS * EE];  // fast path
__device__ float g_pooled[BB * EE];

// fp16 buffers: weights hi-only; activations hi/lo split
#define NW_TOTAL 26214400
#define OW_IN   0
#define OW_OUT  6291456
#define OW_F1   8388608
#define OW_F2   16777216
#define OW_FAST 25165824
__device__ __half g_wb_hi[NW_TOTAL];
__device__ __half g_actA_hi[MROWS * 1024];   // narrow activations
__device__ __half g_actA_lo[MROWS * 1024];
__device__ __half g_actB_hi[MROWS * 4096];   // qkv (3072) / ffn hidden (4096)
__device__ __half g_actB_lo[MROWS * 4096];

__device__ __forceinline__ float gelu_exact(float v) {
    return 0.5f * v * (1.0f + erff(v * 0.7071067811865476f));
}
__device__ __forceinline__ uint32_t pack_f16(float a, float b) {
    __half2 t = __floats2half2_rn(a, b);
    return *(uint32_t*)&t;
}

// =================== portable tensor-core primitives (sm_80+ PTX) ============
__device__ __forceinline__ uint32_t smem_u32(const void* p) {
    uint32_t a;
    asm("{ .reg .u64 t; cvta.to.shared.u64 t, %1; cvt.u32.u64 %0, t; }" : "=r"(a) : "l"(p));
    return a;
}
__device__ __forceinline__ void ldm_x4(uint32_t& r0, uint32_t& r1, uint32_t& r2, uint32_t& r3,
                                       uint32_t addr) {
    asm volatile("ldmatrix.sync.aligned.m8n8.x4.shared.b16 {%0,%1,%2,%3}, [%4];"
                 : "=r"(r0), "=r"(r1), "=r"(r2), "=r"(r3) : "r"(addr));
}
__device__ __forceinline__ void ldm_x4_t(uint32_t& r0, uint32_t& r1, uint32_t& r2, uint32_t& r3,
                                         uint32_t addr) {
    asm volatile("ldmatrix.sync.aligned.m8n8.x4.trans.shared.b16 {%0,%1,%2,%3}, [%4];"
                 : "=r"(r0), "=r"(r1), "=r"(r2), "=r"(r3) : "r"(addr));
}
__device__ __forceinline__ void mma_f32(float* c, uint32_t a0, uint32_t a1, uint32_t a2,
                                        uint32_t a3, uint32_t b0, uint32_t b1) {
    asm volatile(
        "mma.sync.aligned.m16n8k16.row.col.f32.f16.f16.f32 "
        "{%0,%1,%2,%3}, {%4,%5,%6,%7}, {%8,%9}, {%0,%1,%2,%3};"
        : "+f"(c[0]), "+f"(c[1]), "+f"(c[2]), "+f"(c[3])
        : "r"(a0), "r"(a1), "r"(a2), "r"(a3), "r"(b0), "r"(b1));
}
__device__ __forceinline__ void cp16(uint32_t saddr, const void* g) {
    asm volatile("cp.async.cg.shared.global [%0], [%1], 16;" :: "r"(saddr), "l"(g));
}
#define CP_COMMIT() asm volatile("cp.async.commit_group;" ::: "memory")
#define CP_WAIT(N)  asm volatile("cp.async.wait_group %0;" :: "n"(N) : "memory")

// =================== mma.sync GEMM: C[M,N] = A[M,K] @ Bh[N,K]^T ==============
// One-sided split: A = Ah + Al (exact), B = Bh (fp16-rounded weights).
// 2 mma per fragment: Ah*Bh + Al*Bh. 128x128 block, 8 warps, K-chunk 32.
// Stage = 3 tiles (Ahi, Alo, Bhi) = 30720 B; 2 stages.
// EPI: 0 fp32, 2 fp16 split, 3 gelu+split,
//      4 fused qkv+fast (cols<3072: split->Chi/Clo stride 3072;
//                        cols>=3072: gelu fp32 -> CF stride 1024, B from BhiF)
#define TIL   10240
#define STAGE (3 * TIL)
#define SMT   (2 * STAGE)          // 61440

__device__ __forceinline__ void copy_tile_async(uint32_t sdst, const __half* __restrict__ g,
                                                int row0, int K, int k0, int tid) {
    #pragma unroll
    for (int i = 0; i < 2; i++) {
        int idx = tid + i * 256;
        int r = idx >> 2, c4 = idx & 3;
        cp16(sdst + r * 80 + c4 * 16, g + (size_t)(row0 + r) * K + k0 + c4 * 8);
    }
}

template<int EPI>
__global__ __launch_bounds__(256, 2) void mma_gemm(
        const __half* __restrict__ Ahi, const __half* __restrict__ Alo,
        const __half* __restrict__ Bhi, const __half* __restrict__ BhiF,
        float* __restrict__ C, __half* __restrict__ Chi,
        __half* __restrict__ Clo, float* __restrict__ CF, int N, int K) {
    extern __shared__ __align__(128) char smem[];
    uint32_t sb = smem_u32(smem);
    int tid = threadIdx.x, lane = tid & 31, warp = tid >> 5;
    int wm = warp & 1, wn = warp >> 1;
    int rowB = blockIdx.y * 128, colB = blockIdx.x * 128;

    const __half* BhU = Bhi;
    int bcol = colB;
    bool isFast = false;
    if (EPI == 4 && colB >= 3 * EE) {
        BhU = BhiF; bcol = colB - 3 * EE; isFast = true;
    }

    int aRow = wm * 64 + (lane & 15);
    int aK   = (lane >> 4) * 8;
    uint32_t aOff = (uint32_t)(aRow * 80 + aK * 2);
    int bRow = wn * 32 + ((lane >> 4) << 3) + (lane & 7);
    int bK   = ((lane >> 3) & 1) * 8;
    uint32_t bOff = (uint32_t)(bRow * 80 + bK * 2);

    float acc[4][4][4];
    #pragma unroll
    for (int i = 0; i < 4; i++)
        #pragma unroll
        for (int j = 0; j < 4; j++)
            #pragma unroll
            for (int k = 0; k < 4; k++) acc[i][j][k] = 0.0f;

    int nch = K >> 5;
    {
        copy_tile_async(sb + 0 * TIL, Ahi, rowB, K, 0, tid);
        copy_tile_async(sb + 1 * TIL, Alo, rowB, K, 0, tid);
        copy_tile_async(sb + 2 * TIL, BhU, bcol, K, 0, tid);
        CP_COMMIT();
    }

    for (int c = 0; c < nch; c++) {
        CP_WAIT(0);
        __syncthreads();   // cp(c) visible; all warps done reading stage (c+1)&1
        if (c + 1 < nch) {
            uint32_t sn = sb + ((c + 1) & 1) * STAGE;
            int k0 = (c + 1) * 32;
            copy_tile_async(sn + 0 * TIL, Ahi, rowB, K, k0, tid);
            copy_tile_async(sn + 1 * TIL, Alo, rowB, K, k0, tid);
            copy_tile_async(sn + 2 * TIL, BhU, bcol, K, k0, tid);
            CP_COMMIT();
        }

        uint32_t ss = sb + (c & 1) * STAGE;
        uint32_t sAh = ss + aOff, sAl = ss + TIL + aOff;
        uint32_t sBh = ss + 2 * TIL + bOff;

        #pragma unroll
        for (int k16 = 0; k16 < 2; k16++) {
            uint32_t kb = k16 * 32;
            uint32_t bh[2][4];
            #pragma unroll
            for (int nh = 0; nh < 2; nh++) {
                uint32_t off = (uint32_t)(nh * 16 * 80) + kb;
                ldm_x4(bh[nh][0], bh[nh][1], bh[nh][2], bh[nh][3], sBh + off);
            }
            #pragma unroll
            for (int mt = 0; mt < 4; mt++) {
                uint32_t off = (uint32_t)(mt * 16 * 80) + kb;
                uint32_t ah0, ah1, ah2, ah3, al0, al1, al2, al3;
                ldm_x4(ah0, ah1, ah2, ah3, sAh + off);
                ldm_x4(al0, al1, al2, al3, sAl + off);
                #pragma unroll
                for (int nt = 0; nt < 4; nt++) {
                    int nh = nt >> 1, o = (nt & 1) * 2;
                    mma_f32(acc[mt][nt], ah0, ah1, ah2, ah3, bh[nh][o], bh[nh][o + 1]);
                    mma_f32(acc[mt][nt], al0, al1, al2, al3, bh[nh][o], bh[nh][o + 1]);
                }
            }
        }
    }

    int r = lane >> 2, c2 = (lane & 3) * 2;
    int row0 = rowB + wm * 64;
    #pragma unroll
    for (int mt = 0; mt < 4; mt++)
        #pragma unroll
        for (int nt = 0; nt < 4; nt++) {
            float v0 = acc[mt][nt][0], v1 = acc[mt][nt][1];
            float v2 = acc[mt][nt][2], v3 = acc[mt][nt][3];
            int row = row0 + mt * 16 + r;
            int colLoc = wn * 32 + nt * 8 + c2;
            if (EPI == 4) {
                if (isFast) {
                    v0 = gelu_exact(v0); v1 = gelu_exact(v1);
                    v2 = gelu_exact(v2); v3 = gelu_exact(v3);
                    int col = bcol + colLoc;
                    float2 p0 = {v0, v1}, p1 = {v2, v3};
                    *(float2*)(CF + (size_t)row * EE + col) = p0;
                    *(float2*)(CF + (size_t)(row + 8) * EE + col) = p1;
                } else {
                    int col = colB + colLoc;
                    __half h0 = __float2half_rn(v0), h1 = __float2half_rn(v1);
                    __half h2 = __float2half_rn(v2), h3 = __float2half_rn(v3);
                    uint32_t hp0 = (uint32_t)__half_as_ushort(h0) |
                                   ((uint32_t)__half_as_ushort(h1) << 16);
                    uint32_t hp1 = (uint32_t)__half_as_ushort(h2) |
                                   ((uint32_t)__half_as_ushort(h3) << 16);
                    *(uint32_t*)(Chi + (size_t)row * (3 * EE) + col) = hp0;
                    *(uint32_t*)(Chi + (size_t)(row + 8) * (3 * EE) + col) = hp1;
                    *(uint32_t*)(Clo + (size_t)row * (3 * EE) + col) =
                        pack_f16(v0 - __half2float(h0), v1 - __half2float(h1));
                    *(uint32_t*)(Clo + (size_t)(row + 8) * (3 * EE) + col) =
                        pack_f16(v2 - __half2float(h2), v3 - __half2float(h3));
                }
            } else {
                if (EPI == 3) {
                    v0 = gelu_exact(v0); v1 = gelu_exact(v1);
                    v2 = gelu_exact(v2); v3 = gelu_exact(v3);
                }
                int col = colB + colLoc;
                if (EPI == 0) {
                    float2 p0 = {v0, v1}, p1 = {v2, v3};
                    *(float2*)(C + (size_t)row * N + col) = p0;
                    *(float2*)(C + (size_t)(row + 8) * N + col) = p1;
                } else {
                    __half h0 = __float2half_rn(v0), h1 = __float2half_rn(v1);
                    __half h2 = __float2half_rn(v2), h3 = __float2half_rn(v3);
                    uint32_t hp0 = (uint32_t)__half_as_ushort(h0) |
                                   ((uint32_t)__half_as_ushort(h1) << 16);
                    uint32_t hp1 = (uint32_t)__half_as_ushort(h2) |
                                   ((uint32_t)__half_as_ushort(h3) << 16);
                    *(uint32_t*)(Chi + (size_t)row * N + col) = hp0;
                    *(uint32_t*)(Chi + (size_t)(row + 8) * N + col) = hp1;
                    *(uint32_t*)(Clo + (size_t)row * N + col) =
                        pack_f16(v0 - __half2float(h0), v1 - __half2float(h1));
                    *(uint32_t*)(Clo + (size_t)(row + 8) * N + col) =
                        pack_f16(v2 - __half2float(h2), v3 - __half2float(h3));
                }
            }
        }
}

// =================== tensor-core flash attention (fp16 split, 3-term) ========
#define ATT_SQH 0
#define ATT_SQL 18432
#define ATT_KV  36864
#define ATT_KSTR 36864
#define KOF_KH 0
#define KOF_KL 9216
#define KOF_VH 18432
#define KOF_VL 27648
#define ATT_SMEM 110592
#define QSTR 3072

__device__ __forceinline__ void attn_prefetch_kv(char* smem, uint32_t stageOff,
        const __half* __restrict__ qh, const __half* __restrict__ ql,
        size_t rowbase, int h, int tid, uint32_t sb) {
    #pragma unroll
    for (int i = 0; i < 2; i++) {
        int idx = tid + i * 256;
        int r = idx >> 3, c8 = idx & 7;
        size_t srow = (rowbase + r) * QSTR + h * 64 + c8 * 8;
        uint32_t d = sb + stageOff + (uint32_t)(r * 144 + c8 * 16);
        cp16(d + KOF_KH, qh + srow + 1024);
        cp16(d + KOF_KL, ql + srow + 1024);
        cp16(d + KOF_VH, qh + srow + 2048);
        cp16(d + KOF_VL, ql + srow + 2048);
    }
}

__global__ __launch_bounds__(256) void attn_mma(
        const __half* __restrict__ qh, const __half* __restrict__ ql,
        __half* __restrict__ oh, __half* __restrict__ ol) {
    extern __shared__ __align__(128) char smem[];
    uint32_t sb = smem_u32(smem);
    int tid = threadIdx.x, lane = tid & 31, warp = tid >> 5;
    int qt = blockIdx.x, h = blockIdx.y, b = blockIdx.z;
    int rb = b * SS;

    #pragma unroll
    for (int i = 0; i < 4; i++) {
        int idx = tid + i * 256;
        int r = idx >> 3, c8 = idx & 7;
        size_t srow = (size_t)(rb + qt * 128 + r) * QSTR + h * 64 + c8 * 8;
        *(uint4*)(smem + ATT_SQH + r * 144 + c8 * 16) = *(const uint4*)(qh + srow);
        *(uint4*)(smem + ATT_SQL + r * 144 + c8 * 16) = *(const uint4*)(ql + srow);
    }
    attn_prefetch_kv(smem, ATT_KV, qh, ql, (size_t)rb, h, tid, sb);
    CP_COMMIT();

    float m0 = -1e30f, m1 = -1e30f, l0 = 0.0f, l1 = 0.0f;
    float accO[8][4];
    #pragma unroll
    for (int i = 0; i < 8; i++)
        #pragma unroll
        for (int j = 0; j < 4; j++) accO[i][j] = 0.0f;

    uint32_t aAddr = sb + ATT_SQH + (uint32_t)((warp * 16 + (lane & 15)) * 144 + (lane >> 4) * 16);
    uint32_t bOff  = (uint32_t)(((lane & 7) + ((lane >> 4) << 3)) * 144 + ((lane >> 3) & 1) * 16);
    uint32_t vOff  = (uint32_t)(((lane & 7) + ((lane >> 3) & 1) * 8) * 144 + ((lane >> 4) & 1) * 16);

    for (int c = 0; c < SS / 64; c++) {
        CP_WAIT(0);
        __syncthreads();
        if (c + 1 < SS / 64) {
            attn_prefetch_kv(smem, ATT_KV + ((c + 1) & 1) * ATT_KSTR,
                             qh, ql, (size_t)(rb + (c + 1) * 64), h, tid, sb);
            CP_COMMIT();
        }
        uint32_t kvB = ATT_KV + (uint32_t)((c & 1) * ATT_KSTR);

        float s[8][4];
        #pragma unroll
        for (int i = 0; i < 8; i++)
            #pragma unroll
            for (int j = 0; j < 4; j++) s[i][j] = 0.0f;

        #pragma unroll
        for (int kc = 0; kc < 4; kc++) {
            uint32_t ah0, ah1, ah2, ah3, al0, al1, al2, al3;
            ldm_x4(ah0, ah1, ah2, ah3, aAddr + kc * 32);
            ldm_x4(al0, al1, al2, al3, aAddr + (ATT_SQL - ATT_SQH) + kc * 32);
            #pragma unroll
            for (int nh = 0; nh < 4; nh++) {
                uint32_t ba = sb + kvB + KOF_KH + (uint32_t)(nh * 16 * 144) + bOff + kc * 32;
                uint32_t bh_[4], bl_[4];
                ldm_x4(bh_[0], bh_[1], bh_[2], bh_[3], ba);
                ldm_x4(bl_[0], bl_[1], bl_[2], bl_[3], ba + (KOF_KL - KOF_KH));
                #pragma unroll
                for (int o = 0; o < 2; o++) {
                    int nt = nh * 2 + o;
                    mma_f32(s[nt], ah0, ah1, ah2, ah3, bh_[o * 2], bh_[o * 2 + 1]);
                    mma_f32(s[nt], ah0, ah1, ah2, ah3, bl_[o * 2], bl_[o * 2 + 1]);
                    mma_f32(s[nt], al0, al1, al2, al3, bh_[o * 2], bh_[o * 2 + 1]);
                }
            }
        }

        float mx0 = -1e30f, mx1 = -1e30f;
        #pragma unroll
        for (int nt = 0; nt < 8; nt++) {
            s[nt][0] *= 0.125f; s[nt][1] *= 0.125f; s[nt][2] *= 0.125f; s[nt][3] *= 0.125f;
            mx0 = fmaxf(mx0, fmaxf(s[nt][0], s[nt][1]));
            mx1 = fmaxf(mx1, fmaxf(s[nt][2], s[nt][3]));
        }
        mx0 = fmaxf(mx0, __shfl_xor_sync(0xffffffffu, mx0, 1));
        mx0 = fmaxf(mx0, __shfl_xor_sync(0xffffffffu, mx0, 2));
        mx1 = fmaxf(mx1, __shfl_xor_sync(0xffffffffu, mx1, 1));
        mx1 = fmaxf(mx1, __shfl_xor_sync(0xffffffffu, mx1, 2));
        float mn0 = fmaxf(m0, mx0), mn1 = fmaxf(m1, mx1);
        float alpha0 = __expf(m0 - mn0), alpha1 = __expf(m1 - mn1);
        m0 = mn0; m1 = mn1;
        float sum0 = 0.0f, sum1 = 0.0f;
        #pragma unroll
        for (int nt = 0; nt < 8; nt++) {
            s[nt][0] = __expf(s[nt][0] - m0);
            s[nt][1] = __expf(s[nt][1] - m0);
            s[nt][2] = __expf(s[nt][2] - m1);
            s[nt][3] = __expf(s[nt][3] - m1);
            sum0 += s[nt][0] + s[nt][1];
            sum1 += s[nt][2] + s[nt][3];
        }
        sum0 += __shfl_xor_sync(0xffffffffu, sum0, 1);
        sum0 += __shfl_xor_sync(0xffffffffu, sum0, 2);
        sum1 += __shfl_xor_sync(0xffffffffu, sum1, 1);
        sum1 += __shfl_xor_sync(0xffffffffu, sum1, 2);
        l0 = l0 * alpha0 + sum0;
        l1 = l1 * alpha1 + sum1;
        #pragma unroll
        for (int dt = 0; dt < 8; dt++) {
            accO[dt][0] *= alpha0; accO[dt][1] *= alpha0;
            accO[dt][2] *= alpha1; accO[dt][3] *= alpha1;
        }

        #pragma unroll
        for (int kc2 = 0; kc2 < 4; kc2++) {
            int n0 = kc2 * 2, n1 = kc2 * 2 + 1;
            __half h00 = __float2half_rn(s[n0][0]), h01 = __float2half_rn(s[n0][1]);
            __half h02 = __float2half_rn(s[n0][2]), h03 = __float2half_rn(s[n0][3]);
            __half h10 = __float2half_rn(s[n1][0]), h11 = __float2half_rn(s[n1][1]);
            __half h12 = __float2half_rn(s[n1][2]), h13 = __float2half_rn(s[n1][3]);
            uint32_t ph0 = (uint32_t)__half_as_ushort(h00) | ((uint32_t)__half_as_ushort(h01) << 16);
            uint32_t ph1 = (uint32_t)__half_as_ushort(h02) | ((uint32_t)__half_as_ushort(h03) << 16);
            uint32_t ph2 = (uint32_t)__half_as_ushort(h10) | ((uint32_t)__half_as_ushort(h11) << 16);
            uint32_t ph3 = (uint32_t)__half_as_ushort(h12) | ((uint32_t)__half_as_ushort(h13) << 16);
            uint32_t pl0 = pack_f16(s[n0][0] - __half2float(h00), s[n0][1] - __half2float(h01));
            uint32_t pl1 = pack_f16(s[n0][2] - __half2float(h02), s[n0][3] - __half2float(h03));
            uint32_t pl2 = pack_f16(s[n1][0] - __half2float(h10), s[n1][1] - __half2float(h11));
            uint32_t pl3 = pack_f16(s[n1][2] - __half2float(h12), s[n1][3] - __half2float(h13));
            #pragma unroll
            for (int nd = 0; nd < 4; nd++) {
                uint32_t va = sb + kvB + KOF_VH + (uint32_t)(kc2 * 16 * 144) + vOff + nd * 32;
                uint32_t vh_[4], vl_[4];
                ldm_x4_t(vh_[0], vh_[1], vh_[2], vh_[3], va);
                ldm_x4_t(vl_[0], vl_[1], vl_[2], vl_[3], va + (KOF_VL - KOF_VH));
                #pragma unroll
                for (int o = 0; o < 2; o++) {
                    int dt = nd * 2 + o;
                    mma_f32(accO[dt], ph0, ph1, ph2, ph3, vh_[o * 2], vh_[o * 2 + 1]);
                    mma_f32(accO[dt], ph0, ph1, ph2, ph3, vl_[o * 2], vl_[o * 2 + 1]);
                    mma_f32(accO[dt], pl0, pl1, pl2, pl3, vh_[o * 2], vh_[o * 2 + 1]);
                }
            }
        }
    }

    float inv0 = 1.0f / l0, inv1 = 1.0f / l1;
    int g = lane >> 2, c2 = (lane & 3) * 2;
    int row = rb + qt * 128 + warp * 16 + g;
    int colb = h * 64 + c2;
    #pragma unroll
    for (int dt = 0; dt < 8; dt++) {
        float v0 = accO[dt][0] * inv0, v1 = accO[dt][1] * inv0;
        float v2 = accO[dt][2] * inv1, v3 = accO[dt][3] * inv1;
        __half h0 = __float2half_rn(v0), h1 = __float2half_rn(v1);
        __half h2 = __float2half_rn(v2), h3 = __float2half_rn(v3);
        uint32_t hp0 = (uint32_t)__half_as_ushort(h0) | ((uint32_t)__half_as_ushort(h1) << 16);
        uint32_t hp1 = (uint32_t)__half_as_ushort(h2) | ((uint32_t)__half_as_ushort(h3) << 16);
        int col = colb + dt * 8;
        *(uint32_t*)(oh + (size_t)row * EE + col) = hp0;
        *(uint32_t*)(oh + (size_t)(row + 8) * EE + col) = hp1;
        *(uint32_t*)(ol + (size_t)row * EE + col) =
            pack_f16(v0 - __half2float(h0), v1 - __half2float(h1));
        *(uint32_t*)(ol + (size_t)(row + 8) * EE + col) =
            pack_f16(v2 - __half2float(h2), v3 - __half2float(h3));
    }
}

// ---------------- fp32 -> fp16 hi/lo split -----------------------------------
__global__ __launch_bounds__(256) void split_kernel(const float* __restrict__ in,
                                                    __half* __restrict__ hi,
                                                    __half* __restrict__ lo,
                                                    int n4) {
    int i = blockIdx.x * 256 + threadIdx.x;
    if (i >= n4) return;
    float4 v = ((const float4*)in)[i];
    float x[4] = {v.x, v.y, v.z, v.w};
    uint32_t hw[4], lw[4];
    #pragma unroll
    for (int k = 0; k < 4; k++) {
        __half h = __float2half_rn(x[k]);
        float rr = x[k] - __half2float(h);
        __half l = __float2half_rn(rr);
        hw[k] = (uint32_t)__half_as_ushort(h);
        lw[k] = (uint32_t)__half_as_ushort(l);
    }
    uint2 ho, loo;
    ho.x  = hw[0] | (hw[1] << 16);  ho.y  = hw[2] | (hw[3] << 16);
    loo.x = lw[0] | (lw[1] << 16);  loo.y = lw[2] | (lw[3] << 16);
    ((uint2*)hi)[i] = ho;
    ((uint2*)lo)[i] = loo;
}

// ---------------- fp32 -> fp16 hi only (weights) -----------------------------
__global__ __launch_bounds__(256) void convert_kernel(const float* __restrict__ in,
                                                      __half* __restrict__ hi,
                                                      int n4) {
    int i = blockIdx.x * 256 + threadIdx.x;
    if (i >= n4) return;
    float4 v = ((const float4*)in)[i];
    uint2 ho; ho.x = pack_f16(v.x, v.y); ho.y = pack_f16(v.z, v.w);
    ((uint2*)hi)[i] = ho;
}

// ---------------- y = LN(a + b) * g + beta (+ fp16 split) --------------------
__global__ __launch_bounds__(256) void add_ln_split_kernel(const float* __restrict__ a,
                                                           const float* __restrict__ bsrc,
                                                           const float* __restrict__ g,
                                                           const float* __restrict__ beta,
                                                           float* __restrict__ y,
                                                           __half* __restrict__ yh,
                                                           __half* __restrict__ yl) {
    int row = blockIdx.x;
    int tid = threadIdx.x;
    const float* ar = a + (size_t)row * EE;
    const float* br = bsrc + (size_t)row * EE;
    float v[4];
    float s = 0.0f, s2 = 0.0f;
    #pragma unroll
    for (int k = 0; k < 4; k++) {
        float t = ar[tid + 256 * k] + br[tid + 256 * k];
        v[k] = t; s += t; s2 += t * t;
    }
    __shared__ float red[18];
    #pragma unroll
    for (int off = 16; off; off >>= 1) {
        s  += __shfl_xor_sync(0xffffffffu, s,  off);
        s2 += __shfl_xor_sync(0xffffffffu, s2, off);
    }
    int wid = tid >> 5, lid = tid & 31;
    if (lid == 0) { red[wid] = s; red[wid + 8] = s2; }
    __syncthreads();
    if (tid < 32) {
        float a1 = (tid < 8) ? red[tid] : 0.0f;
        float a2 = (tid < 8) ? red[tid + 8] : 0.0f;
        #pragma unroll
        for (int off = 4; off; off >>= 1) {
            a1 += __shfl_xor_sync(0xffffffffu, a1, off);
            a2 += __shfl_xor_sync(0xffffffffu, a2, off);
        }
        if (tid == 0) { red[16] = a1; red[17] = a2; }
    }
    __syncthreads();
    float mu = red[16] * (1.0f / EE);
    float var = red[17] * (1.0f / EE) - mu * mu;
    float rs = rsqrtf(var + 1e-5f);
    float* yr = y + (size_t)row * EE;
    __half* yhr = yh + (size_t)row * EE;
    __half* ylr = yl + (size_t)row * EE;
    #pragma unroll
    for (int k = 0; k < 4; k++) {
        int c = tid + 256 * k;
        float val = (v[k] - mu) * rs * g[c] + beta[c];
        yr[c] = val;
        __half h = __float2half_rn(val);
        yhr[c] = h;
        ylr[c] = __float2half_rn(val - __half2float(h));
    }
}

// ---------------- mean-pool over S -------------------------------------------
__global__ __launch_bounds__(256) void pool_kernel(const float* __restrict__ x,
                                                   float* __restrict__ pooled) {
    int idx = blockIdx.x * 256 + threadIdx.x;
    int b = idx >> 10, e = idx & 1023;
    const float* p = x + (size_t)b * SS * EE + e;
    float s = 0.0f;
    for (int sI = 0; sI < SS; sI++) s += p[(size_t)sI * EE];
    pooled[idx] = s * (1.0f / SS);
}

// ---------------- complexity estimator ---------------------------------------
__global__ __launch_bounds__(256) void ce_kernel(const float* __restrict__ pooled,
                                                 const float* __restrict__ w1,
                                                 const float* __restrict__ b1,
                                                 const float* __restrict__ w2,
                                                 const float* __restrict__ b2,
                                                 float* __restrict__ out) {
    int b = blockIdx.x, j = threadIdx.x;
    const float* p = pooled + b * EE;
    const float* w = w1 + (size_t)j * EE;
    float s = b1[j];
    for (int k = 0; k < EE; k++) s = fmaf(p[k], w[k], s);
    float h = fmaxf(s, 0.0f);
    __shared__ float red[256];
    red[j] = h * w2[j];
    __syncthreads();
    for (int off = 128; off; off >>= 1) {
        if (j < off) red[j] += red[j + off];
        __syncthreads();
    }
    if (j == 0) {
        float logit = red[0] + b2[0];
        float prob = 1.0f / (1.0f + expf(-logit));
        out[OFF_PROBS + b] = prob;
        out[OFF_MODE + b] = (prob > 0.5f) ? 1.0f : 0.0f;
    }
}

// ---------------- select + mean(mode) ----------------------------------------
__global__ __launch_bounds__(256) void finalize_kernel(const float* __restrict__ t,
                                                       const float* __restrict__ f,
                                                       float* __restrict__ out) {
    size_t i = (size_t)blockIdx.x * 256 + threadIdx.x;
    int b = (int)((i * 4) >> 20);
    float m = out[OFF_MODE + b];
    float4 r = (m > 0.5f) ? ((const float4*)t)[i] : ((const float4*)f)[i];
    ((float4*)out)[i] = r;
    if (i == 0) {
        float sAcc = 0.0f;
        for (int k = 0; k < 8; k++) sAcc += out[OFF_MODE + k];
        out[OFF_MEAN] = sAcc * 0.125f;
    }
}

// -----------------------------------------------------------------------------
extern "C" void kernel_launch(void* const* d_in, const int* in_sizes, int n_in,
                              void* d_out, int out_size) {
    const float* x      = (const float*)d_in[0];
    const float* w_in   = (const float*)d_in[1];
    const float* w_out  = (const float*)d_in[2];
    const float* ffn_w1 = (const float*)d_in[3];
    const float* ffn_w2 = (const float*)d_in[4];
    const float* ln1_g  = (const float*)d_in[5];
    const float* ln1_b  = (const float*)d_in[6];
    const float* ln2_g  = (const float*)d_in[7];
    const float* ln2_b  = (const float*)d_in[8];
    const float* ce_w1  = (const float*)d_in[9];
    const float* ce_b1  = (const float*)d_in[10];
    const float* ce_w2  = (const float*)d_in[11];
    const float* ce_b2  = (const float*)d_in[12];
    const float* fast_w = (const float*)d_in[13];
    float* out = (float*)d_out;

    float *bufA, *bufB, *bufT, *bufT1, *bufFast, *pooled;
    __half *wbh, *ah, *al, *bh, *bl;
    cudaGetSymbolAddress((void**)&bufA, g_bufA);
    cudaGetSymbolAddress((void**)&bufB, g_bufB);
    cudaGetSymbolAddress((void**)&bufT, g_bufT);
    cudaGetSymbolAddress((void**)&bufT1, g_bufT1);
    cudaGetSymbolAddress((void**)&bufFast, g_bufFast);
    cudaGetSymbolAddress((void**)&pooled, g_pooled);
    cudaGetSymbolAddress((void**)&wbh, g_wb_hi);
    cudaGetSymbolAddress((void**)&ah, g_actA_hi);
    cudaGetSymbolAddress((void**)&al, g_actA_lo);
    cudaGetSymbolAddress((void**)&bh, g_actB_hi);
    cudaGetSymbolAddress((void**)&bl, g_actB_lo);

    cudaFuncSetAttribute(mma_gemm<0>, cudaFuncAttributeMaxDynamicSharedMemorySize, SMT);
    cudaFuncSetAttribute(mma_gemm<2>, cudaFuncAttributeMaxDynamicSharedMemorySize, SMT);
    cudaFuncSetAttribute(mma_gemm<3>, cudaFuncAttributeMaxDynamicSharedMemorySize, SMT);
    cudaFuncSetAttribute(mma_gemm<4>, cudaFuncAttributeMaxDynamicSharedMemorySize, SMT);
    cudaFuncSetAttribute(attn_mma, cudaFuncAttributeMaxDynamicSharedMemorySize, ATT_SMEM);

    // 0: split x -> A (activations need hi/lo)
    split_kernel<<<(MROWS*EE/4)/256, 256>>>(x, ah, al, MROWS*EE/4);
    // complexity estimator
    pool_kernel<<<(BB * EE) / 256, 256>>>(x, pooled);
    ce_kernel<<<BB, 256>>>(pooled, ce_w1, ce_b1, ce_w2, ce_b2, out);
    // weights: hi only
    convert_kernel<<<(2*3*EE*EE/4)/256, 256>>>(w_in,   wbh + OW_IN,   2*3*EE*EE/4);
    convert_kernel<<<(EE*EE/4)/256,     256>>>(fast_w, wbh + OW_FAST, EE*EE/4);

    const float* tin = x;
    for (int l = 0; l < LL; l++) {
        if (l == 0) {
            mma_gemm<4><<<dim3(4*EE/128, MROWS/128), 256, SMT>>>(
                ah, al, wbh + OW_IN, wbh + OW_FAST,
                nullptr, bh, bl, bufFast, 4*EE, EE);
        } else {
            mma_gemm<2><<<dim3(3*EE/128, MROWS/128), 256, SMT>>>(
                ah, al, wbh + OW_IN + (size_t)l*3*EE*EE, nullptr,
                nullptr, bh, bl, nullptr, 3*EE, EE);
        }
        attn_mma<<<dim3(SS/128, HH, BB), 256, ATT_SMEM>>>(bh, bl, ah, al);
        if (l == 0) {
            convert_kernel<<<(2*EE*EE/4)/256,   256>>>(w_out,  wbh + OW_OUT, 2*EE*EE/4);
            convert_kernel<<<(2*4*EE*EE/4)/256, 256>>>(ffn_w1, wbh + OW_F1,  2*4*EE*EE/4);
            convert_kernel<<<(2*4*EE*EE/4)/256, 256>>>(ffn_w2, wbh + OW_F2,  2*4*EE*EE/4);
        }
        mma_gemm<0><<<dim3(EE/128, MROWS/128), 256, SMT>>>(
            ah, al, wbh + OW_OUT + (size_t)l*EE*EE, nullptr,
            bufA, nullptr, nullptr, nullptr, EE, EE);
        add_ln_split_kernel<<<MROWS, 256>>>(tin, bufA, ln1_g + l*EE, ln1_b + l*EE,
                                            bufT1, ah, al);
        mma_gemm<3><<<dim3(4*EE/128, MROWS/128), 256, SMT>>>(
            ah, al, wbh + OW_F1 + (size_t)l*4*EE*EE, nullptr,
            nullptr, bh, bl, nullptr, 4*EE, EE);
        mma_gemm<0><<<dim3(EE/128, MROWS/128), 256, SMT>>>(
            bh, bl, wbh + OW_F2 + (size_t)l*4*EE*EE, nullptr,
            bufB, nullptr, nullptr, nullptr, EE, 4*EE);
        add_ln_split_kernel<<<MROWS, 256>>>(bufT1, bufB, ln2_g + l*EE, ln2_b + l*EE,
                                            bufT, ah, al);
        tin = bufT;
    }

    finalize_kernel<<<(MROWS * EE / 4) / 256, 256>>>(bufT, bufFast, out);
}

// round 14
// speedup vs baseline: 2.1013x; 1.4605x over previous
#include <cuda_runtime.h>
#include <cuda_fp16.h>
#include <math.h>
#include <stdint.h>

#define BB 8
#define SS 1024
#define EE 1024
#define HH 16
#define DD 64
#define LL 2
#define MROWS (BB*SS)              // 8192
#define OUT_MAIN (BB*SS*EE)        // 8388608
#define OFF_PROBS OUT_MAIN
#define OFF_MODE  (OUT_MAIN + 8)
#define OFF_MEAN  (OUT_MAIN + 16)

// ---------------- scratch (device globals; no allocation allowed) ------------
__device__ float g_bufA[MROWS * EE];     // out-proj fp32
__device__ float g_bufB[MROWS * EE];     // ffn2 out fp32
__device__ float g_bufT[MROWS * EE];     // t (post layer)
__device__ float g_bufT1[MROWS * EE];    // t1 (post LN1)
__device__ float g_bufFast[MROWS * EE];  // fast path
__device__ float g_pooled[BB * EE];

// fp16 buffers
#define NW_TOTAL 26214400
#define OW_IN   0
#define OW_OUT  6291456
#define OW_F1   8388608
#define OW_F2   16777216
#define OW_FAST 25165824
__device__ __half g_wb_hi[NW_TOTAL];
__device__ __half g_actA_hi[MROWS * 1024];   // narrow activations (hi)
__device__ __half g_actB_hi[MROWS * 4096];   // qkv (3072) / ffn hidden (4096)
__device__ __half g_actB_lo[MROWS * 4096];   // qkv lo (attention 3-term input)

__device__ __forceinline__ float gelu_exact(float v) {
    return 0.5f * v * (1.0f + erff(v * 0.7071067811865476f));
}
__device__ __forceinline__ uint32_t pack_f16(float a, float b) {
    __half2 t = __floats2half2_rn(a, b);
    return *(uint32_t*)&t;
}

// =================== portable tensor-core primitives (sm_80+ PTX) ============
__device__ __forceinline__ uint32_t smem_u32(const void* p) {
    uint32_t a;
    asm("{ .reg .u64 t; cvta.to.shared.u64 t, %1; cvt.u32.u64 %0, t; }" : "=r"(a) : "l"(p));
    return a;
}
__device__ __forceinline__ void ldm_x4(uint32_t& r0, uint32_t& r1, uint32_t& r2, uint32_t& r3,
                                       uint32_t addr) {
    asm volatile("ldmatrix.sync.aligned.m8n8.x4.shared.b16 {%0,%1,%2,%3}, [%4];"
                 : "=r"(r0), "=r"(r1), "=r"(r2), "=r"(r3) : "r"(addr));
}
__device__ __forceinline__ void ldm_x4_t(uint32_t& r0, uint32_t& r1, uint32_t& r2, uint32_t& r3,
                                         uint32_t addr) {
    asm volatile("ldmatrix.sync.aligned.m8n8.x4.trans.shared.b16 {%0,%1,%2,%3}, [%4];"
                 : "=r"(r0), "=r"(r1), "=r"(r2), "=r"(r3) : "r"(addr));
}
__device__ __forceinline__ void mma_f32(float* c, uint32_t a0, uint32_t a1, uint32_t a2,
                                        uint32_t a3, uint32_t b0, uint32_t b1) {
    asm volatile(
        "mma.sync.aligned.m16n8k16.row.col.f32.f16.f16.f32 "
        "{%0,%1,%2,%3}, {%4,%5,%6,%7}, {%8,%9}, {%0,%1,%2,%3};"
        : "+f"(c[0]), "+f"(c[1]), "+f"(c[2]), "+f"(c[3])
        : "r"(a0), "r"(a1), "r"(a2), "r"(a3), "r"(b0), "r"(b1));
}
__device__ __forceinline__ void cp16(uint32_t saddr, const void* g) {
    asm volatile("cp.async.cg.shared.global [%0], [%1], 16;" :: "r"(saddr), "l"(g));
}
#define CP_COMMIT() asm volatile("cp.async.commit_group;" ::: "memory")
#define CP_WAIT(N)  asm volatile("cp.async.wait_group %0;" :: "n"(N) : "memory")

// =================== mma.sync GEMM: C[M,N] = Ah[M,K] @ Bh[N,K]^T =============
// Pure fp16 inputs, fp32 accumulate: 1 mma per fragment. 128x128 block,
// 8 warps, K-chunk 32. Stage = 2 tiles (Ah, Bh) = 20480 B; 2 stages.
// EPI: 0 fp32, 2 fp16 hi/lo split (qkv; lo needed by 3-term attention),
//      3 gelu + fp16 hi only,
//      4 fused qkv+fast (cols<3072: split->Chi/Clo stride 3072;
//                        cols>=3072: gelu fp32 -> CF stride 1024, B from BhiF)
#define TIL   10240
#define STAGE (2 * TIL)
#define SMT   (2 * STAGE)          // 40960

__device__ __forceinline__ void copy_tile_async(uint32_t sdst, const __half* __restrict__ g,
                                                int row0, int K, int k0, int tid) {
    #pragma unroll
    for (int i = 0; i < 2; i++) {
        int idx = tid + i * 256;
        int r = idx >> 2, c4 = idx & 3;
        cp16(sdst + r * 80 + c4 * 16, g + (size_t)(row0 + r) * K + k0 + c4 * 8);
    }
}

template<int EPI>
__global__ __launch_bounds__(256, 2) void mma_gemm(
        const __half* __restrict__ Ah,
        const __half* __restrict__ Bhi, const __half* __restrict__ BhiF,
        float* __restrict__ C, __half* __restrict__ Chi,
        __half* __restrict__ Clo, float* __restrict__ CF, int N, int K) {
    extern __shared__ __align__(128) char smem[];
    uint32_t sb = smem_u32(smem);
    int tid = threadIdx.x, lane = tid & 31, warp = tid >> 5;
    int wm = warp & 1, wn = warp >> 1;
    int rowB = blockIdx.y * 128, colB = blockIdx.x * 128;

    const __half* BhU = Bhi;
    int bcol = colB;
    bool isFast = false;
    if (EPI == 4 && colB >= 3 * EE) {
        BhU = BhiF; bcol = colB - 3 * EE; isFast = true;
    }

    int aRow = wm * 64 + (lane & 15);
    int aK   = (lane >> 4) * 8;
    uint32_t aOff = (uint32_t)(aRow * 80 + aK * 2);
    int bRow = wn * 32 + ((lane >> 4) << 3) + (lane & 7);
    int bK   = ((lane >> 3) & 1) * 8;
    uint32_t bOff = (uint32_t)(bRow * 80 + bK * 2);

    float acc[4][4][4];
    #pragma unroll
    for (int i = 0; i < 4; i++)
        #pragma unroll
        for (int j = 0; j < 4; j++)
            #pragma unroll
            for (int k = 0; k < 4; k++) acc[i][j][k] = 0.0f;

    int nch = K >> 5;
    {
        copy_tile_async(sb + 0 * TIL, Ah,  rowB, K, 0, tid);
        copy_tile_async(sb + 1 * TIL, BhU, bcol, K, 0, tid);
        CP_COMMIT();
    }

    for (int c = 0; c < nch; c++) {
        CP_WAIT(0);
        __syncthreads();   // cp(c) visible; all warps done reading stage (c+1)&1
        if (c + 1 < nch) {
            uint32_t sn = sb + ((c + 1) & 1) * STAGE;
            int k0 = (c + 1) * 32;
            copy_tile_async(sn + 0 * TIL, Ah,  rowB, K, k0, tid);
            copy_tile_async(sn + 1 * TIL, BhU, bcol, K, k0, tid);
            CP_COMMIT();
        }

        uint32_t ss = sb + (c & 1) * STAGE;
        uint32_t sAh = ss + aOff;
        uint32_t sBh = ss + TIL + bOff;

        #pragma unroll
        for (int k16 = 0; k16 < 2; k16++) {
            uint32_t kb = k16 * 32;
            uint32_t bh[2][4];
            #pragma unroll
            for (int nh = 0; nh < 2; nh++) {
                uint32_t off = (uint32_t)(nh * 16 * 80) + kb;
                ldm_x4(bh[nh][0], bh[nh][1], bh[nh][2], bh[nh][3], sBh + off);
            }
            #pragma unroll
            for (int mt = 0; mt < 4; mt++) {
                uint32_t off = (uint32_t)(mt * 16 * 80) + kb;
                uint32_t ah0, ah1, ah2, ah3;
                ldm_x4(ah0, ah1, ah2, ah3, sAh + off);
                #pragma unroll
                for (int nt = 0; nt < 4; nt++) {
                    int nh = nt >> 1, o = (nt & 1) * 2;
                    mma_f32(acc[mt][nt], ah0, ah1, ah2, ah3, bh[nh][o], bh[nh][o + 1]);
                }
            }
        }
    }

    int r = lane >> 2, c2 = (lane & 3) * 2;
    int row0 = rowB + wm * 64;
    #pragma unroll
    for (int mt = 0; mt < 4; mt++)
        #pragma unroll
        for (int nt = 0; nt < 4; nt++) {
            float v0 = acc[mt][nt][0], v1 = acc[mt][nt][1];
            float v2 = acc[mt][nt][2], v3 = acc[mt][nt][3];
            int row = row0 + mt * 16 + r;
            int colLoc = wn * 32 + nt * 8 + c2;
            if (EPI == 4) {
                if (isFast) {
                    v0 = gelu_exact(v0); v1 = gelu_exact(v1);
                    v2 = gelu_exact(v2); v3 = gelu_exact(v3);
                    int col = bcol + colLoc;
                    float2 p0 = {v0, v1}, p1 = {v2, v3};
                    *(float2*)(CF + (size_t)row * EE + col) = p0;
                    *(float2*)(CF + (size_t)(row + 8) * EE + col) = p1;
                } else {
                    int col = colB + colLoc;
                    __half h0 = __float2half_rn(v0), h1 = __float2half_rn(v1);
                    __half h2 = __float2half_rn(v2), h3 = __float2half_rn(v3);
                    uint32_t hp0 = (uint32_t)__half_as_ushort(h0) |
                                   ((uint32_t)__half_as_ushort(h1) << 16);
                    uint32_t hp1 = (uint32_t)__half_as_ushort(h2) |
                                   ((uint32_t)__half_as_ushort(h3) << 16);
                    *(uint32_t*)(Chi + (size_t)row * (3 * EE) + col) = hp0;
                    *(uint32_t*)(Chi + (size_t)(row + 8) * (3 * EE) + col) = hp1;
                    *(uint32_t*)(Clo + (size_t)row * (3 * EE) + col) =
                        pack_f16(v0 - __half2float(h0), v1 - __half2float(h1));
                    *(uint32_t*)(Clo + (size_t)(row + 8) * (3 * EE) + col) =
                        pack_f16(v2 - __half2float(h2), v3 - __half2float(h3));
                }
            } else if (EPI == 2) {
                int col = colB + colLoc;
                __half h0 = __float2half_rn(v0), h1 = __float2half_rn(v1);
                __half h2 = __float2half_rn(v2), h3 = __float2half_rn(v3);
                uint32_t hp0 = (uint32_t)__half_as_ushort(h0) |
                               ((uint32_t)__half_as_ushort(h1) << 16);
                uint32_t hp1 = (uint32_t)__half_as_ushort(h2) |
                               ((uint32_t)__half_as_ushort(h3) << 16);
                *(uint32_t*)(Chi + (size_t)row * N + col) = hp0;
                *(uint32_t*)(Chi + (size_t)(row + 8) * N + col) = hp1;
                *(uint32_t*)(Clo + (size_t)row * N + col) =
                    pack_f16(v0 - __half2float(h0), v1 - __half2float(h1));
                *(uint32_t*)(Clo + (size_t)(row + 8) * N + col) =
                    pack_f16(v2 - __half2float(h2), v3 - __half2float(h3));
            } else if (EPI == 3) {
                v0 = gelu_exact(v0); v1 = gelu_exact(v1);
                v2 = gelu_exact(v2); v3 = gelu_exact(v3);
                int col = colB + colLoc;
                *(uint32_t*)(Chi + (size_t)row * N + col) = pack_f16(v0, v1);
                *(uint32_t*)(Chi + (size_t)(row + 8) * N + col) = pack_f16(v2, v3);
            } else {
                int col = colB + colLoc;
                float2 p0 = {v0, v1}, p1 = {v2, v3};
                *(float2*)(C + (size_t)row * N + col) = p0;
                *(float2*)(C + (size_t)(row + 8) * N + col) = p1;
            }
        }
}

// =================== tensor-core flash attention (fp16 split, 3-term) ========
#define ATT_SQH 0
#define ATT_SQL 18432
#define ATT_KV  36864
#define ATT_KSTR 36864
#define KOF_KH 0
#define KOF_KL 9216
#define KOF_VH 18432
#define KOF_VL 27648
#define ATT_SMEM 110592
#define QSTR 3072

__device__ __forceinline__ void attn_prefetch_kv(char* smem, uint32_t stageOff,
        const __half* __restrict__ qh, const __half* __restrict__ ql,
        size_t rowbase, int h, int tid, uint32_t sb) {
    #pragma unroll
    for (int i = 0; i < 2; i++) {
        int idx = tid + i * 256;
        int r = idx >> 3, c8 = idx & 7;
        size_t srow = (rowbase + r) * QSTR + h * 64 + c8 * 8;
        uint32_t d = sb + stageOff + (uint32_t)(r * 144 + c8 * 16);
        cp16(d + KOF_KH, qh + srow + 1024);
        cp16(d + KOF_KL, ql + srow + 1024);
        cp16(d + KOF_VH, qh + srow + 2048);
        cp16(d + KOF_VL, ql + srow + 2048);
    }
}

__global__ __launch_bounds__(256) void attn_mma(
        const __half* __restrict__ qh, const __half* __restrict__ ql,
        __half* __restrict__ oh) {
    extern __shared__ __align__(128) char smem[];
    uint32_t sb = smem_u32(smem);
    int tid = threadIdx.x, lane = tid & 31, warp = tid >> 5;
    int qt = blockIdx.x, h = blockIdx.y, b = blockIdx.z;
    int rb = b * SS;

    #pragma unroll
    for (int i = 0; i < 4; i++) {
        int idx = tid + i * 256;
        int r = idx >> 3, c8 = idx & 7;
        size_t srow = (size_t)(rb + qt * 128 + r) * QSTR + h * 64 + c8 * 8;
        *(uint4*)(smem + ATT_SQH + r * 144 + c8 * 16) = *(const uint4*)(qh + srow);
        *(uint4*)(smem + ATT_SQL + r * 144 + c8 * 16) = *(const uint4*)(ql + srow);
    }
    attn_prefetch_kv(smem, ATT_KV, qh, ql, (size_t)rb, h, tid, sb);
    CP_COMMIT();

    float m0 = -1e30f, m1 = -1e30f, l0 = 0.0f, l1 = 0.0f;
    float accO[8][4];
    #pragma unroll
    for (int i = 0; i < 8; i++)
        #pragma unroll
        for (int j = 0; j < 4; j++) accO[i][j] = 0.0f;

    uint32_t aAddr = sb + ATT_SQH + (uint32_t)((warp * 16 + (lane & 15)) * 144 + (lane >> 4) * 16);
    uint32_t bOff  = (uint32_t)(((lane & 7) + ((lane >> 4) << 3)) * 144 + ((lane >> 3) & 1) * 16);
    uint32_t vOff  = (uint32_t)(((lane & 7) + ((lane >> 3) & 1) * 8) * 144 + ((lane >> 4) & 1) * 16);

    for (int c = 0; c < SS / 64; c++) {
        CP_WAIT(0);
        __syncthreads();
        if (c + 1 < SS / 64) {
            attn_prefetch_kv(smem, ATT_KV + ((c + 1) & 1) * ATT_KSTR,
                             qh, ql, (size_t)(rb + (c + 1) * 64), h, tid, sb);
            CP_COMMIT();
        }
        uint32_t kvB = ATT_KV + (uint32_t)((c & 1) * ATT_KSTR);

        float s[8][4];
        #pragma unroll
        for (int i = 0; i < 8; i++)
            #pragma unroll
            for (int j = 0; j < 4; j++) s[i][j] = 0.0f;

        #pragma unroll
        for (int kc = 0; kc < 4; kc++) {
            uint32_t ah0, ah1, ah2, ah3, al0, al1, al2, al3;
            ldm_x4(ah0, ah1, ah2, ah3, aAddr + kc * 32);
            ldm_x4(al0, al1, al2, al3, aAddr + (ATT_SQL - ATT_SQH) + kc * 32);
            #pragma unroll
            for (int nh = 0; nh < 4; nh++) {
                uint32_t ba = sb + kvB + KOF_KH + (uint32_t)(nh * 16 * 144) + bOff + kc * 32;
                uint32_t bh_[4], bl_[4];
                ldm_x4(bh_[0], bh_[1], bh_[2], bh_[3], ba);
                ldm_x4(bl_[0], bl_[1], bl_[2], bl_[3], ba + (KOF_KL - KOF_KH));
                #pragma unroll
                for (int o = 0; o < 2; o++) {
                    int nt = nh * 2 + o;
                    mma_f32(s[nt], ah0, ah1, ah2, ah3, bh_[o * 2], bh_[o * 2 + 1]);
                    mma_f32(s[nt], ah0, ah1, ah2, ah3, bl_[o * 2], bl_[o * 2 + 1]);
                    mma_f32(s[nt], al0, al1, al2, al3, bh_[o * 2], bh_[o * 2 + 1]);
                }
            }
        }

        float mx0 = -1e30f, mx1 = -1e30f;
        #pragma unroll
        for (int nt = 0; nt < 8; nt++) {
            s[nt][0] *= 0.125f; s[nt][1] *= 0.125f; s[nt][2] *= 0.125f; s[nt][3] *= 0.125f;
            mx0 = fmaxf(mx0, fmaxf(s[nt][0], s[nt][1]));
            mx1 = fmaxf(mx1, fmaxf(s[nt][2], s[nt][3]));
        }
        mx0 = fmaxf(mx0, __shfl_xor_sync(0xffffffffu, mx0, 1));
        mx0 = fmaxf(mx0, __shfl_xor_sync(0xffffffffu, mx0, 2));
        mx1 = fmaxf(mx1, __shfl_xor_sync(0xffffffffu, mx1, 1));
        mx1 = fmaxf(mx1, __shfl_xor_sync(0xffffffffu, mx1, 2));
        float mn0 = fmaxf(m0, mx0), mn1 = fmaxf(m1, mx1);
        float alpha0 = __expf(m0 - mn0), alpha1 = __expf(m1 - mn1);
        m0 = mn0; m1 = mn1;
        float sum0 = 0.0f, sum1 = 0.0f;
        #pragma unroll
        for (int nt = 0; nt < 8; nt++) {
            s[nt][0] = __expf(s[nt][0] - m0);
            s[nt][1] = __expf(s[nt][1] - m0);
            s[nt][2] = __expf(s[nt][2] - m1);
            s[nt][3] = __expf(s[nt][3] - m1);
            sum0 += s[nt][0] + s[nt][1];
            sum1 += s[nt][2] + s[nt][3];
        }
        sum0 += __shfl_xor_sync(0xffffffffu, sum0, 1);
        sum0 += __shfl_xor_sync(0xffffffffu, sum0, 2);
        sum1 += __shfl_xor_sync(0xffffffffu, sum1, 1);
        sum1 += __shfl_xor_sync(0xffffffffu, sum1, 2);
        l0 = l0 * alpha0 + sum0;
        l1 = l1 * alpha1 + sum1;
        #pragma unroll
        for (int dt = 0; dt < 8; dt++) {
            accO[dt][0] *= alpha0; accO[dt][1] *= alpha0;
            accO[dt][2] *= alpha1; accO[dt][3] *= alpha1;
        }

        #pragma unroll
        for (int kc2 = 0; kc2 < 4; kc2++) {
            int n0 = kc2 * 2, n1 = kc2 * 2 + 1;
            __half h00 = __float2half_rn(s[n0][0]), h01 = __float2half_rn(s[n0][1]);
            __half h02 = __float2half_rn(s[n0][2]), h03 = __float2half_rn(s[n0][3]);
            __half h10 = __float2half_rn(s[n1][0]), h11 = __float2half_rn(s[n1][1]);
            __half h12 = __float2half_rn(s[n1][2]), h13 = __float2half_rn(s[n1][3]);
            uint32_t ph0 = (uint32_t)__half_as_ushort(h00) | ((uint32_t)__half_as_ushort(h01) << 16);
            uint32_t ph1 = (uint32_t)__half_as_ushort(h02) | ((uint32_t)__half_as_ushort(h03) << 16);
            uint32_t ph2 = (uint32_t)__half_as_ushort(h10) | ((uint32_t)__half_as_ushort(h11) << 16);
            uint32_t ph3 = (uint32_t)__half_as_ushort(h12) | ((uint32_t)__half_as_ushort(h13) << 16);
            uint32_t pl0 = pack_f16(s[n0][0] - __half2float(h00), s[n0][1] - __half2float(h01));
            uint32_t pl1 = pack_f16(s[n0][2] - __half2float(h02), s[n0][3] - __half2float(h03));
            uint32_t pl2 = pack_f16(s[n1][0] - __half2float(h10), s[n1][1] - __half2float(h11));
            uint32_t pl3 = pack_f16(s[n1][2] - __half2float(h12), s[n1][3] - __half2float(h13));
            #pragma unroll
            for (int nd = 0; nd < 4; nd++) {
                uint32_t va = sb + kvB + KOF_VH + (uint32_t)(kc2 * 16 * 144) + vOff + nd * 32;
                uint32_t vh_[4], vl_[4];
                ldm_x4_t(vh_[0], vh_[1], vh_[2], vh_[3], va);
                ldm_x4_t(vl_[0], vl_[1], vl_[2], vl_[3], va + (KOF_VL - KOF_VH));
                #pragma unroll
                for (int o = 0; o < 2; o++) {
                    int dt = nd * 2 + o;
                    mma_f32(accO[dt], ph0, ph1, ph2, ph3, vh_[o * 2], vh_[o * 2 + 1]);
                    mma_f32(accO[dt], ph0, ph1, ph2, ph3, vl_[o * 2], vl_[o * 2 + 1]);
                    mma_f32(accO[dt], pl0, pl1, pl2, pl3, vh_[o * 2], vh_[o * 2 + 1]);
                }
            }
        }
    }

    float inv0 = 1.0f / l0, inv1 = 1.0f / l1;
    int g = lane >> 2, c2 = (lane & 3) * 2;
    int row = rb + qt * 128 + warp * 16 + g;
    int colb = h * 64 + c2;
    #pragma unroll
    for (int dt = 0; dt < 8; dt++) {
        float v0 = accO[dt][0] * inv0, v1 = accO[dt][1] * inv0;
        float v2 = accO[dt][2] * inv1, v3 = accO[dt][3] * inv1;
        int col = colb + dt * 8;
        *(uint32_t*)(oh + (size_t)row * EE + col) = pack_f16(v0, v1);
        *(uint32_t*)(oh + (size_t)(row + 8) * EE + col) = pack_f16(v2, v3);
    }
}

// ---------------- fp32 -> fp16 (hi only) -------------------------------------
__global__ __launch_bounds__(256) void convert_kernel(const float* __restrict__ in,
                                                      __half* __restrict__ hi,
                                                      int n4) {
    int i = blockIdx.x * 256 + threadIdx.x;
    if (i >= n4) return;
    float4 v = ((const float4*)in)[i];
    uint2 ho; ho.x = pack_f16(v.x, v.y); ho.y = pack_f16(v.z, v.w);
    ((uint2*)hi)[i] = ho;
}

// ---------------- y = LN(a + b) * g + beta (+ fp16 hi) -----------------------
__global__ __launch_bounds__(256) void add_ln_split_kernel(const float* __restrict__ a,
                                                           const float* __restrict__ bsrc,
                                                           const float* __restrict__ g,
                                                           const float* __restrict__ beta,
                                                           float* __restrict__ y,
                                                           __half* __restrict__ yh) {
    int row = blockIdx.x;
    int tid = threadIdx.x;
    const float* ar = a + (size_t)row * EE;
    const float* br = bsrc + (size_t)row * EE;
    float v[4];
    float s = 0.0f, s2 = 0.0f;
    #pragma unroll
    for (int k = 0; k < 4; k++) {
        float t = ar[tid + 256 * k] + br[tid + 256 * k];
        v[k] = t; s += t; s2 += t * t;
    }
    __shared__ float red[18];
    #pragma unroll
    for (int off = 16; off; off >>= 1) {
        s  += __shfl_xor_sync(0xffffffffu, s,  off);
        s2 += __shfl_xor_sync(0xffffffffu, s2, off);
    }
    int wid = tid >> 5, lid = tid & 31;
    if (lid == 0) { red[wid] = s; red[wid + 8] = s2; }
    __syncthreads();
    if (tid < 32) {
        float a1 = (tid < 8) ? red[tid] : 0.0f;
        float a2 = (tid < 8) ? red[tid + 8] : 0.0f;
        #pragma unroll
        for (int off = 4; off; off >>= 1) {
            a1 += __shfl_xor_sync(0xffffffffu, a1, off);
            a2 += __shfl_xor_sync(0xffffffffu, a2, off);
        }
        if (tid == 0) { red[16] = a1; red[17] = a2; }
    }
    __syncthreads();
    float mu = red[16] * (1.0f / EE);
    float var = red[17] * (1.0f / EE) - mu * mu;
    float rs = rsqrtf(var + 1e-5f);
    float* yr = y + (size_t)row * EE;
    __half* yhr = yh + (size_t)row * EE;
    #pragma unroll
    for (int k = 0; k < 4; k++) {
        int c = tid + 256 * k;
        float val = (v[k] - mu) * rs * g[c] + beta[c];
        yr[c] = val;
        yhr[c] = __float2half_rn(val);
    }
}

// ---------------- mean-pool over S -------------------------------------------
__global__ __launch_bounds__(256) void pool_kernel(const float* __restrict__ x,
                                                   float* __restrict__ pooled) {
    int idx = blockIdx.x * 256 + threadIdx.x;
    int b = idx >> 10, e = idx & 1023;
    const float* p = x + (size_t)b * SS * EE + e;
    float s = 0.0f;
    for (int sI = 0; sI < SS; sI++) s += p[(size_t)sI * EE];
    pooled[idx] = s * (1.0f / SS);
}

// ---------------- complexity estimator ---------------------------------------
__global__ __launch_bounds__(256) void ce_kernel(const float* __restrict__ pooled,
                                                 const float* __restrict__ w1,
                                                 const float* __restrict__ b1,
                                                 const float* __restrict__ w2,
                                                 const float* __restrict__ b2,
                                                 float* __restrict__ out) {
    int b = blockIdx.x, j = threadIdx.x;
    const float* p = pooled + b * EE;
    const float* w = w1 + (size_t)j * EE;
    float s = b1[j];
    for (int k = 0; k < EE; k++) s = fmaf(p[k], w[k], s);
    float h = fmaxf(s, 0.0f);
    __shared__ float red[256];
    red[j] = h * w2[j];
    __syncthreads();
    for (int off = 128; off; off >>= 1) {
        if (j < off) red[j] += red[j + off];
        __syncthreads();
    }
    if (j == 0) {
        float logit = red[0] + b2[0];
        float prob = 1.0f / (1.0f + expf(-logit));
        out[OFF_PROBS + b] = prob;
        out[OFF_MODE + b] = (prob > 0.5f) ? 1.0f : 0.0f;
    }
}

// ---------------- select + mean(mode) ----------------------------------------
__global__ __launch_bounds__(256) void finalize_kernel(const float* __restrict__ t,
                                                       const float* __restrict__ f,
                                                       float* __restrict__ out) {
    size_t i = (size_t)blockIdx.x * 256 + threadIdx.x;
    int b = (int)((i * 4) >> 20);
    float m = out[OFF_MODE + b];
    float4 r = (m > 0.5f) ? ((const float4*)t)[i] : ((const float4*)f)[i];
    ((float4*)out)[i] = r;
    if (i == 0) {
        float sAcc = 0.0f;
        for (int k = 0; k < 8; k++) sAcc += out[OFF_MODE + k];
        out[OFF_MEAN] = sAcc * 0.125f;
    }
}

// -----------------------------------------------------------------------------
extern "C" void kernel_launch(void* const* d_in, const int* in_sizes, int n_in,
                              void* d_out, int out_size) {
    const float* x      = (const float*)d_in[0];
    const float* w_in   = (const float*)d_in[1];
    const float* w_out  = (const float*)d_in[2];
    const float* ffn_w1 = (const float*)d_in[3];
    const float* ffn_w2 = (const float*)d_in[4];
    const float* ln1_g  = (const float*)d_in[5];
    const float* ln1_b  = (const float*)d_in[6];
    const float* ln2_g  = (const float*)d_in[7];
    const float* ln2_b  = (const float*)d_in[8];
    const float* ce_w1  = (const float*)d_in[9];
    const float* ce_b1  = (const float*)d_in[10];
    const float* ce_w2  = (const float*)d_in[11];
    const float* ce_b2  = (const float*)d_in[12];
    const float* fast_w = (const float*)d_in[13];
    float* out = (float*)d_out;

    float *bufA, *bufB, *bufT, *bufT1, *bufFast, *pooled;
    __half *wbh, *ah, *bh, *bl;
    cudaGetSymbolAddress((void**)&bufA, g_bufA);
    cudaGetSymbolAddress((void**)&bufB, g_bufB);
    cudaGetSymbolAddress((void**)&bufT, g_bufT);
    cudaGetSymbolAddress((void**)&bufT1, g_bufT1);
    cudaGetSymbolAddress((void**)&bufFast, g_bufFast);
    cudaGetSymbolAddress((void**)&pooled, g_pooled);
    cudaGetSymbolAddress((void**)&wbh, g_wb_hi);
    cudaGetSymbolAddress((void**)&ah, g_actA_hi);
    cudaGetSymbolAddress((void**)&bh, g_actB_hi);
    cudaGetSymbolAddress((void**)&bl, g_actB_lo);

    cudaFuncSetAttribute(mma_gemm<0>, cudaFuncAttributeMaxDynamicSharedMemorySize, SMT);
    cudaFuncSetAttribute(mma_gemm<2>, cudaFuncAttributeMaxDynamicSharedMemorySize, SMT);
    cudaFuncSetAttribute(mma_gemm<3>, cudaFuncAttributeMaxDynamicSharedMemorySize, SMT);
    cudaFuncSetAttribute(mma_gemm<4>, cudaFuncAttributeMaxDynamicSharedMemorySize, SMT);
    cudaFuncSetAttribute(attn_mma, cudaFuncAttributeMaxDynamicSharedMemorySize, ATT_SMEM);

    // convert x -> ah (hi only; x itself remains the fp32 residual)
    convert_kernel<<<(MROWS*EE/4)/256, 256>>>(x, ah, MROWS*EE/4);
    // complexity estimator
    pool_kernel<<<(BB * EE) / 256, 256>>>(x, pooled);
    ce_kernel<<<BB, 256>>>(pooled, ce_w1, ce_b1, ce_w2, ce_b2, out);
    // weights: fp16
    convert_kernel<<<(2*3*EE*EE/4)/256, 256>>>(w_in,   wbh + OW_IN,   2*3*EE*EE/4);
    convert_kernel<<<(EE*EE/4)/256,     256>>>(fast_w, wbh + OW_FAST, EE*EE/4);

    const float* tin = x;
    for (int l = 0; l < LL; l++) {
        if (l == 0) {
            mma_gemm<4><<<dim3(4*EE/128, MROWS/128), 256, SMT>>>(
                ah, wbh + OW_IN, wbh + OW_FAST,
                nullptr, bh, bl, bufFast, 4*EE, EE);
        } else {
            mma_gemm<2><<<dim3(3*EE/128, MROWS/128), 256, SMT>>>(
                ah, wbh + OW_IN + (size_t)l*3*EE*EE, nullptr,
                nullptr, bh, bl, nullptr, 3*EE, EE);
        }
        attn_mma<<<dim3(SS/128, HH, BB), 256, ATT_SMEM>>>(bh, bl, ah);
        if (l == 0) {
            convert_kernel<<<(2*EE*EE/4)/256,   256>>>(w_out,  wbh + OW_OUT, 2*EE*EE/4);
            convert_kernel<<<(2*4*EE*EE/4)/256, 256>>>(ffn_w1, wbh + OW_F1,  2*4*EE*EE/4);
            convert_kernel<<<(2*4*EE*EE/4)/256, 256>>>(ffn_w2, wbh + OW_F2,  2*4*EE*EE/4);
        }
        mma_gemm<0><<<dim3(EE/128, MROWS/128), 256, SMT>>>(
            ah, wbh + OW_OUT + (size_t)l*EE*EE, nullptr,
            bufA, nullptr, nullptr, nullptr, EE, EE);
        add_ln_split_kernel<<<MROWS, 256>>>(tin, bufA, ln1_g + l*EE, ln1_b + l*EE,
                                            bufT1, ah);
        mma_gemm<3><<<dim3(4*EE/128, MROWS/128), 256, SMT>>>(
            ah, wbh + OW_F1 + (size_t)l*4*EE*EE, nullptr,
            nullptr, bh, nullptr, nullptr, 4*EE, EE);
        mma_gemm<0><<<dim3(EE/128, MROWS/128), 256, SMT>>>(
            bh, wbh + OW_F2 + (size_t)l*4*EE*EE, nullptr,
            bufB, nullptr, nullptr, nullptr, EE, 4*EE);
        add_ln_split_kernel<<<MROWS, 256>>>(bufT1, bufB, ln2_g + l*EE, ln2_b + l*EE,
                                            bufT, ah);
        tin = bufT;
    }

    finalize_kernel<<<(MROWS * EE / 4) / 256, 256>>>(bufT, bufFast, out);
}

// round 16
// speedup vs baseline: 2.4390x; 1.1607x over previous
#include <cuda_runtime.h>
#include <cuda_fp16.h>
#include <math.h>
#include <stdint.h>

#define BB 8
#define SS 1024
#define EE 1024
#define HH 16
#define DD 64
#define LL 2
#define MROWS (BB*SS)              // 8192
#define OUT_MAIN (BB*SS*EE)        // 8388608
#define OFF_PROBS OUT_MAIN
#define OFF_MODE  (OUT_MAIN + 8)
#define OFF_MEAN  (OUT_MAIN + 16)

// ---------------- scratch (device globals; no allocation allowed) ------------
__device__ float g_bufA[MROWS * EE];     // out-proj fp32
__device__ float g_bufB[MROWS * EE];     // ffn2 out fp32
__device__ float g_bufT[MROWS * EE];     // t (post layer)
__device__ float g_bufT1[MROWS * EE];    // t1 (post LN1)
__device__ float g_bufFast[MROWS * EE];  // fast path
__device__ float g_pooled[BB * EE];

// fp16 buffers
#define NW_TOTAL 26214400
#define OW_IN   0
#define OW_OUT  6291456
#define OW_F1   8388608
#define OW_F2   16777216
#define OW_FAST 25165824
__device__ __half g_wb_hi[NW_TOTAL];
__device__ __half g_actA_hi[MROWS * 1024];   // narrow activations (hi)
__device__ __half g_actB_hi[MROWS * 4096];   // qkv (3072) / ffn hidden (4096)

__device__ __forceinline__ float gelu_exact(float v) {
    return 0.5f * v * (1.0f + erff(v * 0.7071067811865476f));
}
__device__ __forceinline__ uint32_t pack_f16(float a, float b) {
    __half2 t = __floats2half2_rn(a, b);
    return *(uint32_t*)&t;
}

// =================== portable tensor-core primitives (sm_80+ PTX) ============
__device__ __forceinline__ uint32_t smem_u32(const void* p) {
    uint32_t a;
    asm("{ .reg .u64 t; cvta.to.shared.u64 t, %1; cvt.u32.u64 %0, t; }" : "=r"(a) : "l"(p));
    return a;
}
__device__ __forceinline__ void ldm_x4(uint32_t& r0, uint32_t& r1, uint32_t& r2, uint32_t& r3,
                                       uint32_t addr) {
    asm volatile("ldmatrix.sync.aligned.m8n8.x4.shared.b16 {%0,%1,%2,%3}, [%4];"
                 : "=r"(r0), "=r"(r1), "=r"(r2), "=r"(r3) : "r"(addr));
}
__device__ __forceinline__ void ldm_x4_t(uint32_t& r0, uint32_t& r1, uint32_t& r2, uint32_t& r3,
                                         uint32_t addr) {
    asm volatile("ldmatrix.sync.aligned.m8n8.x4.trans.shared.b16 {%0,%1,%2,%3}, [%4];"
                 : "=r"(r0), "=r"(r1), "=r"(r2), "=r"(r3) : "r"(addr));
}
__device__ __forceinline__ void mma_f32(float* c, uint32_t a0, uint32_t a1, uint32_t a2,
                                        uint32_t a3, uint32_t b0, uint32_t b1) {
    asm volatile(
        "mma.sync.aligned.m16n8k16.row.col.f32.f16.f16.f32 "
        "{%0,%1,%2,%3}, {%4,%5,%6,%7}, {%8,%9}, {%0,%1,%2,%3};"
        : "+f"(c[0]), "+f"(c[1]), "+f"(c[2]), "+f"(c[3])
        : "r"(a0), "r"(a1), "r"(a2), "r"(a3), "r"(b0), "r"(b1));
}
__device__ __forceinline__ void cp16(uint32_t saddr, const void* g) {
    asm volatile("cp.async.cg.shared.global [%0], [%1], 16;" :: "r"(saddr), "l"(g));
}
#define CP_COMMIT() asm volatile("cp.async.commit_group;" ::: "memory")
#define CP_WAIT(N)  asm volatile("cp.async.wait_group %0;" :: "n"(N) : "memory")

// =================== mma.sync GEMM: C[M,N] = Ah[M,K] @ Bh[N,K]^T =============
// Pure fp16 inputs, fp32 accumulate: 1 mma per fragment. 128x128 block,
// 8 warps, K-chunk 32. Stage = 2 tiles (Ah, Bh) = 20480 B; 2 stages.
// EPI: 0 fp32, 2 fp16, 3 gelu+fp16,
//      4 fused qkv+fast (cols<3072: fp16 -> Chi stride 3072;
//                        cols>=3072: gelu fp32 -> CF stride 1024, B from BhiF)
#define TIL   10240
#define STAGE (2 * TIL)
#define SMT   (2 * STAGE)          // 40960

__device__ __forceinline__ void copy_tile_async(uint32_t sdst, const __half* __restrict__ g,
                                                int row0, int K, int k0, int tid) {
    #pragma unroll
    for (int i = 0; i < 2; i++) {
        int idx = tid + i * 256;
        int r = idx >> 2, c4 = idx & 3;
        cp16(sdst + r * 80 + c4 * 16, g + (size_t)(row0 + r) * K + k0 + c4 * 8);
    }
}

template<int EPI>
__global__ __launch_bounds__(256, 2) void mma_gemm(
        const __half* __restrict__ Ah,
        const __half* __restrict__ Bhi, const __half* __restrict__ BhiF,
        float* __restrict__ C, __half* __restrict__ Chi,
        float* __restrict__ CF, int N, int K) {
    extern __shared__ __align__(128) char smem[];
    uint32_t sb = smem_u32(smem);
    int tid = threadIdx.x, lane = tid & 31, warp = tid >> 5;
    int wm = warp & 1, wn = warp >> 1;
    int rowB = blockIdx.y * 128, colB = blockIdx.x * 128;

    const __half* BhU = Bhi;
    int bcol = colB;
    bool isFast = false;
    if (EPI == 4 && colB >= 3 * EE) {
        BhU = BhiF; bcol = colB - 3 * EE; isFast = true;
    }

    int aRow = wm * 64 + (lane & 15);
    int aK   = (lane >> 4) * 8;
    uint32_t aOff = (uint32_t)(aRow * 80 + aK * 2);
    int bRow = wn * 32 + ((lane >> 4) << 3) + (lane & 7);
    int bK   = ((lane >> 3) & 1) * 8;
    uint32_t bOff = (uint32_t)(bRow * 80 + bK * 2);

    float acc[4][4][4];
    #pragma unroll
    for (int i = 0; i < 4; i++)
        #pragma unroll
        for (int j = 0; j < 4; j++)
            #pragma unroll
            for (int k = 0; k < 4; k++) acc[i][j][k] = 0.0f;

    int nch = K >> 5;
    {
        copy_tile_async(sb + 0 * TIL, Ah,  rowB, K, 0, tid);
        copy_tile_async(sb + 1 * TIL, BhU, bcol, K, 0, tid);
        CP_COMMIT();
    }

    for (int c = 0; c < nch; c++) {
        CP_WAIT(0);
        __syncthreads();
        if (c + 1 < nch) {
            uint32_t sn = sb + ((c + 1) & 1) * STAGE;
            int k0 = (c + 1) * 32;
            copy_tile_async(sn + 0 * TIL, Ah,  rowB, K, k0, tid);
            copy_tile_async(sn + 1 * TIL, BhU, bcol, K, k0, tid);
            CP_COMMIT();
        }

        uint32_t ss = sb + (c & 1) * STAGE;
        uint32_t sAh = ss + aOff;
        uint32_t sBh = ss + TIL + bOff;

        #pragma unroll
        for (int k16 = 0; k16 < 2; k16++) {
            uint32_t kb = k16 * 32;
            uint32_t bh[2][4];
            #pragma unroll
            for (int nh = 0; nh < 2; nh++) {
                uint32_t off = (uint32_t)(nh * 16 * 80) + kb;
                ldm_x4(bh[nh][0], bh[nh][1], bh[nh][2], bh[nh][3], sBh + off);
            }
            #pragma unroll
            for (int mt = 0; mt < 4; mt++) {
                uint32_t off = (uint32_t)(mt * 16 * 80) + kb;
                uint32_t ah0, ah1, ah2, ah3;
                ldm_x4(ah0, ah1, ah2, ah3, sAh + off);
                #pragma unroll
                for (int nt = 0; nt < 4; nt++) {
                    int nh = nt >> 1, o = (nt & 1) * 2;
                    mma_f32(acc[mt][nt], ah0, ah1, ah2, ah3, bh[nh][o], bh[nh][o + 1]);
                }
            }
        }
    }

    int r = lane >> 2, c2 = (lane & 3) * 2;
    int row0 = rowB + wm * 64;
    #pragma unroll
    for (int mt = 0; mt < 4; mt++)
        #pragma unroll
        for (int nt = 0; nt < 4; nt++) {
            float v0 = acc[mt][nt][0], v1 = acc[mt][nt][1];
            float v2 = acc[mt][nt][2], v3 = acc[mt][nt][3];
            int row = row0 + mt * 16 + r;
            int colLoc = wn * 32 + nt * 8 + c2;
            if (EPI == 4) {
                if (isFast) {
                    v0 = gelu_exact(v0); v1 = gelu_exact(v1);
                    v2 = gelu_exact(v2); v3 = gelu_exact(v3);
                    int col = bcol + colLoc;
                    float2 p0 = {v0, v1}, p1 = {v2, v3};
                    *(float2*)(CF + (size_t)row * EE + col) = p0;
                    *(float2*)(CF + (size_t)(row + 8) * EE + col) = p1;
                } else {
                    int col = colB + colLoc;
                    *(uint32_t*)(Chi + (size_t)row * (3 * EE) + col) = pack_f16(v0, v1);
                    *(uint32_t*)(Chi + (size_t)(row + 8) * (3 * EE) + col) = pack_f16(v2, v3);
                }
            } else if (EPI == 2) {
                int col = colB + colLoc;
                *(uint32_t*)(Chi + (size_t)row * N + col) = pack_f16(v0, v1);
                *(uint32_t*)(Chi + (size_t)(row + 8) * N + col) = pack_f16(v2, v3);
            } else if (EPI == 3) {
                v0 = gelu_exact(v0); v1 = gelu_exact(v1);
                v2 = gelu_exact(v2); v3 = gelu_exact(v3);
                int col = colB + colLoc;
                *(uint32_t*)(Chi + (size_t)row * N + col) = pack_f16(v0, v1);
                *(uint32_t*)(Chi + (size_t)(row + 8) * N + col) = pack_f16(v2, v3);
            } else {
                int col = colB + colLoc;
                float2 p0 = {v0, v1}, p1 = {v2, v3};
                *(float2*)(C + (size_t)row * N + col) = p0;
                *(float2*)(C + (size_t)(row + 8) * N + col) = p1;
            }
        }
}

// =================== tensor-core flash attention (pure fp16) =================
// Q resident; KV double-buffered via cp.async. 1 mma per fragment.
#define ATT_SQ  0              // 128 x 144B = 18432
#define ATT_KV  18432          // stage base; stride 18432 (K 9216 + V 9216)
#define ATT_KSTR 18432
#define KOF_K 0
#define KOF_V 9216
#define ATT_SMEM 55296
#define QSTR 3072

__device__ __forceinline__ void attn_prefetch_kv(uint32_t stageOff,
        const __half* __restrict__ qh, size_t rowbase, int h, int tid, uint32_t sb) {
    #pragma unroll
    for (int i = 0; i < 2; i++) {
        int idx = tid + i * 256;
        int r = idx >> 3, c8 = idx & 7;
        size_t srow = (rowbase + r) * QSTR + h * 64 + c8 * 8;
        uint32_t d = sb + stageOff + (uint32_t)(r * 144 + c8 * 16);
        cp16(d + KOF_K, qh + srow + 1024);
        cp16(d + KOF_V, qh + srow + 2048);
    }
}

__global__ __launch_bounds__(256, 2) void attn_mma(
        const __half* __restrict__ qh, __half* __restrict__ oh) {
    extern __shared__ __align__(128) char smem[];
    uint32_t sb = smem_u32(smem);
    int tid = threadIdx.x, lane = tid & 31, warp = tid >> 5;
    int qt = blockIdx.x, h = blockIdx.y, b = blockIdx.z;
    int rb = b * SS;

    #pragma unroll
    for (int i = 0; i < 4; i++) {
        int idx = tid + i * 256;
        int r = idx >> 3, c8 = idx & 7;
        size_t srow = (size_t)(rb + qt * 128 + r) * QSTR + h * 64 + c8 * 8;
        *(uint4*)(smem + ATT_SQ + r * 144 + c8 * 16) = *(const uint4*)(qh + srow);
    }
    attn_prefetch_kv(ATT_KV, qh, (size_t)rb, h, tid, sb);
    CP_COMMIT();

    float m0 = -1e30f, m1 = -1e30f, l0 = 0.0f, l1 = 0.0f;
    float accO[8][4];
    #pragma unroll
    for (int i = 0; i < 8; i++)
        #pragma unroll
        for (int j = 0; j < 4; j++) accO[i][j] = 0.0f;

    uint32_t aAddr = sb + ATT_SQ + (uint32_t)((warp * 16 + (lane & 15)) * 144 + (lane >> 4) * 16);
    uint32_t bOff  = (uint32_t)(((lane & 7) + ((lane >> 4) << 3)) * 144 + ((lane >> 3) & 1) * 16);
    uint32_t vOff  = (uint32_t)(((lane & 7) + ((lane >> 3) & 1) * 8) * 144 + ((lane >> 4) & 1) * 16);

    for (int c = 0; c < SS / 64; c++) {
        CP_WAIT(0);
        __syncthreads();
        if (c + 1 < SS / 64) {
            attn_prefetch_kv(ATT_KV + ((c + 1) & 1) * ATT_KSTR,
                             qh, (size_t)(rb + (c + 1) * 64), h, tid, sb);
            CP_COMMIT();
        }
        uint32_t kvB = ATT_KV + (uint32_t)((c & 1) * ATT_KSTR);

        float s[8][4];
        #pragma unroll
        for (int i = 0; i < 8; i++)
            #pragma unroll
            for (int j = 0; j < 4; j++) s[i][j] = 0.0f;

        #pragma unroll
        for (int kc = 0; kc < 4; kc++) {
            uint32_t ah0, ah1, ah2, ah3;
            ldm_x4(ah0, ah1, ah2, ah3, aAddr + kc * 32);
            #pragma unroll
            for (int nh = 0; nh < 4; nh++) {
                uint32_t ba = sb + kvB + KOF_K + (uint32_t)(nh * 16 * 144) + bOff + kc * 32;
                uint32_t bh_[4];
                ldm_x4(bh_[0], bh_[1], bh_[2], bh_[3], ba);
                #pragma unroll
                for (int o = 0; o < 2; o++) {
                    int nt = nh * 2 + o;
                    mma_f32(s[nt], ah0, ah1, ah2, ah3, bh_[o * 2], bh_[o * 2 + 1]);
                }
            }
        }

        float mx0 = -1e30f, mx1 = -1e30f;
        #pragma unroll
        for (int nt = 0; nt < 8; nt++) {
            s[nt][0] *= 0.125f; s[nt][1] *= 0.125f; s[nt][2] *= 0.125f; s[nt][3] *= 0.125f;
            mx0 = fmaxf(mx0, fmaxf(s[nt][0], s[nt][1]));
            mx1 = fmaxf(mx1, fmaxf(s[nt][2], s[nt][3]));
        }
        mx0 = fmaxf(mx0, __shfl_xor_sync(0xffffffffu, mx0, 1));
        mx0 = fmaxf(mx0, __shfl_xor_sync(0xffffffffu, mx0, 2));
        mx1 = fmaxf(mx1, __shfl_xor_sync(0xffffffffu, mx1, 1));
        mx1 = fmaxf(mx1, __shfl_xor_sync(0xffffffffu, mx1, 2));
        float mn0 = fmaxf(m0, mx0), mn1 = fmaxf(m1, mx1);
        float alpha0 = __expf(m0 - mn0), alpha1 = __expf(m1 - mn1);
        m0 = mn0; m1 = mn1;
        float sum0 = 0.0f, sum1 = 0.0f;
        #pragma unroll
        for (int nt = 0; nt < 8; nt++) {
            s[nt][0] = __expf(s[nt][0] - m0);
            s[nt][1] = __expf(s[nt][1] - m0);
            s[nt][2] = __expf(s[nt][2] - m1);
            s[nt][3] = __expf(s[nt][3] - m1);
            sum0 += s[nt][0] + s[nt][1];
            sum1 += s[nt][2] + s[nt][3];
        }
        sum0 += __shfl_xor_sync(0xffffffffu, sum0, 1);
        sum0 += __shfl_xor_sync(0xffffffffu, sum0, 2);
        sum1 += __shfl_xor_sync(0xffffffffu, sum1, 1);
        sum1 += __shfl_xor_sync(0xffffffffu, sum1, 2);
        l0 = l0 * alpha0 + sum0;
        l1 = l1 * alpha1 + sum1;
        #pragma unroll
        for (int dt = 0; dt < 8; dt++) {
            accO[dt][0] *= alpha0; accO[dt][1] *= alpha0;
            accO[dt][2] *= alpha1; accO[dt][3] *= alpha1;
        }

        #pragma unroll
        for (int kc2 = 0; kc2 < 4; kc2++) {
            int n0 = kc2 * 2, n1 = kc2 * 2 + 1;
            uint32_t ph0 = pack_f16(s[n0][0], s[n0][1]);
            uint32_t ph1 = pack_f16(s[n0][2], s[n0][3]);
            uint32_t ph2 = pack_f16(s[n1][0], s[n1][1]);
            uint32_t ph3 = pack_f16(s[n1][2], s[n1][3]);
            #pragma unroll
            for (int nd = 0; nd < 4; nd++) {
                uint32_t va = sb + kvB + KOF_V + (uint32_t)(kc2 * 16 * 144) + vOff + nd * 32;
                uint32_t vh_[4];
                ldm_x4_t(vh_[0], vh_[1], vh_[2], vh_[3], va);
                #pragma unroll
                for (int o = 0; o < 2; o++) {
                    int dt = nd * 2 + o;
                    mma_f32(accO[dt], ph0, ph1, ph2, ph3, vh_[o * 2], vh_[o * 2 + 1]);
                }
            }
        }
    }

    float inv0 = 1.0f / l0, inv1 = 1.0f / l1;
    int g = lane >> 2, c2 = (lane & 3) * 2;
    int row = rb + qt * 128 + warp * 16 + g;
    int colb = h * 64 + c2;
    #pragma unroll
    for (int dt = 0; dt < 8; dt++) {
        float v0 = accO[dt][0] * inv0, v1 = accO[dt][1] * inv0;
        float v2 = accO[dt][2] * inv1, v3 = accO[dt][3] * inv1;
        int col = colb + dt * 8;
        *(uint32_t*)(oh + (size_t)row * EE + col) = pack_f16(v0, v1);
        *(uint32_t*)(oh + (size_t)(row + 8) * EE + col) = pack_f16(v2, v3);
    }
}

// ---------------- fp32 -> fp16 -----------------------------------------------
__global__ __launch_bounds__(256) void convert_kernel(const float* __restrict__ in,
                                                      __half* __restrict__ hi,
                                                      int n4) {
    int i = blockIdx.x * 256 + threadIdx.x;
    if (i >= n4) return;
    float4 v = ((const float4*)in)[i];
    uint2 ho; ho.x = pack_f16(v.x, v.y); ho.y = pack_f16(v.z, v.w);
    ((uint2*)hi)[i] = ho;
}

// ---------------- y = LN(a + b) * g + beta (+ fp16) --------------------------
__global__ __launch_bounds__(256) void add_ln_split_kernel(const float* __restrict__ a,
                                                           const float* __restrict__ bsrc,
                                                           const float* __restrict__ g,
                                                           const float* __restrict__ beta,
                                                           float* __restrict__ y,
                                                           __half* __restrict__ yh) {
    int row = blockIdx.x;
    int tid = threadIdx.x;
    const float* ar = a + (size_t)row * EE;
    const float* br = bsrc + (size_t)row * EE;
    float v[4];
    float s = 0.0f, s2 = 0.0f;
    #pragma unroll
    for (int k = 0; k < 4; k++) {
        float t = ar[tid + 256 * k] + br[tid + 256 * k];
        v[k] = t; s += t; s2 += t * t;
    }
    __shared__ float red[18];
    #pragma unroll
    for (int off = 16; off; off >>= 1) {
        s  += __shfl_xor_sync(0xffffffffu, s,  off);
        s2 += __shfl_xor_sync(0xffffffffu, s2, off);
    }
    int wid = tid >> 5, lid = tid & 31;
    if (lid == 0) { red[wid] = s; red[wid + 8] = s2; }
    __syncthreads();
    if (tid < 32) {
        float a1 = (tid < 8) ? red[tid] : 0.0f;
        float a2 = (tid < 8) ? red[tid + 8] : 0.0f;
        #pragma unroll
        for (int off = 4; off; off >>= 1) {
            a1 += __shfl_xor_sync(0xffffffffu, a1, off);
            a2 += __shfl_xor_sync(0xffffffffu, a2, off);
        }
        if (tid == 0) { red[16] = a1; red[17] = a2; }
    }
    __syncthreads();
    float mu = red[16] * (1.0f / EE);
    float var = red[17] * (1.0f / EE) - mu * mu;
    float rs = rsqrtf(var + 1e-5f);
    float* yr = y + (size_t)row * EE;
    __half* yhr = yh + (size_t)row * EE;
    #pragma unroll
    for (int k = 0; k < 4; k++) {
        int c = tid + 256 * k;
        float val = (v[k] - mu) * rs * g[c] + beta[c];
        yr[c] = val;
        yhr[c] = __float2half_rn(val);
    }
}

// ---------------- mean-pool over S -------------------------------------------
__global__ __launch_bounds__(256) void pool_kernel(const float* __restrict__ x,
                                                   float* __restrict__ pooled) {
    int idx = blockIdx.x * 256 + threadIdx.x;
    int b = idx >> 10, e = idx & 1023;
    const float* p = x + (size_t)b * SS * EE + e;
    float s = 0.0f;
    for (int sI = 0; sI < SS; sI++) s += p[(size_t)sI * EE];
    pooled[idx] = s * (1.0f / SS);
}

// ---------------- complexity estimator ---------------------------------------
__global__ __launch_bounds__(256) void ce_kernel(const float* __restrict__ pooled,
                                                 const float* __restrict__ w1,
                                                 const float* __restrict__ b1,
                                                 const float* __restrict__ w2,
                                                 const float* __restrict__ b2,
                                                 float* __restrict__ out) {
    int b = blockIdx.x, j = threadIdx.x;
    const float* p = pooled + b * EE;
    const float* w = w1 + (size_t)j * EE;
    float s = b1[j];
    for (int k = 0; k < EE; k++) s = fmaf(p[k], w[k], s);
    float h = fmaxf(s, 0.0f);
    __shared__ float red[256];
    red[j] = h * w2[j];
    __syncthreads();
    for (int off = 128; off; off >>= 1) {
        if (j < off) red[j] += red[j + off];
        __syncthreads();
    }
    if (j == 0) {
        float logit = red[0] + b2[0];
        float prob = 1.0f / (1.0f + expf(-logit));
        out[OFF_PROBS + b] = prob;
        out[OFF_MODE + b] = (prob > 0.5f) ? 1.0f : 0.0f;
    }
}

// ---------------- select + mean(mode) ----------------------------------------
__global__ __launch_bounds__(256) void finalize_kernel(const float* __restrict__ t,
                                                       const float* __restrict__ f,
                                                       float* __restrict__ out) {
    size_t i = (size_t)blockIdx.x * 256 + threadIdx.x;
    int b = (int)((i * 4) >> 20);
    float m = out[OFF_MODE + b];
    float4 r = (m > 0.5f) ? ((const float4*)t)[i] : ((const float4*)f)[i];
    ((float4*)out)[i] = r;
    if (i == 0) {
        float sAcc = 0.0f;
        for (int k = 0; k < 8; k++) sAcc += out[OFF_MODE + k];
        out[OFF_MEAN] = sAcc * 0.125f;
    }
}

// -----------------------------------------------------------------------------
extern "C" void kernel_launch(void* const* d_in, const int* in_sizes, int n_in,
                              void* d_out, int out_size) {
    const float* x      = (const float*)d_in[0];
    const float* w_in   = (const float*)d_in[1];
    const float* w_out  = (const float*)d_in[2];
    const float* ffn_w1 = (const float*)d_in[3];
    const float* ffn_w2 = (const float*)d_in[4];
    const float* ln1_g  = (const float*)d_in[5];
    const float* ln1_b  = (const float*)d_in[6];
    const float* ln2_g  = (const float*)d_in[7];
    const float* ln2_b  = (const float*)d_in[8];
    const float* ce_w1  = (const float*)d_in[9];
    const float* ce_b1  = (const float*)d_in[10];
    const float* ce_w2  = (const float*)d_in[11];
    const float* ce_b2  = (const float*)d_in[12];
    const float* fast_w = (const float*)d_in[13];
    float* out = (float*)d_out;

    float *bufA, *bufB, *bufT, *bufT1, *bufFast, *pooled;
    __half *wbh, *ah, *bh;
    cudaGetSymbolAddress((void**)&bufA, g_bufA);
    cudaGetSymbolAddress((void**)&bufB, g_bufB);
    cudaGetSymbolAddress((void**)&bufT, g_bufT);
    cudaGetSymbolAddress((void**)&bufT1, g_bufT1);
    cudaGetSymbolAddress((void**)&bufFast, g_bufFast);
    cudaGetSymbolAddress((void**)&pooled, g_pooled);
    cudaGetSymbolAddress((void**)&wbh, g_wb_hi);
    cudaGetSymbolAddress((void**)&ah, g_actA_hi);
    cudaGetSymbolAddress((void**)&bh, g_actB_hi);

    cudaFuncSetAttribute(mma_gemm<0>, cudaFuncAttributeMaxDynamicSharedMemorySize, SMT);
    cudaFuncSetAttribute(mma_gemm<2>, cudaFuncAttributeMaxDynamicSharedMemorySize, SMT);
    cudaFuncSetAttribute(mma_gemm<3>, cudaFuncAttributeMaxDynamicSharedMemorySize, SMT);
    cudaFuncSetAttribute(mma_gemm<4>, cudaFuncAttributeMaxDynamicSharedMemorySize, SMT);
    cudaFuncSetAttribute(attn_mma, cudaFuncAttributeMaxDynamicSharedMemorySize, ATT_SMEM);

    // convert x -> ah (x itself remains the fp32 residual)
    convert_kernel<<<(MROWS*EE/4)/256, 256>>>(x, ah, MROWS*EE/4);
    // complexity estimator
    pool_kernel<<<(BB * EE) / 256, 256>>>(x, pooled);
    ce_kernel<<<BB, 256>>>(pooled, ce_w1, ce_b1, ce_w2, ce_b2, out);
    // weights: fp16
    convert_kernel<<<(2*3*EE*EE/4)/256, 256>>>(w_in,   wbh + OW_IN,   2*3*EE*EE/4);
    convert_kernel<<<(EE*EE/4)/256,     256>>>(fast_w, wbh + OW_FAST, EE*EE/4);

    const float* tin = x;
    for (int l = 0; l < LL; l++) {
        if (l == 0) {
            mma_gemm<4><<<dim3(4*EE/128, MROWS/128), 256, SMT>>>(
                ah, wbh + OW_IN, wbh + OW_FAST,
                nullptr, bh, bufFast, 4*EE, EE);
        } else {
            mma_gemm<2><<<dim3(3*EE/128, MROWS/128), 256, SMT>>>(
                ah, wbh + OW_IN + (size_t)l*3*EE*EE, nullptr,
                nullptr, bh, nullptr, 3*EE, EE);
        }
        attn_mma<<<dim3(SS/128, HH, BB), 256, ATT_SMEM>>>(bh, ah);
        if (l == 0) {
            convert_kernel<<<(2*EE*EE/4)/256,   256>>>(w_out,  wbh + OW_OUT, 2*EE*EE/4);
            convert_kernel<<<(2*4*EE*EE/4)/256, 256>>>(ffn_w1, wbh + OW_F1,  2*4*EE*EE/4);
            convert_kernel<<<(2*4*EE*EE/4)/256, 256>>>(ffn_w2, wbh + OW_F2,  2*4*EE*EE/4);
        }
        mma_gemm<0><<<dim3(EE/128, MROWS/128), 256, SMT>>>(
            ah, wbh + OW_OUT + (size_t)l*EE*EE, nullptr,
            bufA, nullptr, nullptr, EE, EE);
        add_ln_split_kernel<<<MROWS, 256>>>(tin, bufA, ln1_g + l*EE, ln1_b + l*EE,
                                            bufT1, ah);
        mma_gemm<3><<<dim3(4*EE/128, MROWS/128), 256, SMT>>>(
            ah, wbh + OW_F1 + (size_t)l*4*EE*EE, nullptr,
            nullptr, bh, nullptr, 4*EE, EE);
        mma_gemm<0><<<dim3(EE/128, MROWS/128), 256, SMT>>>(
            bh, wbh + OW_F2 + (size_t)l*4*EE*EE, nullptr,
            bufB, nullptr, nullptr, EE, 4*EE);
        add_ln_split_kernel<<<MROWS, 256>>>(bufT1, bufB, ln2_g + l*EE, ln2_b + l*EE,
                                            bufT, ah);
        tin = bufT;
    }

    finalize_kernel<<<(MROWS * EE / 4) / 256, 256>>>(bufT, bufFast, out);
}